// round 12
// baseline (speedup 1.0000x reference)
#include <cuda_runtime.h>
#include <cuda_fp16.h>
#include <math.h>

// ---------------- problem constants ----------------
#define BB 2
#define SS 2048
#define DM 1024
#define NH 16
#define NKV 4
#define HDIM 64
#define NE 8
#define FF 2048
#define NT (BB*SS)                    // 4096 tokens
#define QKVN (DM + 2*NKV*HDIM)        // 1536
#define CAP (2*NT + NE*128)           // 9216 padded MoE slots
#define SCALEQ 0.125f
#define CLIPV 8.0f

// ---------------- device scratch ----------------
__device__ float g_hidden[NT*DM];
__device__ float g_x2[NT*DM];
__device__ int   g_top_e[NT*2];
__device__ float g_top_w[NT*2];
__device__ int   g_cnt[NE];
__device__ int   g_fill[NE];
__device__ int   g_segoff[NE+1];
__device__ int   g_total;
__device__ int   g_perm[CAP];
__device__ int   g_tok_slot[NT*2];
__device__ float g_y[CAP*DM];
__device__ float g_invfreq[32];
// fp16 buffers
__device__ __half g_x1h[NT*DM];
__device__ __half g_x2h[NT*DM];
__device__ __half g_attnh[NT*DM];
__device__ __half g_h1h[CAP*FF];
__device__ __half g_qkvh[NT*QKVN];           // qkv (fp16), q/k roped in place
__device__ __half g_vth[BB*NKV*HDIM*SS];     // V transposed: [b][kvh][dim][seq]
__device__ __half g_wqkvh[QKVN*DM];
__device__ __half g_outwh[DM*DM];
__device__ __half g_w1h[NE*FF*DM];
__device__ __half g_v1h[NE*FF*DM];
__device__ __half g_w2h[NE*DM*FF];

// ---------------- weight conversion ----------------
__global__ void conv_h(const float* __restrict__ in, __half* __restrict__ out, int n4) {
    int i = blockIdx.x*blockDim.x + threadIdx.x;
    if (i >= n4) return;
    float4 v = ((const float4*)in)[i];
    ((half2*)out)[i*2]   = __floats2half2_rn(v.x, v.y);
    ((half2*)out)[i*2+1] = __floats2half2_rn(v.z, v.w);
}
// transpose-convert: in [R][C] fp32 -> out [C][R] fp16; 64(R) x 32(C) tiles,
// half2-coalesced writes (128B per warp).
__global__ void convT_h(const float* __restrict__ in, __half* __restrict__ out,
                        int R, int C) {
    __shared__ float t[32][65];   // [c][r]
    int e = blockIdx.z;
    in  += (size_t)e*R*C;
    out += (size_t)e*R*C;
    int r0 = blockIdx.x*64, c0 = blockIdx.y*32;
    int tx = threadIdx.x, ty = threadIdx.y;
#pragma unroll
    for (int k = 0; k < 64; k += 8)
        t[tx][ty+k] = in[(size_t)(r0+ty+k)*C + c0+tx];
    __syncthreads();
#pragma unroll
    for (int k = 0; k < 32; k += 8) {
        int row = ty + k;
        half2 hv = __floats2half2_rn(t[row][2*tx], t[row][2*tx+1]);
        *(half2*)(out + (size_t)(c0+row)*R + r0 + 2*tx) = hv;
    }
}

// ---------------- layernorm ----------------
template<bool OUTF, bool OUTH>
__global__ void ln_kernel(const float* __restrict__ x, const float* __restrict__ w,
                          float* __restrict__ outf, __half* __restrict__ outh) {
    int row = blockIdx.x, tid = threadIdx.x;
    float4 v = ((const float4*)(x + (size_t)row*DM))[tid];
    float s = v.x+v.y+v.z+v.w;
    float q = v.x*v.x+v.y*v.y+v.z*v.z+v.w*v.w;
#pragma unroll
    for (int o = 16; o; o >>= 1) {
        s += __shfl_xor_sync(0xffffffffu, s, o);
        q += __shfl_xor_sync(0xffffffffu, q, o);
    }
    __shared__ float ssm[8], qsm[8];
    if ((tid & 31) == 0) { ssm[tid>>5] = s; qsm[tid>>5] = q; }
    __syncthreads();
    float ts = 0.f, tq = 0.f;
#pragma unroll
    for (int i = 0; i < 8; i++) { ts += ssm[i]; tq += qsm[i]; }
    float mu  = ts * (1.f/DM);
    float var = tq * (1.f/DM) - mu*mu;
    float rs  = rsqrtf(var + 1e-5f);
    float4 wv = ((const float4*)w)[tid];
    float4 r;
    r.x = (v.x-mu)*rs*wv.x; r.y = (v.y-mu)*rs*wv.y;
    r.z = (v.z-mu)*rs*wv.z; r.w = (v.w-mu)*rs*wv.w;
    if (OUTF) ((float4*)(outf + (size_t)row*DM))[tid] = r;
    if (OUTH) {
        ((half2*)(outh + (size_t)row*DM))[tid*2]   = __floats2half2_rn(r.x, r.y);
        ((half2*)(outh + (size_t)row*DM))[tid*2+1] = __floats2half2_rn(r.z, r.w);
    }
}

// ---------------- mma / cp.async helpers ----------------
__device__ __forceinline__ void mma_f16(float* c,
        unsigned a0, unsigned a1, unsigned a2, unsigned a3,
        unsigned b0, unsigned b1) {
    asm volatile("mma.sync.aligned.m16n8k16.row.col.f32.f16.f16.f32 "
        "{%0,%1,%2,%3}, {%4,%5,%6,%7}, {%8,%9}, {%0,%1,%2,%3};"
        : "+f"(c[0]), "+f"(c[1]), "+f"(c[2]), "+f"(c[3])
        : "r"(a0), "r"(a1), "r"(a2), "r"(a3), "r"(b0), "r"(b1));
}
__device__ __forceinline__ void cp16(void* smem_dst, const void* gsrc, int src_bytes) {
    unsigned sa = (unsigned)__cvta_generic_to_shared(smem_dst);
    asm volatile("cp.async.cg.shared.global [%0], [%1], 16, %2;\n"
                 :: "r"(sa), "l"(gsrc), "r"(src_bytes));
}
#define CP_COMMIT() asm volatile("cp.async.commit_group;\n")
#define CP_WAITG2() asm volatile("cp.async.wait_group 2;\n")
#define CP_WAITG1() asm volatile("cp.async.wait_group 1;\n")

// ---------------- fp16 GEMM: 128x128 tile, K=32 halfs/slab, 4-stage cp.async ------
// EPI: 0 none(f32), 1 clip(f32), 2 +resid(f32), 4 clip(fp16 out)
#define HSTRW 20
#define HSLABW (128*HSTRW)
#define HNSTG 4
#define HGEMM_SMEM (HNSTG*2*HSLABW*4)   // 81920 B
template<int EPI, bool GATHER, bool EXPERT>
__global__ void __launch_bounds__(256, 2)
hgemm(const __half* __restrict__ A, const __half* __restrict__ Bm,
      void* __restrict__ Cv, const float* __restrict__ resid,
      int N, int K, long ldbE) {
    int mbase = blockIdx.y * 128;
    if (EXPERT) {
        if (mbase >= g_total) return;
        int e = 0;
#pragma unroll
        for (int i = 0; i < NE; i++) if (g_segoff[i+1] <= mbase) e = i + 1;
        Bm += (size_t)e * ldbE;
    }
    int nbase = blockIdx.x * 128;
    extern __shared__ unsigned smw[];
    int tid  = threadIdx.x;
    int lane = tid & 31, warp = tid >> 5;
    int wM = (warp & 1) * 64;
    int wN = (warp >> 1) * 32;
    int g  = lane >> 2, tg = lane & 3;

    int ar = tid >> 1, ac = (tid & 1) * 16;
    const __half* arow;
    int asz = 16;
    if (GATHER) {
        int tok = g_perm[mbase + ar];
        asz  = (tok >= 0) ? 16 : 0;
        arow = A + (size_t)(tok >= 0 ? tok : 0) * K;
    } else {
        arow = A + (size_t)(mbase + ar) * K;
    }
    const __half* brow = Bm + (size_t)(nbase + ar) * K;

    float acc[4][4][4];
#pragma unroll
    for (int mi = 0; mi < 4; mi++)
#pragma unroll
        for (int nj = 0; nj < 4; nj++)
#pragma unroll
            for (int r = 0; r < 4; r++) acc[mi][nj][r] = 0.f;

    auto load_slab = [&](int s, int kb) {
        unsigned* As = smw + s*(2*HSLABW);
        unsigned* Bs = As + HSLABW;
        cp16(&As[ar*HSTRW + ac/2],     arow + kb + ac,     asz);
        cp16(&As[ar*HSTRW + ac/2 + 4], arow + kb + ac + 8, asz);
        cp16(&Bs[ar*HSTRW + ac/2],     brow + kb + ac,     16);
        cp16(&Bs[ar*HSTRW + ac/2 + 4], brow + kb + ac + 8, 16);
    };

    int ns = K >> 5;
#pragma unroll
    for (int j = 0; j < 3; j++) { load_slab(j, j*32); CP_COMMIT(); }

    for (int i = 0; i < ns; i++) {
        int s = i & (HNSTG-1);
        CP_WAITG2();
        __syncthreads();
        int j = i + 3;
        if (j < ns) load_slab(j & (HNSTG-1), j*32);
        CP_COMMIT();
        const unsigned* as = smw + s*(2*HSLABW);
        const unsigned* bs = as + HSLABW;
#pragma unroll
        for (int ks = 0; ks < 2; ks++) {
            int k0w = ks * 8;
            unsigned bf[4][2];
#pragma unroll
            for (int nj = 0; nj < 4; nj++) {
                int n = wN + nj*8 + g;
                bf[nj][0] = bs[n*HSTRW + k0w + tg];
                bf[nj][1] = bs[n*HSTRW + k0w + 4 + tg];
            }
#pragma unroll
            for (int mi = 0; mi < 4; mi++) {
                int m = wM + mi*16 + g;
                unsigned a0 = as[m*HSTRW + k0w + tg];
                unsigned a1 = as[(m+8)*HSTRW + k0w + tg];
                unsigned a2 = as[m*HSTRW + k0w + 4 + tg];
                unsigned a3 = as[(m+8)*HSTRW + k0w + 4 + tg];
#pragma unroll
                for (int nj = 0; nj < 4; nj++)
                    mma_f16(acc[mi][nj], a0, a1, a2, a3, bf[nj][0], bf[nj][1]);
            }
        }
    }
    float* C = (float*)Cv;
    __half* Ch = (__half*)Cv;
#pragma unroll
    for (int mi = 0; mi < 4; mi++) {
#pragma unroll
        for (int nj = 0; nj < 4; nj++) {
            int r0 = mbase + wM + mi*16 + g;
            int r1 = r0 + 8;
            int c  = nbase + wN + nj*8 + tg*2;
            float v0 = acc[mi][nj][0], v1 = acc[mi][nj][1];
            float v2 = acc[mi][nj][2], v3 = acc[mi][nj][3];
            if (EPI == 1 || EPI == 4) {
                v0 = fminf(fmaxf(v0,-CLIPV),CLIPV); v1 = fminf(fmaxf(v1,-CLIPV),CLIPV);
                v2 = fminf(fmaxf(v2,-CLIPV),CLIPV); v3 = fminf(fmaxf(v3,-CLIPV),CLIPV);
            }
            if (EPI == 2) {
                float2 r0v = *(const float2*)(resid + (size_t)r0*N + c);
                float2 r1v = *(const float2*)(resid + (size_t)r1*N + c);
                v0 += r0v.x; v1 += r0v.y; v2 += r1v.x; v3 += r1v.y;
            }
            if (EPI == 4) {
                *(half2*)(Ch + (size_t)r0*N + c) = __floats2half2_rn(v0, v1);
                *(half2*)(Ch + (size_t)r1*N + c) = __floats2half2_rn(v2, v3);
            } else {
                *(float2*)(C + (size_t)r0*N + c) = make_float2(v0, v1);
                *(float2*)(C + (size_t)r1*N + c) = make_float2(v2, v3);
            }
        }
    }
}

// ---------------- fp16 dual-B up GEMM ----------------
#define UNSTG 4
#define UP_SMEM (UNSTG*3*HSLABW*4)     // 122880 B
__global__ void __launch_bounds__(256, 1)
up_hgemm(const __half* __restrict__ A, const __half* __restrict__ Bw,
         const __half* __restrict__ Bv, __half* __restrict__ C) {
    const int N = FF, K = DM;
    int mbase = blockIdx.y * 128;
    if (mbase >= g_total) return;
    int e = 0;
#pragma unroll
    for (int i = 0; i < NE; i++) if (g_segoff[i+1] <= mbase) e = i + 1;
    Bw += (size_t)e * FF * DM;
    Bv += (size_t)e * FF * DM;
    int nbase = blockIdx.x * 128;
    extern __shared__ unsigned smw[];
    int tid  = threadIdx.x;
    int lane = tid & 31, warp = tid >> 5;
    int wM = (warp & 1) * 64;
    int wN = (warp >> 1) * 32;
    int g  = lane >> 2, tg = lane & 3;

    int ar = tid >> 1, ac = (tid & 1) * 16;
    int tok = g_perm[mbase + ar];
    int asz  = (tok >= 0) ? 16 : 0;
    const __half* arow = A + (size_t)(tok >= 0 ? tok : 0) * K;
    const __half* wrow = Bw + (size_t)(nbase + ar) * K;
    const __half* vrow = Bv + (size_t)(nbase + ar) * K;

    float accw[4][4][4], accv[4][4][4];
#pragma unroll
    for (int mi = 0; mi < 4; mi++)
#pragma unroll
        for (int nj = 0; nj < 4; nj++)
#pragma unroll
            for (int r = 0; r < 4; r++) { accw[mi][nj][r] = 0.f; accv[mi][nj][r] = 0.f; }

    auto load_slab = [&](int s, int kb) {
        unsigned* As = smw + s*(3*HSLABW);
        unsigned* Ws = As + HSLABW;
        unsigned* Vs = Ws + HSLABW;
        cp16(&As[ar*HSTRW + ac/2],     arow + kb + ac,     asz);
        cp16(&As[ar*HSTRW + ac/2 + 4], arow + kb + ac + 8, asz);
        cp16(&Ws[ar*HSTRW + ac/2],     wrow + kb + ac,     16);
        cp16(&Ws[ar*HSTRW + ac/2 + 4], wrow + kb + ac + 8, 16);
        cp16(&Vs[ar*HSTRW + ac/2],     vrow + kb + ac,     16);
        cp16(&Vs[ar*HSTRW + ac/2 + 4], vrow + kb + ac + 8, 16);
    };

    const int ns = K >> 5;
#pragma unroll
    for (int j = 0; j < 3; j++) { load_slab(j, j*32); CP_COMMIT(); }

    for (int i = 0; i < ns; i++) {
        int s = i & (UNSTG-1);
        CP_WAITG2();
        __syncthreads();
        int j = i + 3;
        if (j < ns) load_slab(j & (UNSTG-1), j*32);
        CP_COMMIT();
        const unsigned* as = smw + s*(3*HSLABW);
        const unsigned* ws = as + HSLABW;
        const unsigned* vs = ws + HSLABW;
#pragma unroll
        for (int ks = 0; ks < 2; ks++) {
            int k0w = ks * 8;
            unsigned bw[4][2], bv[4][2];
#pragma unroll
            for (int nj = 0; nj < 4; nj++) {
                int n = wN + nj*8 + g;
                bw[nj][0] = ws[n*HSTRW + k0w + tg];
                bw[nj][1] = ws[n*HSTRW + k0w + 4 + tg];
                bv[nj][0] = vs[n*HSTRW + k0w + tg];
                bv[nj][1] = vs[n*HSTRW + k0w + 4 + tg];
            }
#pragma unroll
            for (int mi = 0; mi < 4; mi++) {
                int m = wM + mi*16 + g;
                unsigned a0 = as[m*HSTRW + k0w + tg];
                unsigned a1 = as[(m+8)*HSTRW + k0w + tg];
                unsigned a2 = as[m*HSTRW + k0w + 4 + tg];
                unsigned a3 = as[(m+8)*HSTRW + k0w + 4 + tg];
#pragma unroll
                for (int nj = 0; nj < 4; nj++) {
                    mma_f16(accw[mi][nj], a0, a1, a2, a3, bw[nj][0], bw[nj][1]);
                    mma_f16(accv[mi][nj], a0, a1, a2, a3, bv[nj][0], bv[nj][1]);
                }
            }
        }
    }
#pragma unroll
    for (int mi = 0; mi < 4; mi++) {
#pragma unroll
        for (int nj = 0; nj < 4; nj++) {
            int r0 = mbase + wM + mi*16 + g;
            int r1 = r0 + 8;
            int c  = nbase + wN + nj*8 + tg*2;
            float w0 = accw[mi][nj][0], w1 = accw[mi][nj][1];
            float w2 = accw[mi][nj][2], w3 = accw[mi][nj][3];
            float v0 = accv[mi][nj][0] * (w0 / (1.f + __expf(-w0)));
            float v1 = accv[mi][nj][1] * (w1 / (1.f + __expf(-w1)));
            float v2 = accv[mi][nj][2] * (w2 / (1.f + __expf(-w2)));
            float v3 = accv[mi][nj][3] * (w3 / (1.f + __expf(-w3)));
            *(half2*)(C + (size_t)r0*N + c) = __floats2half2_rn(v0, v1);
            *(half2*)(C + (size_t)r1*N + c) = __floats2half2_rn(v2, v3);
        }
    }
}

// ---------------- RoPE (fp16 in-place on q/k of g_qkvh) ----------------
__global__ void ropetab_kernel() {
    int i = threadIdx.x;
    if (i < 32) g_invfreq[i] = (float)pow(10000.0, -(double)i / 32.0);
}
__global__ void rope_h_kernel() {
    int idx = blockIdx.x*blockDim.x + threadIdx.x;
    if (idx >= NT*20*32) return;
    int i    = idx & 31;
    int head = (idx >> 5) % 20;
    int n    = idx / (32*20);
    int s    = n & (SS - 1);
    float ang = (float)s * g_invfreq[i];
    float sn, cs;
    sincosf(ang, &sn, &cs);
    __half* base = g_qkvh + (size_t)n*QKVN + (head < NH ? head*HDIM : DM + (head-NH)*HDIM);
    float x1 = __half2float(base[i]), x2 = __half2float(base[i+32]);
    float y1 = x1*cs - x2*sn;
    float y2 = x1*sn + x2*cs;
    if (head < NH) { y1 *= SCALEQ; y2 *= SCALEQ; }
    base[i]    = __float2half_rn(y1);
    base[i+32] = __float2half_rn(y2);
}
// V transpose: g_qkvh v slots [tok][kvh][d] -> g_vth [b][kvh][d][s]
__global__ void vt_kernel() {
    __shared__ float t[32][65];     // [dim][seq]
    int bk = blockIdx.z;
    int b  = bk >> 2, kvh = bk & 3;
    int s0 = blockIdx.x*64, d0 = blockIdx.y*32;
    int tx = threadIdx.x, ty = threadIdx.y;
    const __half* src = g_qkvh + (size_t)(b*SS)*QKVN + DM + NKV*HDIM + kvh*HDIM;
#pragma unroll
    for (int k = 0; k < 64; k += 8)
        t[tx][ty+k] = __half2float(src[(size_t)(s0+ty+k)*QKVN + d0+tx]);
    __syncthreads();
    __half* dst = g_vth + ((size_t)bk*HDIM)*SS;
#pragma unroll
    for (int k = 0; k < 32; k += 8) {
        int row = ty + k;
        half2 hv = __floats2half2_rn(t[row][2*tx], t[row][2*tx+1]);
        *(half2*)(dst + (size_t)(d0+row)*SS + s0 + 2*tx) = hv;
    }
}

// ---------------- fp16 flash attention: QK | PV(prev) | softmax pipeline ----------------
#define FQ 128
#define FKT 64
#define FSTW 36
#define FLASH_SMEM ((FQ + 2*FKT + 3*FKT + FQ)*FSTW*4)   // 82944 B
__global__ void __launch_bounds__(256)
flash_h_kernel(const __half* __restrict__ qkvh, const __half* __restrict__ vth,
               __half* __restrict__ out) {
    extern __shared__ unsigned smw[];
    unsigned* Qs = smw;
    unsigned* Kst = Qs + FQ*FSTW;
    unsigned* Vst = Kst + 2*FKT*FSTW;
    unsigned* Ps = Vst + 3*FKT*FSTW;
    int qb = gridDim.x - 1 - blockIdx.x;
    int bh = blockIdx.y;
    int b = bh >> 4, h = bh & 15, kh = h >> 2;
    int tid = threadIdx.x, lane = tid & 31, warp = tid >> 5;
    int g = lane >> 2, tg = lane & 3;

    {
        const __half* qp = qkvh + (size_t)(b*SS + qb*FQ)*QKVN + h*HDIM;
        int r = tid >> 1;
        int c0 = (tid & 1) * 4;
#pragma unroll
        for (int q = 0; q < 4; q++)
            cp16(&Qs[r*FSTW + (c0+q)*4], qp + (size_t)r*QKVN + (c0+q)*8, 16);
    }
    int kvr = tid >> 2, kvc = (tid & 3) * 2;
    const __half* kbase = qkvh + (size_t)(b*SS)*QKVN + DM + kh*HDIM;
    const __half* vtb = vth + ((size_t)(b*NKV + kh)*HDIM)*SS;
    auto load_kv = [&](int kst, int vst, int kt) {
        const __half* kp = kbase + (size_t)(kt*FKT + kvr)*QKVN;
        const __half* vp = vtb + (size_t)kvr*SS + kt*FKT;
        unsigned* kd = Kst + kst*FKT*FSTW + kvr*FSTW;
        unsigned* vd = Vst + vst*FKT*FSTW + kvr*FSTW;
#pragma unroll
        for (int q = 0; q < 2; q++) {
            cp16(kd + (kvc+q)*4, kp + (kvc+q)*8, 16);
            cp16(vd + (kvc+q)*4, vp + (kvc+q)*8, 16);
        }
    };

    int wrow = warp*16;
    int grow = qb*FQ + wrow;

    float m0 = -1e30f, m1 = -1e30f, l0 = 0.f, l1 = 0.f;
    float o[8][4];
#pragma unroll
    for (int nj = 0; nj < 8; nj++)
#pragma unroll
        for (int r = 0; r < 4; r++) o[nj][r] = 0.f;

    int ktmax = 2*qb + 1;
    load_kv(0, 0, 0);
    CP_COMMIT();

    bool pend = false;
    int pkt = 0;

    for (int kt = 0; kt <= ktmax; kt++) {
        __syncthreads();
        if (kt < ktmax) load_kv((kt+1)&1, (kt+1)%3, kt+1);
        CP_COMMIT();
        CP_WAITG1();
        __syncthreads();

        bool act = (kt*FKT <= grow + 15);
        float s[8][4];
        if (act) {
            const unsigned* Ks = Kst + (kt&1)*FKT*FSTW;
#pragma unroll
            for (int nj = 0; nj < 8; nj++)
#pragma unroll
                for (int r = 0; r < 4; r++) s[nj][r] = 0.f;
#pragma unroll
            for (int k0w = 0; k0w < 32; k0w += 8) {
                unsigned a0 = Qs[(wrow+g  )*FSTW + k0w+tg];
                unsigned a1 = Qs[(wrow+g+8)*FSTW + k0w+tg];
                unsigned a2 = Qs[(wrow+g  )*FSTW + k0w+4+tg];
                unsigned a3 = Qs[(wrow+g+8)*FSTW + k0w+4+tg];
#pragma unroll
                for (int nj = 0; nj < 8; nj++) {
                    unsigned b0 = Ks[(nj*8+g)*FSTW + k0w+tg];
                    unsigned b1 = Ks[(nj*8+g)*FSTW + k0w+4+tg];
                    mma_f16(s[nj], a0, a1, a2, a3, b0, b1);
                }
            }
        }

        if (pend) {
            const unsigned* Vs = Vst + (pkt%3)*FKT*FSTW;
#pragma unroll
            for (int k0w = 0; k0w < 32; k0w += 8) {
                unsigned a0 = Ps[(wrow+g  )*FSTW + k0w+tg];
                unsigned a1 = Ps[(wrow+g+8)*FSTW + k0w+tg];
                unsigned a2 = Ps[(wrow+g  )*FSTW + k0w+4+tg];
                unsigned a3 = Ps[(wrow+g+8)*FSTW + k0w+4+tg];
#pragma unroll
                for (int nj = 0; nj < 8; nj++) {
                    unsigned b0 = Vs[(nj*8+g)*FSTW + k0w+tg];
                    unsigned b1 = Vs[(nj*8+g)*FSTW + k0w+4+tg];
                    mma_f16(o[nj], a0, a1, a2, a3, b0, b1);
                }
            }
            pend = false;
        }

        if (act) {
            if (kt >= 2*qb) {
                int r0 = grow + g, r1 = grow + g + 8;
#pragma unroll
                for (int nj = 0; nj < 8; nj++) {
                    int c = kt*FKT + nj*8 + 2*tg;
                    if (c     > r0) s[nj][0] = -1e30f;
                    if (c + 1 > r0) s[nj][1] = -1e30f;
                    if (c     > r1) s[nj][2] = -1e30f;
                    if (c + 1 > r1) s[nj][3] = -1e30f;
                }
            }
            float mt0 = -1e30f, mt1 = -1e30f;
#pragma unroll
            for (int nj = 0; nj < 8; nj++) {
                mt0 = fmaxf(mt0, fmaxf(s[nj][0], s[nj][1]));
                mt1 = fmaxf(mt1, fmaxf(s[nj][2], s[nj][3]));
            }
            mt0 = fmaxf(mt0, __shfl_xor_sync(0xffffffffu, mt0, 1));
            mt0 = fmaxf(mt0, __shfl_xor_sync(0xffffffffu, mt0, 2));
            mt1 = fmaxf(mt1, __shfl_xor_sync(0xffffffffu, mt1, 1));
            mt1 = fmaxf(mt1, __shfl_xor_sync(0xffffffffu, mt1, 2));
            float mn0 = fmaxf(m0, mt0), mn1 = fmaxf(m1, mt1);
            float c0 = __expf(m0 - mn0), c1 = __expf(m1 - mn1);
            l0 *= c0; l1 *= c1;
#pragma unroll
            for (int nj = 0; nj < 8; nj++) {
                o[nj][0] *= c0; o[nj][1] *= c0;
                o[nj][2] *= c1; o[nj][3] *= c1;
            }
            float rs0 = 0.f, rs1 = 0.f;
#pragma unroll
            for (int nj = 0; nj < 8; nj++) {
                float p0 = __expf(s[nj][0] - mn0);
                float p1 = __expf(s[nj][1] - mn0);
                float p2 = __expf(s[nj][2] - mn1);
                float p3 = __expf(s[nj][3] - mn1);
                rs0 += p0 + p1; rs1 += p2 + p3;
                int w = nj*4 + tg;
                ((half2*)Ps)[ ((wrow+g  )*FSTW + w) ] = __floats2half2_rn(p0, p1);
                ((half2*)Ps)[ ((wrow+g+8)*FSTW + w) ] = __floats2half2_rn(p2, p3);
            }
            rs0 += __shfl_xor_sync(0xffffffffu, rs0, 1);
            rs0 += __shfl_xor_sync(0xffffffffu, rs0, 2);
            rs1 += __shfl_xor_sync(0xffffffffu, rs1, 1);
            rs1 += __shfl_xor_sync(0xffffffffu, rs1, 2);
            l0 += rs0; l1 += rs1;
            m0 = mn0; m1 = mn1;
            __syncwarp();
            pend = true;
            pkt  = kt;
        }
    }

    if (pend) {
        const unsigned* Vs = Vst + (pkt%3)*FKT*FSTW;
#pragma unroll
        for (int k0w = 0; k0w < 32; k0w += 8) {
            unsigned a0 = Ps[(wrow+g  )*FSTW + k0w+tg];
            unsigned a1 = Ps[(wrow+g+8)*FSTW + k0w+tg];
            unsigned a2 = Ps[(wrow+g  )*FSTW + k0w+4+tg];
            unsigned a3 = Ps[(wrow+g+8)*FSTW + k0w+4+tg];
#pragma unroll
            for (int nj = 0; nj < 8; nj++) {
                unsigned b0 = Vs[(nj*8+g)*FSTW + k0w+tg];
                unsigned b1 = Vs[(nj*8+g)*FSTW + k0w+4+tg];
                mma_f16(o[nj], a0, a1, a2, a3, b0, b1);
            }
        }
    }

    float il0 = 1.f/l0, il1 = 1.f/l1;
    size_t tok0 = (size_t)(b*SS + qb*FQ + wrow + g);
    size_t tok1 = tok0 + 8;
#pragma unroll
    for (int nj = 0; nj < 8; nj++) {
        int col = h*HDIM + nj*8 + 2*tg;
        *(half2*)(out + tok0*DM + col) = __floats2half2_rn(o[nj][0]*il0, o[nj][1]*il0);
        *(half2*)(out + tok1*DM + col) = __floats2half2_rn(o[nj][2]*il1, o[nj][3]*il1);
    }
}

// ---------------- router ----------------
__global__ void router_kernel(const float* __restrict__ x2, const float* __restrict__ rw) {
    int t = (blockIdx.x*blockDim.x + threadIdx.x) >> 5;
    int lane = threadIdx.x & 31;
    if (t >= NT) return;
    const float* xr = x2 + (size_t)t*DM;
    float acc[NE];
#pragma unroll
    for (int e = 0; e < NE; e++) acc[e] = 0.f;
    for (int d = lane; d < DM; d += 32) {
        float xv = xr[d];
        float4 r0 = ((const float4*)rw)[d*2];
        float4 r1 = ((const float4*)rw)[d*2+1];
        acc[0]+=xv*r0.x; acc[1]+=xv*r0.y; acc[2]+=xv*r0.z; acc[3]+=xv*r0.w;
        acc[4]+=xv*r1.x; acc[5]+=xv*r1.y; acc[6]+=xv*r1.z; acc[7]+=xv*r1.w;
    }
#pragma unroll
    for (int o = 16; o; o >>= 1)
#pragma unroll
        for (int e = 0; e < NE; e++)
            acc[e] += __shfl_xor_sync(0xffffffffu, acc[e], o);
    if (lane == 0) {
        int e0 = 0; float m0 = acc[0];
#pragma unroll
        for (int e = 1; e < NE; e++) if (acc[e] > m0) { m0 = acc[e]; e0 = e; }
        int e1 = -1; float m1 = -3.4e38f;
#pragma unroll
        for (int e = 0; e < NE; e++) if (e != e0 && acc[e] > m1) { m1 = acc[e]; e1 = e; }
        float p1 = expf(m1 - m0);
        float w0 = 1.f / (1.f + p1);
        float w1 = p1 / (1.f + p1);
        g_top_e[2*t] = e0; g_top_e[2*t+1] = e1;
        g_top_w[2*t] = w0; g_top_w[2*t+1] = w1;
        atomicAdd(&g_cnt[e0], 1);
        atomicAdd(&g_cnt[e1], 1);
    }
}

__global__ void moe_init_kernel() {
    int i = blockIdx.x*blockDim.x + threadIdx.x;
    if (i < NE) { g_cnt[i] = 0; g_fill[i] = 0; }
    if (i < CAP) g_perm[i] = -1;
}

__global__ void segoff_kernel() {
    int off = 0;
    for (int e = 0; e < NE; e++) {
        g_segoff[e] = off;
        off += ((g_cnt[e] + 127) >> 7) << 7;
    }
    g_segoff[NE] = off;
    g_total = off;
}

__global__ void fill_kernel() {
    int i = blockIdx.x*blockDim.x + threadIdx.x;
    if (i >= NT*2) return;
    int e = g_top_e[i];
    int pos = g_segoff[e] + atomicAdd(&g_fill[e], 1);
    g_perm[pos] = i >> 1;
    g_tok_slot[i] = pos;
}

__global__ void combine_kernel(float* __restrict__ out) {
    int i = blockIdx.x*blockDim.x + threadIdx.x;
    int n = i >> 8, d4 = i & 255;
    int s0 = g_tok_slot[2*n], s1 = g_tok_slot[2*n+1];
    float w0 = g_top_w[2*n], w1 = g_top_w[2*n+1];
    float4 hv = *(float4*)&g_hidden[(size_t)n*DM + d4*4];
    float4 y0 = *(float4*)&g_y[(size_t)s0*DM + d4*4];
    float4 y1 = *(float4*)&g_y[(size_t)s1*DM + d4*4];
    float4 r;
    r.x = hv.x + w0*y0.x + w1*y1.x;
    r.y = hv.y + w0*y0.y + w1*y1.y;
    r.z = hv.z + w0*y0.z + w1*y1.z;
    r.w = hv.w + w0*y0.w + w1*y1.w;
    *(float4*)&out[(size_t)n*DM + d4*4] = r;
}

// ---------------- launch ----------------
extern "C" void kernel_launch(void* const* d_in, const int* in_sizes, int n_in,
                              void* d_out, int out_size) {
    const float* hs   = (const float*)d_in[0];
    const float* ln1w = (const float*)d_in[1];
    const float* ln2w = (const float*)d_in[2];
    const float* wqkv = (const float*)d_in[3];
    const float* outw = (const float*)d_in[4];
    const float* rw   = (const float*)d_in[5];
    const float* w1   = (const float*)d_in[6];
    const float* v1   = (const float*)d_in[7];
    const float* w2   = (const float*)d_in[8];
    float* out = (float*)d_out;

    float *phid, *px2, *py;
    __half *px1h, *px2h, *pattnh, *ph1h, *pqkvh, *pvth;
    __half *pwqkvh, *poutwh, *pw1h, *pv1h, *pw2h;
    cudaGetSymbolAddress((void**)&phid,  g_hidden);
    cudaGetSymbolAddress((void**)&px2,   g_x2);
    cudaGetSymbolAddress((void**)&py,    g_y);
    cudaGetSymbolAddress((void**)&px1h,  g_x1h);
    cudaGetSymbolAddress((void**)&px2h,  g_x2h);
    cudaGetSymbolAddress((void**)&pattnh,g_attnh);
    cudaGetSymbolAddress((void**)&ph1h,  g_h1h);
    cudaGetSymbolAddress((void**)&pqkvh, g_qkvh);
    cudaGetSymbolAddress((void**)&pvth,  g_vth);
    cudaGetSymbolAddress((void**)&pwqkvh,g_wqkvh);
    cudaGetSymbolAddress((void**)&poutwh,g_outwh);
    cudaGetSymbolAddress((void**)&pw1h,  g_w1h);
    cudaGetSymbolAddress((void**)&pv1h,  g_v1h);
    cudaGetSymbolAddress((void**)&pw2h,  g_w2h);

    cudaFuncSetAttribute(flash_h_kernel,
                         cudaFuncAttributeMaxDynamicSharedMemorySize, FLASH_SMEM);
    cudaFuncSetAttribute(hgemm<4,false,false>,
                         cudaFuncAttributeMaxDynamicSharedMemorySize, HGEMM_SMEM);
    cudaFuncSetAttribute(hgemm<2,false,false>,
                         cudaFuncAttributeMaxDynamicSharedMemorySize, HGEMM_SMEM);
    cudaFuncSetAttribute(hgemm<0,false,true>,
                         cudaFuncAttributeMaxDynamicSharedMemorySize, HGEMM_SMEM);
    cudaFuncSetAttribute(up_hgemm,
                         cudaFuncAttributeMaxDynamicSharedMemorySize, UP_SMEM);

    // ---- side stream: weight conversions overlap the attention phase ----
    cudaStream_t s2;
    cudaStreamCreateWithFlags(&s2, cudaStreamNonBlocking);
    cudaEvent_t evF, evQ, evO, evM;
    cudaEventCreateWithFlags(&evF, cudaEventDisableTiming);
    cudaEventCreateWithFlags(&evQ, cudaEventDisableTiming);
    cudaEventCreateWithFlags(&evO, cudaEventDisableTiming);
    cudaEventCreateWithFlags(&evM, cudaEventDisableTiming);

    cudaEventRecord(evF, 0);
    cudaStreamWaitEvent(s2, evF, 0);
    convT_h<<<dim3(DM/64, QKVN/32, 1), dim3(32,8), 0, s2>>>(wqkv, pwqkvh, DM, QKVN);
    cudaEventRecord(evQ, s2);
    convT_h<<<dim3(DM/64, DM/32, 1), dim3(32,8), 0, s2>>>(outw, poutwh, DM, DM);
    cudaEventRecord(evO, s2);
    conv_h<<<(NE*FF*DM/4 + 255)/256, 256, 0, s2>>>(w1, pw1h, NE*FF*DM/4);
    conv_h<<<(NE*FF*DM/4 + 255)/256, 256, 0, s2>>>(v1, pv1h, NE*FF*DM/4);
    convT_h<<<dim3(FF/64, DM/32, NE), dim3(32,8), 0, s2>>>(w2, pw2h, FF, DM);
    cudaEventRecord(evM, s2);

    // LN1 -> QKV(clip, fp16 out) -> RoPE(in-place fp16) + V^T -> attention -> out-proj
    ln_kernel<false,true><<<NT, 256>>>(hs, ln1w, nullptr, px1h);
    ropetab_kernel<<<1, 32>>>();
    cudaStreamWaitEvent(0, evQ, 0);
    hgemm<4,false,false><<<dim3(QKVN/128, NT/128), 256, HGEMM_SMEM>>>(
        px1h, pwqkvh, pqkvh, nullptr, QKVN, DM, 0);
    rope_h_kernel<<<(NT*20*32 + 255)/256, 256>>>();
    vt_kernel<<<dim3(SS/64, HDIM/32, BB*NKV), dim3(32,8)>>>();
    flash_h_kernel<<<dim3(SS/FQ, BB*NH), 256, FLASH_SMEM>>>(pqkvh, pvth, pattnh);
    cudaStreamWaitEvent(0, evO, 0);
    hgemm<2,false,false><<<dim3(DM/128, NT/128), 256, HGEMM_SMEM>>>(
        pattnh, poutwh, phid, hs, DM, DM, 0);

    // LN2 -> router -> top-2 dispatch
    ln_kernel<true,true><<<NT, 256>>>(phid, ln2w, px2, px2h);
    moe_init_kernel<<<(CAP + 255)/256, 256>>>();
    router_kernel<<<NT/8, 256>>>(px2, rw);
    segoff_kernel<<<1, 1>>>();
    fill_kernel<<<(NT*2 + 255)/256, 256>>>();

    // MoE: fused dual-B up (silu epilogue, fp16 out), then down
    cudaStreamWaitEvent(0, evM, 0);
    up_hgemm<<<dim3(FF/128, CAP/128), 256, UP_SMEM>>>(px2h, pw1h, pv1h, ph1h);
    hgemm<0,false,true><<<dim3(DM/128, CAP/128), 256, HGEMM_SMEM>>>(
        ph1h, pw2h, py, nullptr, DM, FF, (long)DM*FF);

    // resid2 + gated expert outputs
    combine_kernel<<<NT, 256>>>(out);
}

// round 13
// speedup vs baseline: 1.4784x; 1.4784x over previous
#include <cuda_runtime.h>
#include <cuda_fp16.h>
#include <math.h>

// ---------------- problem constants ----------------
#define BB 2
#define SS 2048
#define DM 1024
#define NH 16
#define NKV 4
#define HDIM 64
#define NE 8
#define FF 2048
#define NT (BB*SS)                    // 4096 tokens
#define QKVN (DM + 2*NKV*HDIM)        // 1536
#define CAP (2*NT + NE*128)           // 9216 padded MoE slots
#define SCALEQ 0.125f
#define CLIPV 8.0f

// ---------------- device scratch ----------------
__device__ float g_hidden[NT*DM];
__device__ float g_x2[NT*DM];
__device__ int   g_top_e[NT*2];
__device__ float g_top_w[NT*2];
__device__ int   g_cnt[NE];
__device__ int   g_fill[NE];
__device__ int   g_segoff[NE+1];
__device__ int   g_total;
__device__ int   g_perm[CAP];
__device__ int   g_tok_slot[NT*2];
__device__ float g_y[CAP*DM];
__device__ float g_invfreq[32];
// fp16 buffers
__device__ __half g_x1h[NT*DM];
__device__ __half g_x2h[NT*DM];
__device__ __half g_attnh[NT*DM];
__device__ __half g_h1h[CAP*FF];
__device__ __half g_qkvh[NT*QKVN];           // qkv fp16, q/k roped in place
__device__ __half g_vth[BB*NKV*HDIM*SS];     // V transposed: [b][kvh][dim][seq]
__device__ __half g_wqkvh[QKVN*DM];
__device__ __half g_outwh[DM*DM];
__device__ __half g_w1h[NE*FF*DM];
__device__ __half g_v1h[NE*FF*DM];
__device__ __half g_w2h[NE*DM*FF];

// ---------------- weight conversion ----------------
__global__ void conv_h(const float* __restrict__ in, __half* __restrict__ out, int n4) {
    int i = blockIdx.x*blockDim.x + threadIdx.x;
    if (i >= n4) return;
    float4 v = ((const float4*)in)[i];
    ((half2*)out)[i*2]   = __floats2half2_rn(v.x, v.y);
    ((half2*)out)[i*2+1] = __floats2half2_rn(v.z, v.w);
}
// transpose-convert: in [R][C] fp32 -> out [C][R] fp16; 64(R) x 32(C) tiles,
// half2-coalesced writes (128B/warp).
__global__ void convT_h(const float* __restrict__ in, __half* __restrict__ out,
                        int R, int C) {
    __shared__ float t[32][65];   // [c][r]
    int e = blockIdx.z;
    in  += (size_t)e*R*C;
    out += (size_t)e*R*C;
    int r0 = blockIdx.x*64, c0 = blockIdx.y*32;
    int tx = threadIdx.x, ty = threadIdx.y;
#pragma unroll
    for (int k = 0; k < 64; k += 8)
        t[tx][ty+k] = in[(size_t)(r0+ty+k)*C + c0+tx];
    __syncthreads();
#pragma unroll
    for (int k = 0; k < 32; k += 8) {
        int row = ty + k;
        half2 hv = __floats2half2_rn(t[row][2*tx], t[row][2*tx+1]);
        *(half2*)(out + (size_t)(c0+row)*R + r0 + 2*tx) = hv;
    }
}

// ---------------- layernorm ----------------
template<bool OUTF, bool OUTH>
__global__ void ln_kernel(const float* __restrict__ x, const float* __restrict__ w,
                          float* __restrict__ outf, __half* __restrict__ outh) {
    int row = blockIdx.x, tid = threadIdx.x;
    float4 v = ((const float4*)(x + (size_t)row*DM))[tid];
    float s = v.x+v.y+v.z+v.w;
    float q = v.x*v.x+v.y*v.y+v.z*v.z+v.w*v.w;
#pragma unroll
    for (int o = 16; o; o >>= 1) {
        s += __shfl_xor_sync(0xffffffffu, s, o);
        q += __shfl_xor_sync(0xffffffffu, q, o);
    }
    __shared__ float ssm[8], qsm[8];
    if ((tid & 31) == 0) { ssm[tid>>5] = s; qsm[tid>>5] = q; }
    __syncthreads();
    float ts = 0.f, tq = 0.f;
#pragma unroll
    for (int i = 0; i < 8; i++) { ts += ssm[i]; tq += qsm[i]; }
    float mu  = ts * (1.f/DM);
    float var = tq * (1.f/DM) - mu*mu;
    float rs  = rsqrtf(var + 1e-5f);
    float4 wv = ((const float4*)w)[tid];
    float4 r;
    r.x = (v.x-mu)*rs*wv.x; r.y = (v.y-mu)*rs*wv.y;
    r.z = (v.z-mu)*rs*wv.z; r.w = (v.w-mu)*rs*wv.w;
    if (OUTF) ((float4*)(outf + (size_t)row*DM))[tid] = r;
    if (OUTH) {
        ((half2*)(outh + (size_t)row*DM))[tid*2]   = __floats2half2_rn(r.x, r.y);
        ((half2*)(outh + (size_t)row*DM))[tid*2+1] = __floats2half2_rn(r.z, r.w);
    }
}

// ---------------- mma / cp.async helpers ----------------
__device__ __forceinline__ void mma_f16(float* c,
        unsigned a0, unsigned a1, unsigned a2, unsigned a3,
        unsigned b0, unsigned b1) {
    asm volatile("mma.sync.aligned.m16n8k16.row.col.f32.f16.f16.f32 "
        "{%0,%1,%2,%3}, {%4,%5,%6,%7}, {%8,%9}, {%0,%1,%2,%3};"
        : "+f"(c[0]), "+f"(c[1]), "+f"(c[2]), "+f"(c[3])
        : "r"(a0), "r"(a1), "r"(a2), "r"(a3), "r"(b0), "r"(b1));
}
__device__ __forceinline__ void cp16(void* smem_dst, const void* gsrc, int src_bytes) {
    unsigned sa = (unsigned)__cvta_generic_to_shared(smem_dst);
    asm volatile("cp.async.cg.shared.global [%0], [%1], 16, %2;\n"
                 :: "r"(sa), "l"(gsrc), "r"(src_bytes));
}
#define CP_COMMIT() asm volatile("cp.async.commit_group;\n")
#define CP_WAITG2() asm volatile("cp.async.wait_group 2;\n")
#define CP_WAITG1() asm volatile("cp.async.wait_group 1;\n")

// ---------------- fp16 GEMM: 128x128 tile, K=32 halfs/slab, 4-stage cp.async ------
// EPI: 0 none(f32), 2 +resid(f32), 4 clip(fp16 out)
#define HSTRW 20
#define HSLABW (128*HSTRW)
#define HNSTG 4
#define HGEMM_SMEM (HNSTG*2*HSLABW*4)   // 81920 B
template<int EPI, bool GATHER, bool EXPERT>
__global__ void __launch_bounds__(256, 2)
hgemm(const __half* __restrict__ A, const __half* __restrict__ Bm,
      void* __restrict__ Cv, const float* __restrict__ resid,
      int N, int K, long ldbE) {
    int mbase = blockIdx.y * 128;
    if (EXPERT) {
        if (mbase >= g_total) return;
        int e = 0;
#pragma unroll
        for (int i = 0; i < NE; i++) if (g_segoff[i+1] <= mbase) e = i + 1;
        Bm += (size_t)e * ldbE;
    }
    int nbase = blockIdx.x * 128;
    extern __shared__ unsigned smw[];
    int tid  = threadIdx.x;
    int lane = tid & 31, warp = tid >> 5;
    int wM = (warp & 1) * 64;
    int wN = (warp >> 1) * 32;
    int g  = lane >> 2, tg = lane & 3;

    int ar = tid >> 1, ac = (tid & 1) * 16;
    const __half* arow;
    int asz = 16;
    if (GATHER) {
        int tok = g_perm[mbase + ar];
        asz  = (tok >= 0) ? 16 : 0;
        arow = A + (size_t)(tok >= 0 ? tok : 0) * K;
    } else {
        arow = A + (size_t)(mbase + ar) * K;
    }
    const __half* brow = Bm + (size_t)(nbase + ar) * K;

    float acc[4][4][4];
#pragma unroll
    for (int mi = 0; mi < 4; mi++)
#pragma unroll
        for (int nj = 0; nj < 4; nj++)
#pragma unroll
            for (int r = 0; r < 4; r++) acc[mi][nj][r] = 0.f;

    auto load_slab = [&](int s, int kb) {
        unsigned* As = smw + s*(2*HSLABW);
        unsigned* Bs = As + HSLABW;
        cp16(&As[ar*HSTRW + ac/2],     arow + kb + ac,     asz);
        cp16(&As[ar*HSTRW + ac/2 + 4], arow + kb + ac + 8, asz);
        cp16(&Bs[ar*HSTRW + ac/2],     brow + kb + ac,     16);
        cp16(&Bs[ar*HSTRW + ac/2 + 4], brow + kb + ac + 8, 16);
    };

    int ns = K >> 5;
#pragma unroll
    for (int j = 0; j < 3; j++) { load_slab(j, j*32); CP_COMMIT(); }

    for (int i = 0; i < ns; i++) {
        int s = i & (HNSTG-1);
        CP_WAITG2();
        __syncthreads();
        int j = i + 3;
        if (j < ns) load_slab(j & (HNSTG-1), j*32);
        CP_COMMIT();
        const unsigned* as = smw + s*(2*HSLABW);
        const unsigned* bs = as + HSLABW;
#pragma unroll
        for (int ks = 0; ks < 2; ks++) {
            int k0w = ks * 8;
            unsigned bf[4][2];
#pragma unroll
            for (int nj = 0; nj < 4; nj++) {
                int n = wN + nj*8 + g;
                bf[nj][0] = bs[n*HSTRW + k0w + tg];
                bf[nj][1] = bs[n*HSTRW + k0w + 4 + tg];
            }
#pragma unroll
            for (int mi = 0; mi < 4; mi++) {
                int m = wM + mi*16 + g;
                unsigned a0 = as[m*HSTRW + k0w + tg];
                unsigned a1 = as[(m+8)*HSTRW + k0w + tg];
                unsigned a2 = as[m*HSTRW + k0w + 4 + tg];
                unsigned a3 = as[(m+8)*HSTRW + k0w + 4 + tg];
#pragma unroll
                for (int nj = 0; nj < 4; nj++)
                    mma_f16(acc[mi][nj], a0, a1, a2, a3, bf[nj][0], bf[nj][1]);
            }
        }
    }
    float* C = (float*)Cv;
    __half* Ch = (__half*)Cv;
#pragma unroll
    for (int mi = 0; mi < 4; mi++) {
#pragma unroll
        for (int nj = 0; nj < 4; nj++) {
            int r0 = mbase + wM + mi*16 + g;
            int r1 = r0 + 8;
            int c  = nbase + wN + nj*8 + tg*2;
            float v0 = acc[mi][nj][0], v1 = acc[mi][nj][1];
            float v2 = acc[mi][nj][2], v3 = acc[mi][nj][3];
            if (EPI == 4) {
                v0 = fminf(fmaxf(v0,-CLIPV),CLIPV); v1 = fminf(fmaxf(v1,-CLIPV),CLIPV);
                v2 = fminf(fmaxf(v2,-CLIPV),CLIPV); v3 = fminf(fmaxf(v3,-CLIPV),CLIPV);
            }
            if (EPI == 2) {
                float2 r0v = *(const float2*)(resid + (size_t)r0*N + c);
                float2 r1v = *(const float2*)(resid + (size_t)r1*N + c);
                v0 += r0v.x; v1 += r0v.y; v2 += r1v.x; v3 += r1v.y;
            }
            if (EPI == 4) {
                *(half2*)(Ch + (size_t)r0*N + c) = __floats2half2_rn(v0, v1);
                *(half2*)(Ch + (size_t)r1*N + c) = __floats2half2_rn(v2, v3);
            } else {
                *(float2*)(C + (size_t)r0*N + c) = make_float2(v0, v1);
                *(float2*)(C + (size_t)r1*N + c) = make_float2(v2, v3);
            }
        }
    }
}

// ---------------- fp16 dual-B up GEMM ----------------
#define UNSTG 4
#define UP_SMEM (UNSTG*3*HSLABW*4)     // 122880 B
__global__ void __launch_bounds__(256, 1)
up_hgemm(const __half* __restrict__ A, const __half* __restrict__ Bw,
         const __half* __restrict__ Bv, __half* __restrict__ C) {
    const int N = FF, K = DM;
    int mbase = blockIdx.y * 128;
    if (mbase >= g_total) return;
    int e = 0;
#pragma unroll
    for (int i = 0; i < NE; i++) if (g_segoff[i+1] <= mbase) e = i + 1;
    Bw += (size_t)e * FF * DM;
    Bv += (size_t)e * FF * DM;
    int nbase = blockIdx.x * 128;
    extern __shared__ unsigned smw[];
    int tid  = threadIdx.x;
    int lane = tid & 31, warp = tid >> 5;
    int wM = (warp & 1) * 64;
    int wN = (warp >> 1) * 32;
    int g  = lane >> 2, tg = lane & 3;

    int ar = tid >> 1, ac = (tid & 1) * 16;
    int tok = g_perm[mbase + ar];
    int asz  = (tok >= 0) ? 16 : 0;
    const __half* arow = A + (size_t)(tok >= 0 ? tok : 0) * K;
    const __half* wrow = Bw + (size_t)(nbase + ar) * K;
    const __half* vrow = Bv + (size_t)(nbase + ar) * K;

    float accw[4][4][4], accv[4][4][4];
#pragma unroll
    for (int mi = 0; mi < 4; mi++)
#pragma unroll
        for (int nj = 0; nj < 4; nj++)
#pragma unroll
            for (int r = 0; r < 4; r++) { accw[mi][nj][r] = 0.f; accv[mi][nj][r] = 0.f; }

    auto load_slab = [&](int s, int kb) {
        unsigned* As = smw + s*(3*HSLABW);
        unsigned* Ws = As + HSLABW;
        unsigned* Vs = Ws + HSLABW;
        cp16(&As[ar*HSTRW + ac/2],     arow + kb + ac,     asz);
        cp16(&As[ar*HSTRW + ac/2 + 4], arow + kb + ac + 8, asz);
        cp16(&Ws[ar*HSTRW + ac/2],     wrow + kb + ac,     16);
        cp16(&Ws[ar*HSTRW + ac/2 + 4], wrow + kb + ac + 8, 16);
        cp16(&Vs[ar*HSTRW + ac/2],     vrow + kb + ac,     16);
        cp16(&Vs[ar*HSTRW + ac/2 + 4], vrow + kb + ac + 8, 16);
    };

    const int ns = K >> 5;
#pragma unroll
    for (int j = 0; j < 3; j++) { load_slab(j, j*32); CP_COMMIT(); }

    for (int i = 0; i < ns; i++) {
        int s = i & (UNSTG-1);
        CP_WAITG2();
        __syncthreads();
        int j = i + 3;
        if (j < ns) load_slab(j & (UNSTG-1), j*32);
        CP_COMMIT();
        const unsigned* as = smw + s*(3*HSLABW);
        const unsigned* ws = as + HSLABW;
        const unsigned* vs = ws + HSLABW;
#pragma unroll
        for (int ks = 0; ks < 2; ks++) {
            int k0w = ks * 8;
            unsigned bw[4][2], bv[4][2];
#pragma unroll
            for (int nj = 0; nj < 4; nj++) {
                int n = wN + nj*8 + g;
                bw[nj][0] = ws[n*HSTRW + k0w + tg];
                bw[nj][1] = ws[n*HSTRW + k0w + 4 + tg];
                bv[nj][0] = vs[n*HSTRW + k0w + tg];
                bv[nj][1] = vs[n*HSTRW + k0w + 4 + tg];
            }
#pragma unroll
            for (int mi = 0; mi < 4; mi++) {
                int m = wM + mi*16 + g;
                unsigned a0 = as[m*HSTRW + k0w + tg];
                unsigned a1 = as[(m+8)*HSTRW + k0w + tg];
                unsigned a2 = as[m*HSTRW + k0w + 4 + tg];
                unsigned a3 = as[(m+8)*HSTRW + k0w + 4 + tg];
#pragma unroll
                for (int nj = 0; nj < 4; nj++) {
                    mma_f16(accw[mi][nj], a0, a1, a2, a3, bw[nj][0], bw[nj][1]);
                    mma_f16(accv[mi][nj], a0, a1, a2, a3, bv[nj][0], bv[nj][1]);
                }
            }
        }
    }
#pragma unroll
    for (int mi = 0; mi < 4; mi++) {
#pragma unroll
        for (int nj = 0; nj < 4; nj++) {
            int r0 = mbase + wM + mi*16 + g;
            int r1 = r0 + 8;
            int c  = nbase + wN + nj*8 + tg*2;
            float w0 = accw[mi][nj][0], w1 = accw[mi][nj][1];
            float w2 = accw[mi][nj][2], w3 = accw[mi][nj][3];
            float v0 = accv[mi][nj][0] * (w0 / (1.f + __expf(-w0)));
            float v1 = accv[mi][nj][1] * (w1 / (1.f + __expf(-w1)));
            float v2 = accv[mi][nj][2] * (w2 / (1.f + __expf(-w2)));
            float v3 = accv[mi][nj][3] * (w3 / (1.f + __expf(-w3)));
            *(half2*)(C + (size_t)r0*N + c) = __floats2half2_rn(v0, v1);
            *(half2*)(C + (size_t)r1*N + c) = __floats2half2_rn(v2, v3);
        }
    }
}

// ---------------- RoPE (fp16 in-place on q/k of g_qkvh) ----------------
__global__ void ropetab_kernel() {
    int i = threadIdx.x;
    if (i < 32) g_invfreq[i] = (float)pow(10000.0, -(double)i / 32.0);
}
__global__ void rope_h_kernel() {
    int idx = blockIdx.x*blockDim.x + threadIdx.x;
    if (idx >= NT*20*32) return;
    int i    = idx & 31;
    int head = (idx >> 5) % 20;
    int n    = idx / (32*20);
    int s    = n & (SS - 1);
    float ang = (float)s * g_invfreq[i];
    float sn, cs;
    sincosf(ang, &sn, &cs);
    __half* base = g_qkvh + (size_t)n*QKVN + (head < NH ? head*HDIM : DM + (head-NH)*HDIM);
    float x1 = __half2float(base[i]), x2 = __half2float(base[i+32]);
    float y1 = x1*cs - x2*sn;
    float y2 = x1*sn + x2*cs;
    if (head < NH) { y1 *= SCALEQ; y2 *= SCALEQ; }
    base[i]    = __float2half_rn(y1);
    base[i+32] = __float2half_rn(y2);
}
// V transpose: g_qkvh v slots [tok][kvh][d] -> g_vth [b][kvh][d][s]
__global__ void vt_kernel() {
    __shared__ float t[32][65];     // [dim][seq]
    int bk = blockIdx.z;
    int b  = bk >> 2, kvh = bk & 3;
    int s0 = blockIdx.x*64, d0 = blockIdx.y*32;
    int tx = threadIdx.x, ty = threadIdx.y;
    const __half* src = g_qkvh + (size_t)(b*SS)*QKVN + DM + NKV*HDIM + kvh*HDIM;
#pragma unroll
    for (int k = 0; k < 64; k += 8)
        t[tx][ty+k] = __half2float(src[(size_t)(s0+ty+k)*QKVN + d0+tx]);
    __syncthreads();
    __half* dst = g_vth + ((size_t)bk*HDIM)*SS;
#pragma unroll
    for (int k = 0; k < 32; k += 8) {
        int row = ty + k;
        half2 hv = __floats2half2_rn(t[row][2*tx], t[row][2*tx+1]);
        *(half2*)(dst + (size_t)(d0+row)*SS + s0 + 2*tx) = hv;
    }
}

// ---------------- fp16 flash attention: QK | PV(prev) | softmax pipeline ----------------
#define FQ 128
#define FKT 64
#define FSTW 36
#define FLASH_SMEM ((FQ + 2*FKT + 3*FKT + FQ)*FSTW*4)   // 82944 B
__global__ void __launch_bounds__(256)
flash_h_kernel(const __half* __restrict__ qkvh, const __half* __restrict__ vth,
               __half* __restrict__ out) {
    extern __shared__ unsigned smw[];
    unsigned* Qs = smw;
    unsigned* Kst = Qs + FQ*FSTW;
    unsigned* Vst = Kst + 2*FKT*FSTW;
    unsigned* Ps = Vst + 3*FKT*FSTW;
    int qb = gridDim.x - 1 - blockIdx.x;
    int bh = blockIdx.y;
    int b = bh >> 4, h = bh & 15, kh = h >> 2;
    int tid = threadIdx.x, lane = tid & 31, warp = tid >> 5;
    int g = lane >> 2, tg = lane & 3;

    {
        const __half* qp = qkvh + (size_t)(b*SS + qb*FQ)*QKVN + h*HDIM;
        int r = tid >> 1;
        int c0 = (tid & 1) * 4;
#pragma unroll
        for (int q = 0; q < 4; q++)
            cp16(&Qs[r*FSTW + (c0+q)*4], qp + (size_t)r*QKVN + (c0+q)*8, 16);
    }
    int kvr = tid >> 2, kvc = (tid & 3) * 2;
    const __half* kbase = qkvh + (size_t)(b*SS)*QKVN + DM + kh*HDIM;
    const __half* vtb = vth + ((size_t)(b*NKV + kh)*HDIM)*SS;
    auto load_kv = [&](int kst, int vst, int kt) {
        const __half* kp = kbase + (size_t)(kt*FKT + kvr)*QKVN;
        const __half* vp = vtb + (size_t)kvr*SS + kt*FKT;
        unsigned* kd = Kst + kst*FKT*FSTW + kvr*FSTW;
        unsigned* vd = Vst + vst*FKT*FSTW + kvr*FSTW;
#pragma unroll
        for (int q = 0; q < 2; q++) {
            cp16(kd + (kvc+q)*4, kp + (kvc+q)*8, 16);
            cp16(vd + (kvc+q)*4, vp + (kvc+q)*8, 16);
        }
    };

    int wrow = warp*16;
    int grow = qb*FQ + wrow;

    float m0 = -1e30f, m1 = -1e30f, l0 = 0.f, l1 = 0.f;
    float o[8][4];
#pragma unroll
    for (int nj = 0; nj < 8; nj++)
#pragma unroll
        for (int r = 0; r < 4; r++) o[nj][r] = 0.f;

    int ktmax = 2*qb + 1;
    load_kv(0, 0, 0);
    CP_COMMIT();

    bool pend = false;
    int pkt = 0;

    for (int kt = 0; kt <= ktmax; kt++) {
        __syncthreads();
        if (kt < ktmax) load_kv((kt+1)&1, (kt+1)%3, kt+1);
        CP_COMMIT();
        CP_WAITG1();
        __syncthreads();

        bool act = (kt*FKT <= grow + 15);
        float s[8][4];
        if (act) {
            const unsigned* Ks = Kst + (kt&1)*FKT*FSTW;
#pragma unroll
            for (int nj = 0; nj < 8; nj++)
#pragma unroll
                for (int r = 0; r < 4; r++) s[nj][r] = 0.f;
#pragma unroll
            for (int k0w = 0; k0w < 32; k0w += 8) {
                unsigned a0 = Qs[(wrow+g  )*FSTW + k0w+tg];
                unsigned a1 = Qs[(wrow+g+8)*FSTW + k0w+tg];
                unsigned a2 = Qs[(wrow+g  )*FSTW + k0w+4+tg];
                unsigned a3 = Qs[(wrow+g+8)*FSTW + k0w+4+tg];
#pragma unroll
                for (int nj = 0; nj < 8; nj++) {
                    unsigned b0 = Ks[(nj*8+g)*FSTW + k0w+tg];
                    unsigned b1 = Ks[(nj*8+g)*FSTW + k0w+4+tg];
                    mma_f16(s[nj], a0, a1, a2, a3, b0, b1);
                }
            }
        }

        if (pend) {
            const unsigned* Vs = Vst + (pkt%3)*FKT*FSTW;
#pragma unroll
            for (int k0w = 0; k0w < 32; k0w += 8) {
                unsigned a0 = Ps[(wrow+g  )*FSTW + k0w+tg];
                unsigned a1 = Ps[(wrow+g+8)*FSTW + k0w+tg];
                unsigned a2 = Ps[(wrow+g  )*FSTW + k0w+4+tg];
                unsigned a3 = Ps[(wrow+g+8)*FSTW + k0w+4+tg];
#pragma unroll
                for (int nj = 0; nj < 8; nj++) {
                    unsigned b0 = Vs[(nj*8+g)*FSTW + k0w+tg];
                    unsigned b1 = Vs[(nj*8+g)*FSTW + k0w+4+tg];
                    mma_f16(o[nj], a0, a1, a2, a3, b0, b1);
                }
            }
            pend = false;
        }

        if (act) {
            if (kt >= 2*qb) {
                int r0 = grow + g, r1 = grow + g + 8;
#pragma unroll
                for (int nj = 0; nj < 8; nj++) {
                    int c = kt*FKT + nj*8 + 2*tg;
                    if (c     > r0) s[nj][0] = -1e30f;
                    if (c + 1 > r0) s[nj][1] = -1e30f;
                    if (c     > r1) s[nj][2] = -1e30f;
                    if (c + 1 > r1) s[nj][3] = -1e30f;
                }
            }
            float mt0 = -1e30f, mt1 = -1e30f;
#pragma unroll
            for (int nj = 0; nj < 8; nj++) {
                mt0 = fmaxf(mt0, fmaxf(s[nj][0], s[nj][1]));
                mt1 = fmaxf(mt1, fmaxf(s[nj][2], s[nj][3]));
            }
            mt0 = fmaxf(mt0, __shfl_xor_sync(0xffffffffu, mt0, 1));
            mt0 = fmaxf(mt0, __shfl_xor_sync(0xffffffffu, mt0, 2));
            mt1 = fmaxf(mt1, __shfl_xor_sync(0xffffffffu, mt1, 1));
            mt1 = fmaxf(mt1, __shfl_xor_sync(0xffffffffu, mt1, 2));
            float mn0 = fmaxf(m0, mt0), mn1 = fmaxf(m1, mt1);
            float c0 = __expf(m0 - mn0), c1 = __expf(m1 - mn1);
            l0 *= c0; l1 *= c1;
#pragma unroll
            for (int nj = 0; nj < 8; nj++) {
                o[nj][0] *= c0; o[nj][1] *= c0;
                o[nj][2] *= c1; o[nj][3] *= c1;
            }
            float rs0 = 0.f, rs1 = 0.f;
#pragma unroll
            for (int nj = 0; nj < 8; nj++) {
                float p0 = __expf(s[nj][0] - mn0);
                float p1 = __expf(s[nj][1] - mn0);
                float p2 = __expf(s[nj][2] - mn1);
                float p3 = __expf(s[nj][3] - mn1);
                rs0 += p0 + p1; rs1 += p2 + p3;
                int w = nj*4 + tg;
                ((half2*)Ps)[ ((wrow+g  )*FSTW + w) ] = __floats2half2_rn(p0, p1);
                ((half2*)Ps)[ ((wrow+g+8)*FSTW + w) ] = __floats2half2_rn(p2, p3);
            }
            rs0 += __shfl_xor_sync(0xffffffffu, rs0, 1);
            rs0 += __shfl_xor_sync(0xffffffffu, rs0, 2);
            rs1 += __shfl_xor_sync(0xffffffffu, rs1, 1);
            rs1 += __shfl_xor_sync(0xffffffffu, rs1, 2);
            l0 += rs0; l1 += rs1;
            m0 = mn0; m1 = mn1;
            __syncwarp();
            pend = true;
            pkt  = kt;
        }
    }

    if (pend) {
        const unsigned* Vs = Vst + (pkt%3)*FKT*FSTW;
#pragma unroll
        for (int k0w = 0; k0w < 32; k0w += 8) {
            unsigned a0 = Ps[(wrow+g  )*FSTW + k0w+tg];
            unsigned a1 = Ps[(wrow+g+8)*FSTW + k0w+tg];
            unsigned a2 = Ps[(wrow+g  )*FSTW + k0w+4+tg];
            unsigned a3 = Ps[(wrow+g+8)*FSTW + k0w+4+tg];
#pragma unroll
            for (int nj = 0; nj < 8; nj++) {
                unsigned b0 = Vs[(nj*8+g)*FSTW + k0w+tg];
                unsigned b1 = Vs[(nj*8+g)*FSTW + k0w+4+tg];
                mma_f16(o[nj], a0, a1, a2, a3, b0, b1);
            }
        }
    }

    float il0 = 1.f/l0, il1 = 1.f/l1;
    size_t tok0 = (size_t)(b*SS + qb*FQ + wrow + g);
    size_t tok1 = tok0 + 8;
#pragma unroll
    for (int nj = 0; nj < 8; nj++) {
        int col = h*HDIM + nj*8 + 2*tg;
        *(half2*)(out + tok0*DM + col) = __floats2half2_rn(o[nj][0]*il0, o[nj][1]*il0);
        *(half2*)(out + tok1*DM + col) = __floats2half2_rn(o[nj][2]*il1, o[nj][3]*il1);
    }
}

// ---------------- router ----------------
__global__ void router_kernel(const float* __restrict__ x2, const float* __restrict__ rw) {
    int t = (blockIdx.x*blockDim.x + threadIdx.x) >> 5;
    int lane = threadIdx.x & 31;
    if (t >= NT) return;
    const float* xr = x2 + (size_t)t*DM;
    float acc[NE];
#pragma unroll
    for (int e = 0; e < NE; e++) acc[e] = 0.f;
    for (int d = lane; d < DM; d += 32) {
        float xv = xr[d];
        float4 r0 = ((const float4*)rw)[d*2];
        float4 r1 = ((const float4*)rw)[d*2+1];
        acc[0]+=xv*r0.x; acc[1]+=xv*r0.y; acc[2]+=xv*r0.z; acc[3]+=xv*r0.w;
        acc[4]+=xv*r1.x; acc[5]+=xv*r1.y; acc[6]+=xv*r1.z; acc[7]+=xv*r1.w;
    }
#pragma unroll
    for (int o = 16; o; o >>= 1)
#pragma unroll
        for (int e = 0; e < NE; e++)
            acc[e] += __shfl_xor_sync(0xffffffffu, acc[e], o);
    if (lane == 0) {
        int e0 = 0; float m0 = acc[0];
#pragma unroll
        for (int e = 1; e < NE; e++) if (acc[e] > m0) { m0 = acc[e]; e0 = e; }
        int e1 = -1; float m1 = -3.4e38f;
#pragma unroll
        for (int e = 0; e < NE; e++) if (e != e0 && acc[e] > m1) { m1 = acc[e]; e1 = e; }
        float p1 = expf(m1 - m0);
        float w0 = 1.f / (1.f + p1);
        float w1 = p1 / (1.f + p1);
        g_top_e[2*t] = e0; g_top_e[2*t+1] = e1;
        g_top_w[2*t] = w0; g_top_w[2*t+1] = w1;
        atomicAdd(&g_cnt[e0], 1);
        atomicAdd(&g_cnt[e1], 1);
    }
}

__global__ void moe_init_kernel() {
    int i = blockIdx.x*blockDim.x + threadIdx.x;
    if (i < NE) { g_cnt[i] = 0; g_fill[i] = 0; }
    if (i < CAP) g_perm[i] = -1;
}

__global__ void segoff_kernel() {
    int off = 0;
    for (int e = 0; e < NE; e++) {
        g_segoff[e] = off;
        off += ((g_cnt[e] + 127) >> 7) << 7;
    }
    g_segoff[NE] = off;
    g_total = off;
}

__global__ void fill_kernel() {
    int i = blockIdx.x*blockDim.x + threadIdx.x;
    if (i >= NT*2) return;
    int e = g_top_e[i];
    int pos = g_segoff[e] + atomicAdd(&g_fill[e], 1);
    g_perm[pos] = i >> 1;
    g_tok_slot[i] = pos;
}

__global__ void combine_kernel(float* __restrict__ out) {
    int i = blockIdx.x*blockDim.x + threadIdx.x;
    int n = i >> 8, d4 = i & 255;
    int s0 = g_tok_slot[2*n], s1 = g_tok_slot[2*n+1];
    float w0 = g_top_w[2*n], w1 = g_top_w[2*n+1];
    float4 hv = *(float4*)&g_hidden[(size_t)n*DM + d4*4];
    float4 y0 = *(float4*)&g_y[(size_t)s0*DM + d4*4];
    float4 y1 = *(float4*)&g_y[(size_t)s1*DM + d4*4];
    float4 r;
    r.x = hv.x + w0*y0.x + w1*y1.x;
    r.y = hv.y + w0*y0.y + w1*y1.y;
    r.z = hv.z + w0*y0.z + w1*y1.z;
    r.w = hv.w + w0*y0.w + w1*y1.w;
    *(float4*)&out[(size_t)n*DM + d4*4] = r;
}

// ---------------- launch (single stream, proven structure) ----------------
extern "C" void kernel_launch(void* const* d_in, const int* in_sizes, int n_in,
                              void* d_out, int out_size) {
    const float* hs   = (const float*)d_in[0];
    const float* ln1w = (const float*)d_in[1];
    const float* ln2w = (const float*)d_in[2];
    const float* wqkv = (const float*)d_in[3];
    const float* outw = (const float*)d_in[4];
    const float* rw   = (const float*)d_in[5];
    const float* w1   = (const float*)d_in[6];
    const float* v1   = (const float*)d_in[7];
    const float* w2   = (const float*)d_in[8];
    float* out = (float*)d_out;

    float *phid, *px2, *py;
    __half *px1h, *px2h, *pattnh, *ph1h, *pqkvh, *pvth;
    __half *pwqkvh, *poutwh, *pw1h, *pv1h, *pw2h;
    cudaGetSymbolAddress((void**)&phid,  g_hidden);
    cudaGetSymbolAddress((void**)&px2,   g_x2);
    cudaGetSymbolAddress((void**)&py,    g_y);
    cudaGetSymbolAddress((void**)&px1h,  g_x1h);
    cudaGetSymbolAddress((void**)&px2h,  g_x2h);
    cudaGetSymbolAddress((void**)&pattnh,g_attnh);
    cudaGetSymbolAddress((void**)&ph1h,  g_h1h);
    cudaGetSymbolAddress((void**)&pqkvh, g_qkvh);
    cudaGetSymbolAddress((void**)&pvth,  g_vth);
    cudaGetSymbolAddress((void**)&pwqkvh,g_wqkvh);
    cudaGetSymbolAddress((void**)&poutwh,g_outwh);
    cudaGetSymbolAddress((void**)&pw1h,  g_w1h);
    cudaGetSymbolAddress((void**)&pv1h,  g_v1h);
    cudaGetSymbolAddress((void**)&pw2h,  g_w2h);

    cudaFuncSetAttribute(flash_h_kernel,
                         cudaFuncAttributeMaxDynamicSharedMemorySize, FLASH_SMEM);
    cudaFuncSetAttribute(hgemm<4,false,false>,
                         cudaFuncAttributeMaxDynamicSharedMemorySize, HGEMM_SMEM);
    cudaFuncSetAttribute(hgemm<2,false,false>,
                         cudaFuncAttributeMaxDynamicSharedMemorySize, HGEMM_SMEM);
    cudaFuncSetAttribute(hgemm<0,false,true>,
                         cudaFuncAttributeMaxDynamicSharedMemorySize, HGEMM_SMEM);
    cudaFuncSetAttribute(up_hgemm,
                         cudaFuncAttributeMaxDynamicSharedMemorySize, UP_SMEM);

    // ---- weight conversions (single stream, coalesced) ----
    conv_h<<<(NE*FF*DM/4 + 255)/256, 256>>>(w1, pw1h, NE*FF*DM/4);
    conv_h<<<(NE*FF*DM/4 + 255)/256, 256>>>(v1, pv1h, NE*FF*DM/4);
    convT_h<<<dim3(DM/64, QKVN/32, 1), dim3(32,8)>>>(wqkv, pwqkvh, DM, QKVN);
    convT_h<<<dim3(DM/64, DM/32, 1), dim3(32,8)>>>(outw, poutwh, DM, DM);
    convT_h<<<dim3(FF/64, DM/32, NE), dim3(32,8)>>>(w2, pw2h, FF, DM);

    // LN1 -> QKV(clip, fp16 out) -> RoPE(in-place fp16) + V^T -> attention -> out-proj
    ln_kernel<false,true><<<NT, 256>>>(hs, ln1w, nullptr, px1h);
    hgemm<4,false,false><<<dim3(QKVN/128, NT/128), 256, HGEMM_SMEM>>>(
        px1h, pwqkvh, pqkvh, nullptr, QKVN, DM, 0);
    ropetab_kernel<<<1, 32>>>();
    rope_h_kernel<<<(NT*20*32 + 255)/256, 256>>>();
    vt_kernel<<<dim3(SS/64, HDIM/32, BB*NKV), dim3(32,8)>>>();
    flash_h_kernel<<<dim3(SS/FQ, BB*NH), 256, FLASH_SMEM>>>(pqkvh, pvth, pattnh);
    hgemm<2,false,false><<<dim3(DM/128, NT/128), 256, HGEMM_SMEM>>>(
        pattnh, poutwh, phid, hs, DM, DM, 0);

    // LN2 -> router -> top-2 dispatch
    ln_kernel<true,true><<<NT, 256>>>(phid, ln2w, px2, px2h);
    moe_init_kernel<<<(CAP + 255)/256, 256>>>();
    router_kernel<<<NT/8, 256>>>(px2, rw);
    segoff_kernel<<<1, 1>>>();
    fill_kernel<<<(NT*2 + 255)/256, 256>>>();

    // MoE: fused dual-B up (silu epilogue, fp16 out), then down
    up_hgemm<<<dim3(FF/128, CAP/128), 256, UP_SMEM>>>(px2h, pw1h, pv1h, ph1h);
    hgemm<0,false,true><<<dim3(DM/128, CAP/128), 256, HGEMM_SMEM>>>(
        ph1h, pw2h, py, nullptr, DM, FF, (long)DM*FF);

    // resid2 + gated expert outputs
    combine_kernel<<<NT, 256>>>(out);
}

// round 14
// speedup vs baseline: 1.4857x; 1.0049x over previous
#include <cuda_runtime.h>
#include <cuda_fp16.h>
#include <math.h>

// ---------------- problem constants ----------------
#define BB 2
#define SS 2048
#define DM 1024
#define NH 16
#define NKV 4
#define HDIM 64
#define NE 8
#define FF 2048
#define NT (BB*SS)                    // 4096 tokens
#define QKVN (DM + 2*NKV*HDIM)        // 1536
#define CAP (2*NT + NE*128)           // 9216 padded MoE slots
#define SCALEQ 0.125f
#define CLIPV 8.0f

// ---------------- device scratch ----------------
__device__ float g_hidden[NT*DM];
__device__ float g_x2[NT*DM];
__device__ int   g_top_e[NT*2];
__device__ float g_top_w[NT*2];
__device__ int   g_cnt[NE];
__device__ int   g_fill[NE];
__device__ int   g_segoff[NE+1];
__device__ int   g_total;
__device__ int   g_perm[CAP];
__device__ int   g_tok_slot[NT*2];
__device__ float g_invfreq[32];
// fp16 buffers
__device__ __half g_x1h[NT*DM];
__device__ __half g_x2h[NT*DM];
__device__ __half g_attnh[NT*DM];
__device__ __half g_h1h[CAP*FF];
__device__ __half g_yh[CAP*DM];
__device__ __half g_qkvh[NT*QKVN];           // qkv fp16, q/k roped in place
__device__ __half g_vth[BB*NKV*HDIM*SS];     // V transposed: [b][kvh][dim][seq]
__device__ __half g_wqkvh[QKVN*DM];
__device__ __half g_outwh[DM*DM];
__device__ __half g_w1h[NE*FF*DM];
__device__ __half g_v1h[NE*FF*DM];
__device__ __half g_w2h[NE*DM*FF];

// ---------------- weight conversion ----------------
// dual convert: w1 and v1 in one launch
__global__ void conv2_h(const float* __restrict__ in1, __half* __restrict__ out1,
                        const float* __restrict__ in2, __half* __restrict__ out2,
                        int n4) {
    int i = blockIdx.x*blockDim.x + threadIdx.x;
    const float* in; __half* out;
    if (i >= n4) { i -= n4; in = in2; out = out2; } else { in = in1; out = out1; }
    if (i >= n4) return;
    float4 v = ((const float4*)in)[i];
    ((half2*)out)[i*2]   = __floats2half2_rn(v.x, v.y);
    ((half2*)out)[i*2+1] = __floats2half2_rn(v.z, v.w);
}
// transpose-convert: in [R][C] fp32 -> out [C][R] fp16; 64(R) x 32(C) tiles
__global__ void convT_h(const float* __restrict__ in, __half* __restrict__ out,
                        int R, int C) {
    __shared__ float t[32][65];
    int e = blockIdx.z;
    in  += (size_t)e*R*C;
    out += (size_t)e*R*C;
    int r0 = blockIdx.x*64, c0 = blockIdx.y*32;
    int tx = threadIdx.x, ty = threadIdx.y;
#pragma unroll
    for (int k = 0; k < 64; k += 8)
        t[tx][ty+k] = in[(size_t)(r0+ty+k)*C + c0+tx];
    __syncthreads();
#pragma unroll
    for (int k = 0; k < 32; k += 8) {
        int row = ty + k;
        half2 hv = __floats2half2_rn(t[row][2*tx], t[row][2*tx+1]);
        *(half2*)(out + (size_t)(c0+row)*R + r0 + 2*tx) = hv;
    }
}

// ---------------- layernorm ----------------
template<bool OUTF, bool OUTH>
__global__ void ln_kernel(const float* __restrict__ x, const float* __restrict__ w,
                          float* __restrict__ outf, __half* __restrict__ outh) {
    int row = blockIdx.x, tid = threadIdx.x;
    float4 v = ((const float4*)(x + (size_t)row*DM))[tid];
    float s = v.x+v.y+v.z+v.w;
    float q = v.x*v.x+v.y*v.y+v.z*v.z+v.w*v.w;
#pragma unroll
    for (int o = 16; o; o >>= 1) {
        s += __shfl_xor_sync(0xffffffffu, s, o);
        q += __shfl_xor_sync(0xffffffffu, q, o);
    }
    __shared__ float ssm[8], qsm[8];
    if ((tid & 31) == 0) { ssm[tid>>5] = s; qsm[tid>>5] = q; }
    __syncthreads();
    float ts = 0.f, tq = 0.f;
#pragma unroll
    for (int i = 0; i < 8; i++) { ts += ssm[i]; tq += qsm[i]; }
    float mu  = ts * (1.f/DM);
    float var = tq * (1.f/DM) - mu*mu;
    float rs  = rsqrtf(var + 1e-5f);
    float4 wv = ((const float4*)w)[tid];
    float4 r;
    r.x = (v.x-mu)*rs*wv.x; r.y = (v.y-mu)*rs*wv.y;
    r.z = (v.z-mu)*rs*wv.z; r.w = (v.w-mu)*rs*wv.w;
    if (OUTF) ((float4*)(outf + (size_t)row*DM))[tid] = r;
    if (OUTH) {
        ((half2*)(outh + (size_t)row*DM))[tid*2]   = __floats2half2_rn(r.x, r.y);
        ((half2*)(outh + (size_t)row*DM))[tid*2+1] = __floats2half2_rn(r.z, r.w);
    }
}

// ---------------- mma / cp.async helpers ----------------
__device__ __forceinline__ void mma_f16(float* c,
        unsigned a0, unsigned a1, unsigned a2, unsigned a3,
        unsigned b0, unsigned b1) {
    asm volatile("mma.sync.aligned.m16n8k16.row.col.f32.f16.f16.f32 "
        "{%0,%1,%2,%3}, {%4,%5,%6,%7}, {%8,%9}, {%0,%1,%2,%3};"
        : "+f"(c[0]), "+f"(c[1]), "+f"(c[2]), "+f"(c[3])
        : "r"(a0), "r"(a1), "r"(a2), "r"(a3), "r"(b0), "r"(b1));
}
__device__ __forceinline__ void cp16(void* smem_dst, const void* gsrc, int src_bytes) {
    unsigned sa = (unsigned)__cvta_generic_to_shared(smem_dst);
    asm volatile("cp.async.cg.shared.global [%0], [%1], 16, %2;\n"
                 :: "r"(sa), "l"(gsrc), "r"(src_bytes));
}
#define CP_COMMIT() asm volatile("cp.async.commit_group;\n")
#define CP_WAITG2() asm volatile("cp.async.wait_group 2;\n")
#define CP_WAITG1() asm volatile("cp.async.wait_group 1;\n")

// ---------------- fp16 GEMM: 128x128 tile, K=32 halfs/slab, 4-stage cp.async ------
// EPI: 0 none(f32), 2 +resid(f32), 4 clip(fp16 out), 5 fp16 out
#define HSTRW 20
#define HSLABW (128*HSTRW)
#define HNSTG 4
#define HGEMM_SMEM (HNSTG*2*HSLABW*4)   // 81920 B
template<int EPI, bool GATHER, bool EXPERT>
__global__ void __launch_bounds__(256, 2)
hgemm(const __half* __restrict__ A, const __half* __restrict__ Bm,
      void* __restrict__ Cv, const float* __restrict__ resid,
      int N, int K, long ldbE) {
    int mbase = blockIdx.y * 128;
    if (EXPERT) {
        if (mbase >= g_total) return;
        int e = 0;
#pragma unroll
        for (int i = 0; i < NE; i++) if (g_segoff[i+1] <= mbase) e = i + 1;
        Bm += (size_t)e * ldbE;
    }
    int nbase = blockIdx.x * 128;
    extern __shared__ unsigned smw[];
    int tid  = threadIdx.x;
    int lane = tid & 31, warp = tid >> 5;
    int wM = (warp & 1) * 64;
    int wN = (warp >> 1) * 32;
    int g  = lane >> 2, tg = lane & 3;

    int ar = tid >> 1, ac = (tid & 1) * 16;
    const __half* arow;
    int asz = 16;
    if (GATHER) {
        int tok = g_perm[mbase + ar];
        asz  = (tok >= 0) ? 16 : 0;
        arow = A + (size_t)(tok >= 0 ? tok : 0) * K;
    } else {
        arow = A + (size_t)(mbase + ar) * K;
    }
    const __half* brow = Bm + (size_t)(nbase + ar) * K;

    float acc[4][4][4];
#pragma unroll
    for (int mi = 0; mi < 4; mi++)
#pragma unroll
        for (int nj = 0; nj < 4; nj++)
#pragma unroll
            for (int r = 0; r < 4; r++) acc[mi][nj][r] = 0.f;

    auto load_slab = [&](int s, int kb) {
        unsigned* As = smw + s*(2*HSLABW);
        unsigned* Bs = As + HSLABW;
        cp16(&As[ar*HSTRW + ac/2],     arow + kb + ac,     asz);
        cp16(&As[ar*HSTRW + ac/2 + 4], arow + kb + ac + 8, asz);
        cp16(&Bs[ar*HSTRW + ac/2],     brow + kb + ac,     16);
        cp16(&Bs[ar*HSTRW + ac/2 + 4], brow + kb + ac + 8, 16);
    };

    int ns = K >> 5;
#pragma unroll
    for (int j = 0; j < 3; j++) { load_slab(j, j*32); CP_COMMIT(); }

    for (int i = 0; i < ns; i++) {
        int s = i & (HNSTG-1);
        CP_WAITG2();
        __syncthreads();
        int j = i + 3;
        if (j < ns) load_slab(j & (HNSTG-1), j*32);
        CP_COMMIT();
        const unsigned* as = smw + s*(2*HSLABW);
        const unsigned* bs = as + HSLABW;
#pragma unroll
        for (int ks = 0; ks < 2; ks++) {
            int k0w = ks * 8;
            unsigned bf[4][2];
#pragma unroll
            for (int nj = 0; nj < 4; nj++) {
                int n = wN + nj*8 + g;
                bf[nj][0] = bs[n*HSTRW + k0w + tg];
                bf[nj][1] = bs[n*HSTRW + k0w + 4 + tg];
            }
#pragma unroll
            for (int mi = 0; mi < 4; mi++) {
                int m = wM + mi*16 + g;
                unsigned a0 = as[m*HSTRW + k0w + tg];
                unsigned a1 = as[(m+8)*HSTRW + k0w + tg];
                unsigned a2 = as[m*HSTRW + k0w + 4 + tg];
                unsigned a3 = as[(m+8)*HSTRW + k0w + 4 + tg];
#pragma unroll
                for (int nj = 0; nj < 4; nj++)
                    mma_f16(acc[mi][nj], a0, a1, a2, a3, bf[nj][0], bf[nj][1]);
            }
        }
    }
    float* C = (float*)Cv;
    __half* Ch = (__half*)Cv;
#pragma unroll
    for (int mi = 0; mi < 4; mi++) {
#pragma unroll
        for (int nj = 0; nj < 4; nj++) {
            int r0 = mbase + wM + mi*16 + g;
            int r1 = r0 + 8;
            int c  = nbase + wN + nj*8 + tg*2;
            float v0 = acc[mi][nj][0], v1 = acc[mi][nj][1];
            float v2 = acc[mi][nj][2], v3 = acc[mi][nj][3];
            if (EPI == 4) {
                v0 = fminf(fmaxf(v0,-CLIPV),CLIPV); v1 = fminf(fmaxf(v1,-CLIPV),CLIPV);
                v2 = fminf(fmaxf(v2,-CLIPV),CLIPV); v3 = fminf(fmaxf(v3,-CLIPV),CLIPV);
            }
            if (EPI == 2) {
                float2 r0v = *(const float2*)(resid + (size_t)r0*N + c);
                float2 r1v = *(const float2*)(resid + (size_t)r1*N + c);
                v0 += r0v.x; v1 += r0v.y; v2 += r1v.x; v3 += r1v.y;
            }
            if (EPI == 4 || EPI == 5) {
                *(half2*)(Ch + (size_t)r0*N + c) = __floats2half2_rn(v0, v1);
                *(half2*)(Ch + (size_t)r1*N + c) = __floats2half2_rn(v2, v3);
            } else {
                *(float2*)(C + (size_t)r0*N + c) = make_float2(v0, v1);
                *(float2*)(C + (size_t)r1*N + c) = make_float2(v2, v3);
            }
        }
    }
}

// ---------------- fp16 dual-B up GEMM ----------------
#define UNSTG 4
#define UP_SMEM (UNSTG*3*HSLABW*4)     // 122880 B
__global__ void __launch_bounds__(256, 1)
up_hgemm(const __half* __restrict__ A, const __half* __restrict__ Bw,
         const __half* __restrict__ Bv, __half* __restrict__ C) {
    const int N = FF, K = DM;
    int mbase = blockIdx.y * 128;
    if (mbase >= g_total) return;
    int e = 0;
#pragma unroll
    for (int i = 0; i < NE; i++) if (g_segoff[i+1] <= mbase) e = i + 1;
    Bw += (size_t)e * FF * DM;
    Bv += (size_t)e * FF * DM;
    int nbase = blockIdx.x * 128;
    extern __shared__ unsigned smw[];
    int tid  = threadIdx.x;
    int lane = tid & 31, warp = tid >> 5;
    int wM = (warp & 1) * 64;
    int wN = (warp >> 1) * 32;
    int g  = lane >> 2, tg = lane & 3;

    int ar = tid >> 1, ac = (tid & 1) * 16;
    int tok = g_perm[mbase + ar];
    int asz  = (tok >= 0) ? 16 : 0;
    const __half* arow = A + (size_t)(tok >= 0 ? tok : 0) * K;
    const __half* wrow = Bw + (size_t)(nbase + ar) * K;
    const __half* vrow = Bv + (size_t)(nbase + ar) * K;

    float accw[4][4][4], accv[4][4][4];
#pragma unroll
    for (int mi = 0; mi < 4; mi++)
#pragma unroll
        for (int nj = 0; nj < 4; nj++)
#pragma unroll
            for (int r = 0; r < 4; r++) { accw[mi][nj][r] = 0.f; accv[mi][nj][r] = 0.f; }

    auto load_slab = [&](int s, int kb) {
        unsigned* As = smw + s*(3*HSLABW);
        unsigned* Ws = As + HSLABW;
        unsigned* Vs = Ws + HSLABW;
        cp16(&As[ar*HSTRW + ac/2],     arow + kb + ac,     asz);
        cp16(&As[ar*HSTRW + ac/2 + 4], arow + kb + ac + 8, asz);
        cp16(&Ws[ar*HSTRW + ac/2],     wrow + kb + ac,     16);
        cp16(&Ws[ar*HSTRW + ac/2 + 4], wrow + kb + ac + 8, 16);
        cp16(&Vs[ar*HSTRW + ac/2],     vrow + kb + ac,     16);
        cp16(&Vs[ar*HSTRW + ac/2 + 4], vrow + kb + ac + 8, 16);
    };

    const int ns = K >> 5;
#pragma unroll
    for (int j = 0; j < 3; j++) { load_slab(j, j*32); CP_COMMIT(); }

    for (int i = 0; i < ns; i++) {
        int s = i & (UNSTG-1);
        CP_WAITG2();
        __syncthreads();
        int j = i + 3;
        if (j < ns) load_slab(j & (UNSTG-1), j*32);
        CP_COMMIT();
        const unsigned* as = smw + s*(3*HSLABW);
        const unsigned* ws = as + HSLABW;
        const unsigned* vs = ws + HSLABW;
#pragma unroll
        for (int ks = 0; ks < 2; ks++) {
            int k0w = ks * 8;
            unsigned bw[4][2], bv[4][2];
#pragma unroll
            for (int nj = 0; nj < 4; nj++) {
                int n = wN + nj*8 + g;
                bw[nj][0] = ws[n*HSTRW + k0w + tg];
                bw[nj][1] = ws[n*HSTRW + k0w + 4 + tg];
                bv[nj][0] = vs[n*HSTRW + k0w + tg];
                bv[nj][1] = vs[n*HSTRW + k0w + 4 + tg];
            }
#pragma unroll
            for (int mi = 0; mi < 4; mi++) {
                int m = wM + mi*16 + g;
                unsigned a0 = as[m*HSTRW + k0w + tg];
                unsigned a1 = as[(m+8)*HSTRW + k0w + tg];
                unsigned a2 = as[m*HSTRW + k0w + 4 + tg];
                unsigned a3 = as[(m+8)*HSTRW + k0w + 4 + tg];
#pragma unroll
                for (int nj = 0; nj < 4; nj++) {
                    mma_f16(accw[mi][nj], a0, a1, a2, a3, bw[nj][0], bw[nj][1]);
                    mma_f16(accv[mi][nj], a0, a1, a2, a3, bv[nj][0], bv[nj][1]);
                }
            }
        }
    }
#pragma unroll
    for (int mi = 0; mi < 4; mi++) {
#pragma unroll
        for (int nj = 0; nj < 4; nj++) {
            int r0 = mbase + wM + mi*16 + g;
            int r1 = r0 + 8;
            int c  = nbase + wN + nj*8 + tg*2;
            float w0 = accw[mi][nj][0], w1 = accw[mi][nj][1];
            float w2 = accw[mi][nj][2], w3 = accw[mi][nj][3];
            float v0 = accv[mi][nj][0] * (w0 / (1.f + __expf(-w0)));
            float v1 = accv[mi][nj][1] * (w1 / (1.f + __expf(-w1)));
            float v2 = accv[mi][nj][2] * (w2 / (1.f + __expf(-w2)));
            float v3 = accv[mi][nj][3] * (w3 / (1.f + __expf(-w3)));
            *(half2*)(C + (size_t)r0*N + c) = __floats2half2_rn(v0, v1);
            *(half2*)(C + (size_t)r1*N + c) = __floats2half2_rn(v2, v3);
        }
    }
}

// ---------------- RoPE (fp16 in-place) + V transpose, one launch ----------------
__global__ void ropetab_kernel() {
    int i = threadIdx.x;
    if (i < 32) g_invfreq[i] = (float)pow(10000.0, -(double)i / 32.0);
}
#define NRBLK ((NT*20*32)/256)      // 10240 rope blocks
#define NVBLK (32*2*BB*NKV)         // 512 vt blocks (SS/64 x HDIM/32 x 8)
__global__ void ropevt_kernel() {
    int bid = blockIdx.x;
    int tid = threadIdx.x;
    if (bid < NRBLK) {
        int idx = bid*256 + tid;
        int i    = idx & 31;
        int head = (idx >> 5) % 20;
        int n    = idx / (32*20);
        int s    = n & (SS - 1);
        float ang = (float)s * g_invfreq[i];
        float sn, cs;
        sincosf(ang, &sn, &cs);
        __half* base = g_qkvh + (size_t)n*QKVN + (head < NH ? head*HDIM : DM + (head-NH)*HDIM);
        float x1 = __half2float(base[i]), x2 = __half2float(base[i+32]);
        float y1 = x1*cs - x2*sn;
        float y2 = x1*sn + x2*cs;
        if (head < NH) { y1 *= SCALEQ; y2 *= SCALEQ; }
        base[i]    = __float2half_rn(y1);
        base[i+32] = __float2half_rn(y2);
    } else {
        __shared__ float t[32][65];     // [dim][seq]
        int vb = bid - NRBLK;
        int s0 = (vb & 31) * 64;
        int d0 = ((vb >> 5) & 1) * 32;
        int bk = vb >> 6;               // b*NKV + kvh
        int tx = tid & 31, ty = tid >> 5;
        const __half* src = g_qkvh + (size_t)((bk>>2)*SS)*QKVN + DM + NKV*HDIM + (bk&3)*HDIM;
#pragma unroll
        for (int k = 0; k < 64; k += 8)
            t[tx][ty+k] = __half2float(src[(size_t)(s0+ty+k)*QKVN + d0+tx]);
        __syncthreads();
        __half* dst = g_vth + ((size_t)bk*HDIM)*SS;
#pragma unroll
        for (int k = 0; k < 32; k += 8) {
            int row = ty + k;
            half2 hv = __floats2half2_rn(t[row][2*tx], t[row][2*tx+1]);
            *(half2*)(dst + (size_t)(d0+row)*SS + s0 + 2*tx) = hv;
        }
    }
}

// ---------------- fp16 flash attention: QK | PV(prev) | softmax pipeline ----------------
#define FQ 128
#define FKT 64
#define FSTW 36
#define FLASH_SMEM ((FQ + 2*FKT + 3*FKT + FQ)*FSTW*4)   // 82944 B
__global__ void __launch_bounds__(256)
flash_h_kernel(const __half* __restrict__ qkvh, const __half* __restrict__ vth,
               __half* __restrict__ out) {
    extern __shared__ unsigned smw[];
    unsigned* Qs = smw;
    unsigned* Kst = Qs + FQ*FSTW;
    unsigned* Vst = Kst + 2*FKT*FSTW;
    unsigned* Ps = Vst + 3*FKT*FSTW;
    int qb = gridDim.x - 1 - blockIdx.x;
    int bh = blockIdx.y;
    int b = bh >> 4, h = bh & 15, kh = h >> 2;
    int tid = threadIdx.x, lane = tid & 31, warp = tid >> 5;
    int g = lane >> 2, tg = lane & 3;

    {
        const __half* qp = qkvh + (size_t)(b*SS + qb*FQ)*QKVN + h*HDIM;
        int r = tid >> 1;
        int c0 = (tid & 1) * 4;
#pragma unroll
        for (int q = 0; q < 4; q++)
            cp16(&Qs[r*FSTW + (c0+q)*4], qp + (size_t)r*QKVN + (c0+q)*8, 16);
    }
    int kvr = tid >> 2, kvc = (tid & 3) * 2;
    const __half* kbase = qkvh + (size_t)(b*SS)*QKVN + DM + kh*HDIM;
    const __half* vtb = vth + ((size_t)(b*NKV + kh)*HDIM)*SS;
    auto load_kv = [&](int kst, int vst, int kt) {
        const __half* kp = kbase + (size_t)(kt*FKT + kvr)*QKVN;
        const __half* vp = vtb + (size_t)kvr*SS + kt*FKT;
        unsigned* kd = Kst + kst*FKT*FSTW + kvr*FSTW;
        unsigned* vd = Vst + vst*FKT*FSTW + kvr*FSTW;
#pragma unroll
        for (int q = 0; q < 2; q++) {
            cp16(kd + (kvc+q)*4, kp + (kvc+q)*8, 16);
            cp16(vd + (kvc+q)*4, vp + (kvc+q)*8, 16);
        }
    };

    int wrow = warp*16;
    int grow = qb*FQ + wrow;

    float m0 = -1e30f, m1 = -1e30f, l0 = 0.f, l1 = 0.f;
    float o[8][4];
#pragma unroll
    for (int nj = 0; nj < 8; nj++)
#pragma unroll
        for (int r = 0; r < 4; r++) o[nj][r] = 0.f;

    int ktmax = 2*qb + 1;
    load_kv(0, 0, 0);
    CP_COMMIT();

    bool pend = false;
    int pkt = 0;

    for (int kt = 0; kt <= ktmax; kt++) {
        __syncthreads();
        if (kt < ktmax) load_kv((kt+1)&1, (kt+1)%3, kt+1);
        CP_COMMIT();
        CP_WAITG1();
        __syncthreads();

        bool act = (kt*FKT <= grow + 15);
        float s[8][4];
        if (act) {
            const unsigned* Ks = Kst + (kt&1)*FKT*FSTW;
#pragma unroll
            for (int nj = 0; nj < 8; nj++)
#pragma unroll
                for (int r = 0; r < 4; r++) s[nj][r] = 0.f;
#pragma unroll
            for (int k0w = 0; k0w < 32; k0w += 8) {
                unsigned a0 = Qs[(wrow+g  )*FSTW + k0w+tg];
                unsigned a1 = Qs[(wrow+g+8)*FSTW + k0w+tg];
                unsigned a2 = Qs[(wrow+g  )*FSTW + k0w+4+tg];
                unsigned a3 = Qs[(wrow+g+8)*FSTW + k0w+4+tg];
#pragma unroll
                for (int nj = 0; nj < 8; nj++) {
                    unsigned b0 = Ks[(nj*8+g)*FSTW + k0w+tg];
                    unsigned b1 = Ks[(nj*8+g)*FSTW + k0w+4+tg];
                    mma_f16(s[nj], a0, a1, a2, a3, b0, b1);
                }
            }
        }

        if (pend) {
            const unsigned* Vs = Vst + (pkt%3)*FKT*FSTW;
#pragma unroll
            for (int k0w = 0; k0w < 32; k0w += 8) {
                unsigned a0 = Ps[(wrow+g  )*FSTW + k0w+tg];
                unsigned a1 = Ps[(wrow+g+8)*FSTW + k0w+tg];
                unsigned a2 = Ps[(wrow+g  )*FSTW + k0w+4+tg];
                unsigned a3 = Ps[(wrow+g+8)*FSTW + k0w+4+tg];
#pragma unroll
                for (int nj = 0; nj < 8; nj++) {
                    unsigned b0 = Vs[(nj*8+g)*FSTW + k0w+tg];
                    unsigned b1 = Vs[(nj*8+g)*FSTW + k0w+4+tg];
                    mma_f16(o[nj], a0, a1, a2, a3, b0, b1);
                }
            }
            pend = false;
        }

        if (act) {
            if (kt >= 2*qb) {
                int r0 = grow + g, r1 = grow + g + 8;
#pragma unroll
                for (int nj = 0; nj < 8; nj++) {
                    int c = kt*FKT + nj*8 + 2*tg;
                    if (c     > r0) s[nj][0] = -1e30f;
                    if (c + 1 > r0) s[nj][1] = -1e30f;
                    if (c     > r1) s[nj][2] = -1e30f;
                    if (c + 1 > r1) s[nj][3] = -1e30f;
                }
            }
            float mt0 = -1e30f, mt1 = -1e30f;
#pragma unroll
            for (int nj = 0; nj < 8; nj++) {
                mt0 = fmaxf(mt0, fmaxf(s[nj][0], s[nj][1]));
                mt1 = fmaxf(mt1, fmaxf(s[nj][2], s[nj][3]));
            }
            mt0 = fmaxf(mt0, __shfl_xor_sync(0xffffffffu, mt0, 1));
            mt0 = fmaxf(mt0, __shfl_xor_sync(0xffffffffu, mt0, 2));
            mt1 = fmaxf(mt1, __shfl_xor_sync(0xffffffffu, mt1, 1));
            mt1 = fmaxf(mt1, __shfl_xor_sync(0xffffffffu, mt1, 2));
            float mn0 = fmaxf(m0, mt0), mn1 = fmaxf(m1, mt1);
            float c0 = __expf(m0 - mn0), c1 = __expf(m1 - mn1);
            l0 *= c0; l1 *= c1;
#pragma unroll
            for (int nj = 0; nj < 8; nj++) {
                o[nj][0] *= c0; o[nj][1] *= c0;
                o[nj][2] *= c1; o[nj][3] *= c1;
            }
            float rs0 = 0.f, rs1 = 0.f;
#pragma unroll
            for (int nj = 0; nj < 8; nj++) {
                float p0 = __expf(s[nj][0] - mn0);
                float p1 = __expf(s[nj][1] - mn0);
                float p2 = __expf(s[nj][2] - mn1);
                float p3 = __expf(s[nj][3] - mn1);
                rs0 += p0 + p1; rs1 += p2 + p3;
                int w = nj*4 + tg;
                ((half2*)Ps)[ ((wrow+g  )*FSTW + w) ] = __floats2half2_rn(p0, p1);
                ((half2*)Ps)[ ((wrow+g+8)*FSTW + w) ] = __floats2half2_rn(p2, p3);
            }
            rs0 += __shfl_xor_sync(0xffffffffu, rs0, 1);
            rs0 += __shfl_xor_sync(0xffffffffu, rs0, 2);
            rs1 += __shfl_xor_sync(0xffffffffu, rs1, 1);
            rs1 += __shfl_xor_sync(0xffffffffu, rs1, 2);
            l0 += rs0; l1 += rs1;
            m0 = mn0; m1 = mn1;
            __syncwarp();
            pend = true;
            pkt  = kt;
        }
    }

    if (pend) {
        const unsigned* Vs = Vst + (pkt%3)*FKT*FSTW;
#pragma unroll
        for (int k0w = 0; k0w < 32; k0w += 8) {
            unsigned a0 = Ps[(wrow+g  )*FSTW + k0w+tg];
            unsigned a1 = Ps[(wrow+g+8)*FSTW + k0w+tg];
            unsigned a2 = Ps[(wrow+g  )*FSTW + k0w+4+tg];
            unsigned a3 = Ps[(wrow+g+8)*FSTW + k0w+4+tg];
#pragma unroll
            for (int nj = 0; nj < 8; nj++) {
                unsigned b0 = Vs[(nj*8+g)*FSTW + k0w+tg];
                unsigned b1 = Vs[(nj*8+g)*FSTW + k0w+4+tg];
                mma_f16(o[nj], a0, a1, a2, a3, b0, b1);
            }
        }
    }

    float il0 = 1.f/l0, il1 = 1.f/l1;
    size_t tok0 = (size_t)(b*SS + qb*FQ + wrow + g);
    size_t tok1 = tok0 + 8;
#pragma unroll
    for (int nj = 0; nj < 8; nj++) {
        int col = h*HDIM + nj*8 + 2*tg;
        *(half2*)(out + tok0*DM + col) = __floats2half2_rn(o[nj][0]*il0, o[nj][1]*il0);
        *(half2*)(out + tok1*DM + col) = __floats2half2_rn(o[nj][2]*il1, o[nj][3]*il1);
    }
}

// ---------------- router ----------------
__global__ void router_kernel(const float* __restrict__ x2, const float* __restrict__ rw) {
    int t = (blockIdx.x*blockDim.x + threadIdx.x) >> 5;
    int lane = threadIdx.x & 31;
    if (t >= NT) return;
    const float* xr = x2 + (size_t)t*DM;
    float acc[NE];
#pragma unroll
    for (int e = 0; e < NE; e++) acc[e] = 0.f;
    for (int d = lane; d < DM; d += 32) {
        float xv = xr[d];
        float4 r0 = ((const float4*)rw)[d*2];
        float4 r1 = ((const float4*)rw)[d*2+1];
        acc[0]+=xv*r0.x; acc[1]+=xv*r0.y; acc[2]+=xv*r0.z; acc[3]+=xv*r0.w;
        acc[4]+=xv*r1.x; acc[5]+=xv*r1.y; acc[6]+=xv*r1.z; acc[7]+=xv*r1.w;
    }
#pragma unroll
    for (int o = 16; o; o >>= 1)
#pragma unroll
        for (int e = 0; e < NE; e++)
            acc[e] += __shfl_xor_sync(0xffffffffu, acc[e], o);
    if (lane == 0) {
        int e0 = 0; float m0 = acc[0];
#pragma unroll
        for (int e = 1; e < NE; e++) if (acc[e] > m0) { m0 = acc[e]; e0 = e; }
        int e1 = -1; float m1 = -3.4e38f;
#pragma unroll
        for (int e = 0; e < NE; e++) if (e != e0 && acc[e] > m1) { m1 = acc[e]; e1 = e; }
        float p1 = expf(m1 - m0);
        float w0 = 1.f / (1.f + p1);
        float w1 = p1 / (1.f + p1);
        g_top_e[2*t] = e0; g_top_e[2*t+1] = e1;
        g_top_w[2*t] = w0; g_top_w[2*t+1] = w1;
        atomicAdd(&g_cnt[e0], 1);
        atomicAdd(&g_cnt[e1], 1);
    }
}

__global__ void moe_init_kernel() {
    int i = blockIdx.x*blockDim.x + threadIdx.x;
    if (i < NE) { g_cnt[i] = 0; g_fill[i] = 0; }
    if (i < CAP) g_perm[i] = -1;
}

__global__ void segoff_kernel() {
    int off = 0;
    for (int e = 0; e < NE; e++) {
        g_segoff[e] = off;
        off += ((g_cnt[e] + 127) >> 7) << 7;
    }
    g_segoff[NE] = off;
    g_total = off;
}

__global__ void fill_kernel() {
    int i = blockIdx.x*blockDim.x + threadIdx.x;
    if (i >= NT*2) return;
    int e = g_top_e[i];
    int pos = g_segoff[e] + atomicAdd(&g_fill[e], 1);
    g_perm[pos] = i >> 1;
    g_tok_slot[i] = pos;
}

__global__ void combine_kernel(float* __restrict__ out) {
    int i = blockIdx.x*blockDim.x + threadIdx.x;
    int n = i >> 8, d4 = i & 255;
    int s0 = g_tok_slot[2*n], s1 = g_tok_slot[2*n+1];
    float w0 = g_top_w[2*n], w1 = g_top_w[2*n+1];
    float4 hv = *(float4*)&g_hidden[(size_t)n*DM + d4*4];
    const half2* y0p = (const half2*)&g_yh[(size_t)s0*DM + d4*4];
    const half2* y1p = (const half2*)&g_yh[(size_t)s1*DM + d4*4];
    float2 ya0 = __half22float2(y0p[0]), yb0 = __half22float2(y0p[1]);
    float2 ya1 = __half22float2(y1p[0]), yb1 = __half22float2(y1p[1]);
    float4 r;
    r.x = hv.x + w0*ya0.x + w1*ya1.x;
    r.y = hv.y + w0*ya0.y + w1*ya1.y;
    r.z = hv.z + w0*yb0.x + w1*yb1.x;
    r.w = hv.w + w0*yb0.y + w1*yb1.y;
    *(float4*)&out[(size_t)n*DM + d4*4] = r;
}

// ---------------- launch (single stream) ----------------
extern "C" void kernel_launch(void* const* d_in, const int* in_sizes, int n_in,
                              void* d_out, int out_size) {
    const float* hs   = (const float*)d_in[0];
    const float* ln1w = (const float*)d_in[1];
    const float* ln2w = (const float*)d_in[2];
    const float* wqkv = (const float*)d_in[3];
    const float* outw = (const float*)d_in[4];
    const float* rw   = (const float*)d_in[5];
    const float* w1   = (const float*)d_in[6];
    const float* v1   = (const float*)d_in[7];
    const float* w2   = (const float*)d_in[8];
    float* out = (float*)d_out;

    float *phid, *px2;
    __half *px1h, *px2h, *pattnh, *ph1h, *pyh, *pqkvh, *pvth;
    __half *pwqkvh, *poutwh, *pw1h, *pv1h, *pw2h;
    cudaGetSymbolAddress((void**)&phid,  g_hidden);
    cudaGetSymbolAddress((void**)&px2,   g_x2);
    cudaGetSymbolAddress((void**)&px1h,  g_x1h);
    cudaGetSymbolAddress((void**)&px2h,  g_x2h);
    cudaGetSymbolAddress((void**)&pattnh,g_attnh);
    cudaGetSymbolAddress((void**)&ph1h,  g_h1h);
    cudaGetSymbolAddress((void**)&pyh,   g_yh);
    cudaGetSymbolAddress((void**)&pqkvh, g_qkvh);
    cudaGetSymbolAddress((void**)&pvth,  g_vth);
    cudaGetSymbolAddress((void**)&pwqkvh,g_wqkvh);
    cudaGetSymbolAddress((void**)&poutwh,g_outwh);
    cudaGetSymbolAddress((void**)&pw1h,  g_w1h);
    cudaGetSymbolAddress((void**)&pv1h,  g_v1h);
    cudaGetSymbolAddress((void**)&pw2h,  g_w2h);

    cudaFuncSetAttribute(flash_h_kernel,
                         cudaFuncAttributeMaxDynamicSharedMemorySize, FLASH_SMEM);
    cudaFuncSetAttribute(hgemm<4,false,false>,
                         cudaFuncAttributeMaxDynamicSharedMemorySize, HGEMM_SMEM);
    cudaFuncSetAttribute(hgemm<2,false,false>,
                         cudaFuncAttributeMaxDynamicSharedMemorySize, HGEMM_SMEM);
    cudaFuncSetAttribute(hgemm<5,false,true>,
                         cudaFuncAttributeMaxDynamicSharedMemorySize, HGEMM_SMEM);
    cudaFuncSetAttribute(up_hgemm,
                         cudaFuncAttributeMaxDynamicSharedMemorySize, UP_SMEM);

    // ---- weight conversions ----
    conv2_h<<<(2*NE*FF*DM/4 + 255)/256, 256>>>(w1, pw1h, v1, pv1h, NE*FF*DM/4);
    convT_h<<<dim3(DM/64, QKVN/32, 1), dim3(32,8)>>>(wqkv, pwqkvh, DM, QKVN);
    convT_h<<<dim3(DM/64, DM/32, 1), dim3(32,8)>>>(outw, poutwh, DM, DM);
    convT_h<<<dim3(FF/64, DM/32, NE), dim3(32,8)>>>(w2, pw2h, FF, DM);

    // LN1 -> QKV(clip, fp16) -> RoPE+V^T -> attention -> out-proj(+resid)
    ln_kernel<false,true><<<NT, 256>>>(hs, ln1w, nullptr, px1h);
    hgemm<4,false,false><<<dim3(QKVN/128, NT/128), 256, HGEMM_SMEM>>>(
        px1h, pwqkvh, pqkvh, nullptr, QKVN, DM, 0);
    ropetab_kernel<<<1, 32>>>();
    ropevt_kernel<<<NRBLK + NVBLK, 256>>>();
    flash_h_kernel<<<dim3(SS/FQ, BB*NH), 256, FLASH_SMEM>>>(pqkvh, pvth, pattnh);
    hgemm<2,false,false><<<dim3(DM/128, NT/128), 256, HGEMM_SMEM>>>(
        pattnh, poutwh, phid, hs, DM, DM, 0);

    // LN2 -> router -> top-2 dispatch
    ln_kernel<true,true><<<NT, 256>>>(phid, ln2w, px2, px2h);
    moe_init_kernel<<<(CAP + 255)/256, 256>>>();
    router_kernel<<<NT/8, 256>>>(px2, rw);
    segoff_kernel<<<1, 1>>>();
    fill_kernel<<<(NT*2 + 255)/256, 256>>>();

    // MoE: fused dual-B up (silu epilogue, fp16 out), then down (fp16 y)
    up_hgemm<<<dim3(FF/128, CAP/128), 256, UP_SMEM>>>(px2h, pw1h, pv1h, ph1h);
    hgemm<5,false,true><<<dim3(DM/128, CAP/128), 256, HGEMM_SMEM>>>(
        ph1h, pw2h, pyh, nullptr, DM, FF, (long)DM*FF);

    // resid2 + gated expert outputs
    combine_kernel<<<NT, 256>>>(out);
}

// round 15
// speedup vs baseline: 1.4989x; 1.0089x over previous
#include <cuda_runtime.h>
#include <cuda_fp16.h>
#include <math.h>

// ---------------- problem constants ----------------
#define BB 2
#define SS 2048
#define DM 1024
#define NH 16
#define NKV 4
#define HDIM 64
#define NE 8
#define FF 2048
#define NT (BB*SS)                    // 4096 tokens
#define QKVN (DM + 2*NKV*HDIM)        // 1536
#define CAP (2*NT + NE*128)           // 9216 padded MoE slots
#define SCALEQ 0.125f
#define CLIPV 8.0f

// ---------------- device scratch ----------------
__device__ float g_hidden[NT*DM];
__device__ float g_x2[NT*DM];
__device__ int   g_top_e[NT*2];
__device__ float g_top_w[NT*2];
__device__ int   g_cnt[NE];
__device__ int   g_fill[NE];
__device__ int   g_segoff[NE+1];
__device__ int   g_total;
__device__ int   g_perm[CAP];
__device__ int   g_tok_slot[NT*2];
__device__ float g_invfreq[32];
// fp16 buffers
__device__ __half g_x1h[NT*DM];
__device__ __half g_x2h[NT*DM];
__device__ __half g_attnh[NT*DM];
__device__ __half g_h1h[CAP*FF];
__device__ __half g_yh[CAP*DM];
__device__ __half g_qkvh[NT*QKVN];           // qkv fp16, q/k roped in place
__device__ __half g_vth[BB*NKV*HDIM*SS];     // V transposed: [b][kvh][dim][seq]
__device__ __half g_wqkvh[QKVN*DM];
__device__ __half g_outwh[DM*DM];
__device__ __half g_w1h[NE*FF*DM];
__device__ __half g_v1h[NE*FF*DM];
__device__ __half g_w2h[NE*DM*FF];

// ---------------- weight conversion + all one-time init (first kernel) ----------
__global__ void conv2_h(const float* __restrict__ in1, __half* __restrict__ out1,
                        const float* __restrict__ in2, __half* __restrict__ out2,
                        int n4) {
    int gi = blockIdx.x*blockDim.x + threadIdx.x;
    // folded init work (runs before anything that reads these)
    if (gi < 32) g_invfreq[gi] = (float)pow(10000.0, -(double)gi / 32.0);
    if (gi < NE) { g_cnt[gi] = 0; g_fill[gi] = 0; }
    if (gi < CAP) g_perm[gi] = -1;
    int i = gi;
    const float* in; __half* out;
    if (i >= n4) { i -= n4; in = in2; out = out2; } else { in = in1; out = out1; }
    if (i >= n4) return;
    float4 v = ((const float4*)in)[i];
    ((half2*)out)[i*2]   = __floats2half2_rn(v.x, v.y);
    ((half2*)out)[i*2+1] = __floats2half2_rn(v.z, v.w);
}
// transpose-convert: in [R][C] fp32 -> out [C][R] fp16; 64(R) x 32(C) tiles
__global__ void convT_h(const float* __restrict__ in, __half* __restrict__ out,
                        int R, int C) {
    __shared__ float t[32][65];
    int e = blockIdx.z;
    in  += (size_t)e*R*C;
    out += (size_t)e*R*C;
    int r0 = blockIdx.x*64, c0 = blockIdx.y*32;
    int tx = threadIdx.x, ty = threadIdx.y;
#pragma unroll
    for (int k = 0; k < 64; k += 8)
        t[tx][ty+k] = in[(size_t)(r0+ty+k)*C + c0+tx];
    __syncthreads();
#pragma unroll
    for (int k = 0; k < 32; k += 8) {
        int row = ty + k;
        half2 hv = __floats2half2_rn(t[row][2*tx], t[row][2*tx+1]);
        *(half2*)(out + (size_t)(c0+row)*R + r0 + 2*tx) = hv;
    }
}

// ---------------- layernorm ----------------
template<bool OUTF, bool OUTH>
__global__ void ln_kernel(const float* __restrict__ x, const float* __restrict__ w,
                          float* __restrict__ outf, __half* __restrict__ outh) {
    int row = blockIdx.x, tid = threadIdx.x;
    float4 v = ((const float4*)(x + (size_t)row*DM))[tid];
    float s = v.x+v.y+v.z+v.w;
    float q = v.x*v.x+v.y*v.y+v.z*v.z+v.w*v.w;
#pragma unroll
    for (int o = 16; o; o >>= 1) {
        s += __shfl_xor_sync(0xffffffffu, s, o);
        q += __shfl_xor_sync(0xffffffffu, q, o);
    }
    __shared__ float ssm[8], qsm[8];
    if ((tid & 31) == 0) { ssm[tid>>5] = s; qsm[tid>>5] = q; }
    __syncthreads();
    float ts = 0.f, tq = 0.f;
#pragma unroll
    for (int i = 0; i < 8; i++) { ts += ssm[i]; tq += qsm[i]; }
    float mu  = ts * (1.f/DM);
    float var = tq * (1.f/DM) - mu*mu;
    float rs  = rsqrtf(var + 1e-5f);
    float4 wv = ((const float4*)w)[tid];
    float4 r;
    r.x = (v.x-mu)*rs*wv.x; r.y = (v.y-mu)*rs*wv.y;
    r.z = (v.z-mu)*rs*wv.z; r.w = (v.w-mu)*rs*wv.w;
    if (OUTF) ((float4*)(outf + (size_t)row*DM))[tid] = r;
    if (OUTH) {
        ((half2*)(outh + (size_t)row*DM))[tid*2]   = __floats2half2_rn(r.x, r.y);
        ((half2*)(outh + (size_t)row*DM))[tid*2+1] = __floats2half2_rn(r.z, r.w);
    }
}

// ---------------- mma / cp.async helpers ----------------
__device__ __forceinline__ void mma_f16(float* c,
        unsigned a0, unsigned a1, unsigned a2, unsigned a3,
        unsigned b0, unsigned b1) {
    asm volatile("mma.sync.aligned.m16n8k16.row.col.f32.f16.f16.f32 "
        "{%0,%1,%2,%3}, {%4,%5,%6,%7}, {%8,%9}, {%0,%1,%2,%3};"
        : "+f"(c[0]), "+f"(c[1]), "+f"(c[2]), "+f"(c[3])
        : "r"(a0), "r"(a1), "r"(a2), "r"(a3), "r"(b0), "r"(b1));
}
__device__ __forceinline__ void cp16(void* smem_dst, const void* gsrc, int src_bytes) {
    unsigned sa = (unsigned)__cvta_generic_to_shared(smem_dst);
    asm volatile("cp.async.cg.shared.global [%0], [%1], 16, %2;\n"
                 :: "r"(sa), "l"(gsrc), "r"(src_bytes));
}
#define CP_COMMIT() asm volatile("cp.async.commit_group;\n")
#define CP_WAITG2() asm volatile("cp.async.wait_group 2;\n")
#define CP_WAITG1() asm volatile("cp.async.wait_group 1;\n")

// ---------------- fp16 GEMM: 128x128 tile, K=32 halfs/slab, 4-stage cp.async ------
// EPI: 0 none(f32), 2 +resid(f32), 4 clip(fp16 out), 5 fp16 out
#define HSTRW 20
#define HSLABW (128*HSTRW)
#define HNSTG 4
#define HGEMM_SMEM (HNSTG*2*HSLABW*4)   // 81920 B
template<int EPI, bool GATHER, bool EXPERT>
__global__ void __launch_bounds__(256, 2)
hgemm(const __half* __restrict__ A, const __half* __restrict__ Bm,
      void* __restrict__ Cv, const float* __restrict__ resid,
      int N, int K, long ldbE) {
    int mbase = blockIdx.y * 128;
    if (EXPERT) {
        if (mbase >= g_total) return;
        int e = 0;
#pragma unroll
        for (int i = 0; i < NE; i++) if (g_segoff[i+1] <= mbase) e = i + 1;
        Bm += (size_t)e * ldbE;
    }
    int nbase = blockIdx.x * 128;
    extern __shared__ unsigned smw[];
    int tid  = threadIdx.x;
    int lane = tid & 31, warp = tid >> 5;
    int wM = (warp & 1) * 64;
    int wN = (warp >> 1) * 32;
    int g  = lane >> 2, tg = lane & 3;

    int ar = tid >> 1, ac = (tid & 1) * 16;
    const __half* arow;
    int asz = 16;
    if (GATHER) {
        int tok = g_perm[mbase + ar];
        asz  = (tok >= 0) ? 16 : 0;
        arow = A + (size_t)(tok >= 0 ? tok : 0) * K;
    } else {
        arow = A + (size_t)(mbase + ar) * K;
    }
    const __half* brow = Bm + (size_t)(nbase + ar) * K;

    float acc[4][4][4];
#pragma unroll
    for (int mi = 0; mi < 4; mi++)
#pragma unroll
        for (int nj = 0; nj < 4; nj++)
#pragma unroll
            for (int r = 0; r < 4; r++) acc[mi][nj][r] = 0.f;

    auto load_slab = [&](int s, int kb) {
        unsigned* As = smw + s*(2*HSLABW);
        unsigned* Bs = As + HSLABW;
        cp16(&As[ar*HSTRW + ac/2],     arow + kb + ac,     asz);
        cp16(&As[ar*HSTRW + ac/2 + 4], arow + kb + ac + 8, asz);
        cp16(&Bs[ar*HSTRW + ac/2],     brow + kb + ac,     16);
        cp16(&Bs[ar*HSTRW + ac/2 + 4], brow + kb + ac + 8, 16);
    };

    int ns = K >> 5;
#pragma unroll
    for (int j = 0; j < 3; j++) { load_slab(j, j*32); CP_COMMIT(); }

    for (int i = 0; i < ns; i++) {
        int s = i & (HNSTG-1);
        CP_WAITG2();
        __syncthreads();
        int j = i + 3;
        if (j < ns) load_slab(j & (HNSTG-1), j*32);
        CP_COMMIT();
        const unsigned* as = smw + s*(2*HSLABW);
        const unsigned* bs = as + HSLABW;
#pragma unroll
        for (int ks = 0; ks < 2; ks++) {
            int k0w = ks * 8;
            unsigned bf[4][2];
#pragma unroll
            for (int nj = 0; nj < 4; nj++) {
                int n = wN + nj*8 + g;
                bf[nj][0] = bs[n*HSTRW + k0w + tg];
                bf[nj][1] = bs[n*HSTRW + k0w + 4 + tg];
            }
#pragma unroll
            for (int mi = 0; mi < 4; mi++) {
                int m = wM + mi*16 + g;
                unsigned a0 = as[m*HSTRW + k0w + tg];
                unsigned a1 = as[(m+8)*HSTRW + k0w + tg];
                unsigned a2 = as[m*HSTRW + k0w + 4 + tg];
                unsigned a3 = as[(m+8)*HSTRW + k0w + 4 + tg];
#pragma unroll
                for (int nj = 0; nj < 4; nj++)
                    mma_f16(acc[mi][nj], a0, a1, a2, a3, bf[nj][0], bf[nj][1]);
            }
        }
    }
    float* C = (float*)Cv;
    __half* Ch = (__half*)Cv;
#pragma unroll
    for (int mi = 0; mi < 4; mi++) {
#pragma unroll
        for (int nj = 0; nj < 4; nj++) {
            int r0 = mbase + wM + mi*16 + g;
            int r1 = r0 + 8;
            int c  = nbase + wN + nj*8 + tg*2;
            float v0 = acc[mi][nj][0], v1 = acc[mi][nj][1];
            float v2 = acc[mi][nj][2], v3 = acc[mi][nj][3];
            if (EPI == 4) {
                v0 = fminf(fmaxf(v0,-CLIPV),CLIPV); v1 = fminf(fmaxf(v1,-CLIPV),CLIPV);
                v2 = fminf(fmaxf(v2,-CLIPV),CLIPV); v3 = fminf(fmaxf(v3,-CLIPV),CLIPV);
            }
            if (EPI == 2) {
                float2 r0v = *(const float2*)(resid + (size_t)r0*N + c);
                float2 r1v = *(const float2*)(resid + (size_t)r1*N + c);
                v0 += r0v.x; v1 += r0v.y; v2 += r1v.x; v3 += r1v.y;
            }
            if (EPI == 4 || EPI == 5) {
                *(half2*)(Ch + (size_t)r0*N + c) = __floats2half2_rn(v0, v1);
                *(half2*)(Ch + (size_t)r1*N + c) = __floats2half2_rn(v2, v3);
            } else {
                *(float2*)(C + (size_t)r0*N + c) = make_float2(v0, v1);
                *(float2*)(C + (size_t)r1*N + c) = make_float2(v2, v3);
            }
        }
    }
}

// ---------------- fp16 dual-B up GEMM ----------------
#define UNSTG 4
#define UP_SMEM (UNSTG*3*HSLABW*4)     // 122880 B
__global__ void __launch_bounds__(256, 1)
up_hgemm(const __half* __restrict__ A, const __half* __restrict__ Bw,
         const __half* __restrict__ Bv, __half* __restrict__ C) {
    const int N = FF, K = DM;
    int mbase = blockIdx.y * 128;
    if (mbase >= g_total) return;
    int e = 0;
#pragma unroll
    for (int i = 0; i < NE; i++) if (g_segoff[i+1] <= mbase) e = i + 1;
    Bw += (size_t)e * FF * DM;
    Bv += (size_t)e * FF * DM;
    int nbase = blockIdx.x * 128;
    extern __shared__ unsigned smw[];
    int tid  = threadIdx.x;
    int lane = tid & 31, warp = tid >> 5;
    int wM = (warp & 1) * 64;
    int wN = (warp >> 1) * 32;
    int g  = lane >> 2, tg = lane & 3;

    int ar = tid >> 1, ac = (tid & 1) * 16;
    int tok = g_perm[mbase + ar];
    int asz  = (tok >= 0) ? 16 : 0;
    const __half* arow = A + (size_t)(tok >= 0 ? tok : 0) * K;
    const __half* wrow = Bw + (size_t)(nbase + ar) * K;
    const __half* vrow = Bv + (size_t)(nbase + ar) * K;

    float accw[4][4][4], accv[4][4][4];
#pragma unroll
    for (int mi = 0; mi < 4; mi++)
#pragma unroll
        for (int nj = 0; nj < 4; nj++)
#pragma unroll
            for (int r = 0; r < 4; r++) { accw[mi][nj][r] = 0.f; accv[mi][nj][r] = 0.f; }

    auto load_slab = [&](int s, int kb) {
        unsigned* As = smw + s*(3*HSLABW);
        unsigned* Ws = As + HSLABW;
        unsigned* Vs = Ws + HSLABW;
        cp16(&As[ar*HSTRW + ac/2],     arow + kb + ac,     asz);
        cp16(&As[ar*HSTRW + ac/2 + 4], arow + kb + ac + 8, asz);
        cp16(&Ws[ar*HSTRW + ac/2],     wrow + kb + ac,     16);
        cp16(&Ws[ar*HSTRW + ac/2 + 4], wrow + kb + ac + 8, 16);
        cp16(&Vs[ar*HSTRW + ac/2],     vrow + kb + ac,     16);
        cp16(&Vs[ar*HSTRW + ac/2 + 4], vrow + kb + ac + 8, 16);
    };

    const int ns = K >> 5;
#pragma unroll
    for (int j = 0; j < 3; j++) { load_slab(j, j*32); CP_COMMIT(); }

    for (int i = 0; i < ns; i++) {
        int s = i & (UNSTG-1);
        CP_WAITG2();
        __syncthreads();
        int j = i + 3;
        if (j < ns) load_slab(j & (UNSTG-1), j*32);
        CP_COMMIT();
        const unsigned* as = smw + s*(3*HSLABW);
        const unsigned* ws = as + HSLABW;
        const unsigned* vs = ws + HSLABW;
#pragma unroll
        for (int ks = 0; ks < 2; ks++) {
            int k0w = ks * 8;
            unsigned bw[4][2], bv[4][2];
#pragma unroll
            for (int nj = 0; nj < 4; nj++) {
                int n = wN + nj*8 + g;
                bw[nj][0] = ws[n*HSTRW + k0w + tg];
                bw[nj][1] = ws[n*HSTRW + k0w + 4 + tg];
                bv[nj][0] = vs[n*HSTRW + k0w + tg];
                bv[nj][1] = vs[n*HSTRW + k0w + 4 + tg];
            }
#pragma unroll
            for (int mi = 0; mi < 4; mi++) {
                int m = wM + mi*16 + g;
                unsigned a0 = as[m*HSTRW + k0w + tg];
                unsigned a1 = as[(m+8)*HSTRW + k0w + tg];
                unsigned a2 = as[m*HSTRW + k0w + 4 + tg];
                unsigned a3 = as[(m+8)*HSTRW + k0w + 4 + tg];
#pragma unroll
                for (int nj = 0; nj < 4; nj++) {
                    mma_f16(accw[mi][nj], a0, a1, a2, a3, bw[nj][0], bw[nj][1]);
                    mma_f16(accv[mi][nj], a0, a1, a2, a3, bv[nj][0], bv[nj][1]);
                }
            }
        }
    }
#pragma unroll
    for (int mi = 0; mi < 4; mi++) {
#pragma unroll
        for (int nj = 0; nj < 4; nj++) {
            int r0 = mbase + wM + mi*16 + g;
            int r1 = r0 + 8;
            int c  = nbase + wN + nj*8 + tg*2;
            float w0 = accw[mi][nj][0], w1 = accw[mi][nj][1];
            float w2 = accw[mi][nj][2], w3 = accw[mi][nj][3];
            float v0 = accv[mi][nj][0] * (w0 / (1.f + __expf(-w0)));
            float v1 = accv[mi][nj][1] * (w1 / (1.f + __expf(-w1)));
            float v2 = accv[mi][nj][2] * (w2 / (1.f + __expf(-w2)));
            float v3 = accv[mi][nj][3] * (w3 / (1.f + __expf(-w3)));
            *(half2*)(C + (size_t)r0*N + c) = __floats2half2_rn(v0, v1);
            *(half2*)(C + (size_t)r1*N + c) = __floats2half2_rn(v2, v3);
        }
    }
}

// ---------------- RoPE (fp16 in-place) + V transpose, one launch ----------------
#define NRBLK ((NT*20*32)/256)      // 10240 rope blocks
#define NVBLK (32*2*BB*NKV)         // 512 vt blocks
__global__ void ropevt_kernel() {
    int bid = blockIdx.x;
    int tid = threadIdx.x;
    if (bid < NRBLK) {
        int idx = bid*256 + tid;
        int i    = idx & 31;
        int head = (idx >> 5) % 20;
        int n    = idx / (32*20);
        int s    = n & (SS - 1);
        float ang = (float)s * g_invfreq[i];
        float sn, cs;
        sincosf(ang, &sn, &cs);
        __half* base = g_qkvh + (size_t)n*QKVN + (head < NH ? head*HDIM : DM + (head-NH)*HDIM);
        float x1 = __half2float(base[i]), x2 = __half2float(base[i+32]);
        float y1 = x1*cs - x2*sn;
        float y2 = x1*sn + x2*cs;
        if (head < NH) { y1 *= SCALEQ; y2 *= SCALEQ; }
        base[i]    = __float2half_rn(y1);
        base[i+32] = __float2half_rn(y2);
    } else {
        __shared__ float t[32][65];
        int vb = bid - NRBLK;
        int s0 = (vb & 31) * 64;
        int d0 = ((vb >> 5) & 1) * 32;
        int bk = vb >> 6;
        int tx = tid & 31, ty = tid >> 5;
        const __half* src = g_qkvh + (size_t)((bk>>2)*SS)*QKVN + DM + NKV*HDIM + (bk&3)*HDIM;
#pragma unroll
        for (int k = 0; k < 64; k += 8)
            t[tx][ty+k] = __half2float(src[(size_t)(s0+ty+k)*QKVN + d0+tx]);
        __syncthreads();
        __half* dst = g_vth + ((size_t)bk*HDIM)*SS;
#pragma unroll
        for (int k = 0; k < 32; k += 8) {
            int row = ty + k;
            half2 hv = __floats2half2_rn(t[row][2*tx], t[row][2*tx+1]);
            *(half2*)(dst + (size_t)(d0+row)*SS + s0 + 2*tx) = hv;
        }
    }
}

// ---------------- fp16 flash attention: QK | PV(prev) | softmax pipeline ----------------
#define FQ 128
#define FKT 64
#define FSTW 36
#define FLASH_SMEM ((FQ + 2*FKT + 3*FKT + FQ)*FSTW*4)   // 82944 B
__global__ void __launch_bounds__(256)
flash_h_kernel(const __half* __restrict__ qkvh, const __half* __restrict__ vth,
               __half* __restrict__ out) {
    extern __shared__ unsigned smw[];
    unsigned* Qs = smw;
    unsigned* Kst = Qs + FQ*FSTW;
    unsigned* Vst = Kst + 2*FKT*FSTW;
    unsigned* Ps = Vst + 3*FKT*FSTW;
    int qb = gridDim.x - 1 - blockIdx.x;
    int bh = blockIdx.y;
    int b = bh >> 4, h = bh & 15, kh = h >> 2;
    int tid = threadIdx.x, lane = tid & 31, warp = tid >> 5;
    int g = lane >> 2, tg = lane & 3;

    {
        const __half* qp = qkvh + (size_t)(b*SS + qb*FQ)*QKVN + h*HDIM;
        int r = tid >> 1;
        int c0 = (tid & 1) * 4;
#pragma unroll
        for (int q = 0; q < 4; q++)
            cp16(&Qs[r*FSTW + (c0+q)*4], qp + (size_t)r*QKVN + (c0+q)*8, 16);
    }
    int kvr = tid >> 2, kvc = (tid & 3) * 2;
    const __half* kbase = qkvh + (size_t)(b*SS)*QKVN + DM + kh*HDIM;
    const __half* vtb = vth + ((size_t)(b*NKV + kh)*HDIM)*SS;
    auto load_kv = [&](int kst, int vst, int kt) {
        const __half* kp = kbase + (size_t)(kt*FKT + kvr)*QKVN;
        const __half* vp = vtb + (size_t)kvr*SS + kt*FKT;
        unsigned* kd = Kst + kst*FKT*FSTW + kvr*FSTW;
        unsigned* vd = Vst + vst*FKT*FSTW + kvr*FSTW;
#pragma unroll
        for (int q = 0; q < 2; q++) {
            cp16(kd + (kvc+q)*4, kp + (kvc+q)*8, 16);
            cp16(vd + (kvc+q)*4, vp + (kvc+q)*8, 16);
        }
    };

    int wrow = warp*16;
    int grow = qb*FQ + wrow;

    float m0 = -1e30f, m1 = -1e30f, l0 = 0.f, l1 = 0.f;
    float o[8][4];
#pragma unroll
    for (int nj = 0; nj < 8; nj++)
#pragma unroll
        for (int r = 0; r < 4; r++) o[nj][r] = 0.f;

    int ktmax = 2*qb + 1;
    load_kv(0, 0, 0);
    CP_COMMIT();

    bool pend = false;
    int pkt = 0;

    for (int kt = 0; kt <= ktmax; kt++) {
        __syncthreads();
        if (kt < ktmax) load_kv((kt+1)&1, (kt+1)%3, kt+1);
        CP_COMMIT();
        CP_WAITG1();
        __syncthreads();

        bool act = (kt*FKT <= grow + 15);
        float s[8][4];
        if (act) {
            const unsigned* Ks = Kst + (kt&1)*FKT*FSTW;
#pragma unroll
            for (int nj = 0; nj < 8; nj++)
#pragma unroll
                for (int r = 0; r < 4; r++) s[nj][r] = 0.f;
#pragma unroll
            for (int k0w = 0; k0w < 32; k0w += 8) {
                unsigned a0 = Qs[(wrow+g  )*FSTW + k0w+tg];
                unsigned a1 = Qs[(wrow+g+8)*FSTW + k0w+tg];
                unsigned a2 = Qs[(wrow+g  )*FSTW + k0w+4+tg];
                unsigned a3 = Qs[(wrow+g+8)*FSTW + k0w+4+tg];
#pragma unroll
                for (int nj = 0; nj < 8; nj++) {
                    unsigned b0 = Ks[(nj*8+g)*FSTW + k0w+tg];
                    unsigned b1 = Ks[(nj*8+g)*FSTW + k0w+4+tg];
                    mma_f16(s[nj], a0, a1, a2, a3, b0, b1);
                }
            }
        }

        if (pend) {
            const unsigned* Vs = Vst + (pkt%3)*FKT*FSTW;
#pragma unroll
            for (int k0w = 0; k0w < 32; k0w += 8) {
                unsigned a0 = Ps[(wrow+g  )*FSTW + k0w+tg];
                unsigned a1 = Ps[(wrow+g+8)*FSTW + k0w+tg];
                unsigned a2 = Ps[(wrow+g  )*FSTW + k0w+4+tg];
                unsigned a3 = Ps[(wrow+g+8)*FSTW + k0w+4+tg];
#pragma unroll
                for (int nj = 0; nj < 8; nj++) {
                    unsigned b0 = Vs[(nj*8+g)*FSTW + k0w+tg];
                    unsigned b1 = Vs[(nj*8+g)*FSTW + k0w+4+tg];
                    mma_f16(o[nj], a0, a1, a2, a3, b0, b1);
                }
            }
            pend = false;
        }

        if (act) {
            if (kt >= 2*qb) {
                int r0 = grow + g, r1 = grow + g + 8;
#pragma unroll
                for (int nj = 0; nj < 8; nj++) {
                    int c = kt*FKT + nj*8 + 2*tg;
                    if (c     > r0) s[nj][0] = -1e30f;
                    if (c + 1 > r0) s[nj][1] = -1e30f;
                    if (c     > r1) s[nj][2] = -1e30f;
                    if (c + 1 > r1) s[nj][3] = -1e30f;
                }
            }
            float mt0 = -1e30f, mt1 = -1e30f;
#pragma unroll
            for (int nj = 0; nj < 8; nj++) {
                mt0 = fmaxf(mt0, fmaxf(s[nj][0], s[nj][1]));
                mt1 = fmaxf(mt1, fmaxf(s[nj][2], s[nj][3]));
            }
            mt0 = fmaxf(mt0, __shfl_xor_sync(0xffffffffu, mt0, 1));
            mt0 = fmaxf(mt0, __shfl_xor_sync(0xffffffffu, mt0, 2));
            mt1 = fmaxf(mt1, __shfl_xor_sync(0xffffffffu, mt1, 1));
            mt1 = fmaxf(mt1, __shfl_xor_sync(0xffffffffu, mt1, 2));
            float mn0 = fmaxf(m0, mt0), mn1 = fmaxf(m1, mt1);
            float c0 = __expf(m0 - mn0), c1 = __expf(m1 - mn1);
            l0 *= c0; l1 *= c1;
#pragma unroll
            for (int nj = 0; nj < 8; nj++) {
                o[nj][0] *= c0; o[nj][1] *= c0;
                o[nj][2] *= c1; o[nj][3] *= c1;
            }
            float rs0 = 0.f, rs1 = 0.f;
#pragma unroll
            for (int nj = 0; nj < 8; nj++) {
                float p0 = __expf(s[nj][0] - mn0);
                float p1 = __expf(s[nj][1] - mn0);
                float p2 = __expf(s[nj][2] - mn1);
                float p3 = __expf(s[nj][3] - mn1);
                rs0 += p0 + p1; rs1 += p2 + p3;
                int w = nj*4 + tg;
                ((half2*)Ps)[ ((wrow+g  )*FSTW + w) ] = __floats2half2_rn(p0, p1);
                ((half2*)Ps)[ ((wrow+g+8)*FSTW + w) ] = __floats2half2_rn(p2, p3);
            }
            rs0 += __shfl_xor_sync(0xffffffffu, rs0, 1);
            rs0 += __shfl_xor_sync(0xffffffffu, rs0, 2);
            rs1 += __shfl_xor_sync(0xffffffffu, rs1, 1);
            rs1 += __shfl_xor_sync(0xffffffffu, rs1, 2);
            l0 += rs0; l1 += rs1;
            m0 = mn0; m1 = mn1;
            __syncwarp();
            pend = true;
            pkt  = kt;
        }
    }

    if (pend) {
        const unsigned* Vs = Vst + (pkt%3)*FKT*FSTW;
#pragma unroll
        for (int k0w = 0; k0w < 32; k0w += 8) {
            unsigned a0 = Ps[(wrow+g  )*FSTW + k0w+tg];
            unsigned a1 = Ps[(wrow+g+8)*FSTW + k0w+tg];
            unsigned a2 = Ps[(wrow+g  )*FSTW + k0w+4+tg];
            unsigned a3 = Ps[(wrow+g+8)*FSTW + k0w+4+tg];
#pragma unroll
            for (int nj = 0; nj < 8; nj++) {
                unsigned b0 = Vs[(nj*8+g)*FSTW + k0w+tg];
                unsigned b1 = Vs[(nj*8+g)*FSTW + k0w+4+tg];
                mma_f16(o[nj], a0, a1, a2, a3, b0, b1);
            }
        }
    }

    float il0 = 1.f/l0, il1 = 1.f/l1;
    size_t tok0 = (size_t)(b*SS + qb*FQ + wrow + g);
    size_t tok1 = tok0 + 8;
#pragma unroll
    for (int nj = 0; nj < 8; nj++) {
        int col = h*HDIM + nj*8 + 2*tg;
        *(half2*)(out + tok0*DM + col) = __floats2half2_rn(o[nj][0]*il0, o[nj][1]*il0);
        *(half2*)(out + tok1*DM + col) = __floats2half2_rn(o[nj][2]*il1, o[nj][3]*il1);
    }
}

// ---------------- router ----------------
__global__ void router_kernel(const float* __restrict__ x2, const float* __restrict__ rw) {
    int t = (blockIdx.x*blockDim.x + threadIdx.x) >> 5;
    int lane = threadIdx.x & 31;
    if (t >= NT) return;
    const float* xr = x2 + (size_t)t*DM;
    float acc[NE];
#pragma unroll
    for (int e = 0; e < NE; e++) acc[e] = 0.f;
    for (int d = lane; d < DM; d += 32) {
        float xv = xr[d];
        float4 r0 = ((const float4*)rw)[d*2];
        float4 r1 = ((const float4*)rw)[d*2+1];
        acc[0]+=xv*r0.x; acc[1]+=xv*r0.y; acc[2]+=xv*r0.z; acc[3]+=xv*r0.w;
        acc[4]+=xv*r1.x; acc[5]+=xv*r1.y; acc[6]+=xv*r1.z; acc[7]+=xv*r1.w;
    }
#pragma unroll
    for (int o = 16; o; o >>= 1)
#pragma unroll
        for (int e = 0; e < NE; e++)
            acc[e] += __shfl_xor_sync(0xffffffffu, acc[e], o);
    if (lane == 0) {
        int e0 = 0; float m0 = acc[0];
#pragma unroll
        for (int e = 1; e < NE; e++) if (acc[e] > m0) { m0 = acc[e]; e0 = e; }
        int e1 = -1; float m1 = -3.4e38f;
#pragma unroll
        for (int e = 0; e < NE; e++) if (e != e0 && acc[e] > m1) { m1 = acc[e]; e1 = e; }
        float p1 = expf(m1 - m0);
        float w0 = 1.f / (1.f + p1);
        float w1 = p1 / (1.f + p1);
        g_top_e[2*t] = e0; g_top_e[2*t+1] = e1;
        g_top_w[2*t] = w0; g_top_w[2*t+1] = w1;
        atomicAdd(&g_cnt[e0], 1);
        atomicAdd(&g_cnt[e1], 1);
    }
}

// fill + local segoff (prefix over 8 experts recomputed per thread; thread 0 publishes)
__global__ void fill_kernel() {
    int i = blockIdx.x*blockDim.x + threadIdx.x;
    if (i >= NT*2) return;
    int seg[NE+1];
    int off = 0;
#pragma unroll
    for (int e = 0; e < NE; e++) {
        seg[e] = off;
        off += ((g_cnt[e] + 127) >> 7) << 7;
    }
    seg[NE] = off;
    if (i == 0) {
#pragma unroll
        for (int e = 0; e <= NE; e++) g_segoff[e] = seg[e];
        g_total = off;
    }
    int e = g_top_e[i];
    int pos = seg[e] + atomicAdd(&g_fill[e], 1);
    g_perm[pos] = i >> 1;
    g_tok_slot[i] = pos;
}

__global__ void combine_kernel(float* __restrict__ out) {
    int i = blockIdx.x*blockDim.x + threadIdx.x;
    int n = i >> 8, d4 = i & 255;
    int s0 = g_tok_slot[2*n], s1 = g_tok_slot[2*n+1];
    float w0 = g_top_w[2*n], w1 = g_top_w[2*n+1];
    float4 hv = *(float4*)&g_hidden[(size_t)n*DM + d4*4];
    const half2* y0p = (const half2*)&g_yh[(size_t)s0*DM + d4*4];
    const half2* y1p = (const half2*)&g_yh[(size_t)s1*DM + d4*4];
    float2 ya0 = __half22float2(y0p[0]), yb0 = __half22float2(y0p[1]);
    float2 ya1 = __half22float2(y1p[0]), yb1 = __half22float2(y1p[1]);
    float4 r;
    r.x = hv.x + w0*ya0.x + w1*ya1.x;
    r.y = hv.y + w0*ya0.y + w1*ya1.y;
    r.z = hv.z + w0*yb0.x + w1*yb1.x;
    r.w = hv.w + w0*yb0.y + w1*yb1.y;
    *(float4*)&out[(size_t)n*DM + d4*4] = r;
}

// ---------------- launch (single stream) ----------------
extern "C" void kernel_launch(void* const* d_in, const int* in_sizes, int n_in,
                              void* d_out, int out_size) {
    const float* hs   = (const float*)d_in[0];
    const float* ln1w = (const float*)d_in[1];
    const float* ln2w = (const float*)d_in[2];
    const float* wqkv = (const float*)d_in[3];
    const float* outw = (const float*)d_in[4];
    const float* rw   = (const float*)d_in[5];
    const float* w1   = (const float*)d_in[6];
    const float* v1   = (const float*)d_in[7];
    const float* w2   = (const float*)d_in[8];
    float* out = (float*)d_out;

    float *phid, *px2;
    __half *px1h, *px2h, *pattnh, *ph1h, *pyh, *pqkvh, *pvth;
    __half *pwqkvh, *poutwh, *pw1h, *pv1h, *pw2h;
    cudaGetSymbolAddress((void**)&phid,  g_hidden);
    cudaGetSymbolAddress((void**)&px2,   g_x2);
    cudaGetSymbolAddress((void**)&px1h,  g_x1h);
    cudaGetSymbolAddress((void**)&px2h,  g_x2h);
    cudaGetSymbolAddress((void**)&pattnh,g_attnh);
    cudaGetSymbolAddress((void**)&ph1h,  g_h1h);
    cudaGetSymbolAddress((void**)&pyh,   g_yh);
    cudaGetSymbolAddress((void**)&pqkvh, g_qkvh);
    cudaGetSymbolAddress((void**)&pvth,  g_vth);
    cudaGetSymbolAddress((void**)&pwqkvh,g_wqkvh);
    cudaGetSymbolAddress((void**)&poutwh,g_outwh);
    cudaGetSymbolAddress((void**)&pw1h,  g_w1h);
    cudaGetSymbolAddress((void**)&pv1h,  g_v1h);
    cudaGetSymbolAddress((void**)&pw2h,  g_w2h);

    cudaFuncSetAttribute(flash_h_kernel,
                         cudaFuncAttributeMaxDynamicSharedMemorySize, FLASH_SMEM);
    cudaFuncSetAttribute(hgemm<4,false,false>,
                         cudaFuncAttributeMaxDynamicSharedMemorySize, HGEMM_SMEM);
    cudaFuncSetAttribute(hgemm<2,false,false>,
                         cudaFuncAttributeMaxDynamicSharedMemorySize, HGEMM_SMEM);
    cudaFuncSetAttribute(hgemm<5,false,true>,
                         cudaFuncAttributeMaxDynamicSharedMemorySize, HGEMM_SMEM);
    cudaFuncSetAttribute(up_hgemm,
                         cudaFuncAttributeMaxDynamicSharedMemorySize, UP_SMEM);

    // ---- weight conversions + all one-time init (g_cnt/g_fill/g_perm/invfreq) ----
    conv2_h<<<(2*NE*FF*DM/4 + 255)/256, 256>>>(w1, pw1h, v1, pv1h, NE*FF*DM/4);
    convT_h<<<dim3(DM/64, QKVN/32, 1), dim3(32,8)>>>(wqkv, pwqkvh, DM, QKVN);
    convT_h<<<dim3(DM/64, DM/32, 1), dim3(32,8)>>>(outw, poutwh, DM, DM);
    convT_h<<<dim3(FF/64, DM/32, NE), dim3(32,8)>>>(w2, pw2h, FF, DM);

    // LN1 -> QKV(clip, fp16) -> RoPE+V^T -> attention -> out-proj(+resid)
    ln_kernel<false,true><<<NT, 256>>>(hs, ln1w, nullptr, px1h);
    hgemm<4,false,false><<<dim3(QKVN/128, NT/128), 256, HGEMM_SMEM>>>(
        px1h, pwqkvh, pqkvh, nullptr, QKVN, DM, 0);
    ropevt_kernel<<<NRBLK + NVBLK, 256>>>();
    flash_h_kernel<<<dim3(SS/FQ, BB*NH), 256, FLASH_SMEM>>>(pqkvh, pvth, pattnh);
    hgemm<2,false,false><<<dim3(DM/128, NT/128), 256, HGEMM_SMEM>>>(
        pattnh, poutwh, phid, hs, DM, DM, 0);

    // LN2 -> router -> fill(+segoff)
    ln_kernel<true,true><<<NT, 256>>>(phid, ln2w, px2, px2h);
    router_kernel<<<NT/8, 256>>>(px2, rw);
    fill_kernel<<<(NT*2 + 255)/256, 256>>>();

    // MoE: fused dual-B up (silu epilogue, fp16 out), then down (fp16 y)
    up_hgemm<<<dim3(FF/128, CAP/128), 256, UP_SMEM>>>(px2h, pw1h, pv1h, ph1h);
    hgemm<5,false,true><<<dim3(DM/128, CAP/128), 256, HGEMM_SMEM>>>(
        ph1h, pw2h, pyh, nullptr, DM, FF, (long)DM*FF);

    // resid2 + gated expert outputs
    combine_kernel<<<NT, 256>>>(out);
}

// round 16
// speedup vs baseline: 1.6665x; 1.1118x over previous
#include <cuda_runtime.h>
#include <cuda_fp16.h>
#include <math.h>

// ---------------- problem constants ----------------
#define BB 2
#define SS 2048
#define DM 1024
#define NH 16
#define NKV 4
#define HDIM 64
#define NE 8
#define FF 2048
#define NT (BB*SS)                    // 4096 tokens
#define QKVN (DM + 2*NKV*HDIM)        // 1536
#define CAP (2*NT + NE*128)           // 9216 padded MoE slots
#define SCALEQ 0.125f
#define CLIPV 8.0f

// ---------------- device scratch ----------------
__device__ float g_hidden[NT*DM];
__device__ float g_x2[NT*DM];
__device__ int   g_top_e[NT*2];
__device__ float g_top_w[NT*2];
__device__ int   g_cnt[NE];
__device__ int   g_fill[NE];
__device__ int   g_segoff[NE+1];
__device__ int   g_total;
__device__ int   g_perm[CAP];
__device__ int   g_tok_slot[NT*2];
__device__ float g_invfreq[32];
// fp16 buffers
__device__ __half g_x1h[NT*DM];
__device__ __half g_x2h[NT*DM];
__device__ __half g_attnh[NT*DM];
__device__ __half g_h1h[CAP*FF];
__device__ __half g_yh[CAP*DM];
__device__ __half g_qkvh[NT*QKVN];
__device__ __half g_vth[BB*NKV*HDIM*SS];
__device__ __half g_wqkvh[QKVN*DM];
__device__ __half g_outwh[DM*DM];
__device__ __half g_w1h[NE*FF*DM];
__device__ __half g_v1h[NE*FF*DM];
__device__ __half g_w2h[NE*DM*FF];

// ---------------- weight conversion + one-time init ----------------
__global__ void conv2_h(const float* __restrict__ in1, __half* __restrict__ out1,
                        const float* __restrict__ in2, __half* __restrict__ out2,
                        int n4) {
    int gi = blockIdx.x*blockDim.x + threadIdx.x;
    if (gi < 32) g_invfreq[gi] = (float)pow(10000.0, -(double)gi / 32.0);
    if (gi < NE) { g_cnt[gi] = 0; g_fill[gi] = 0; }
    if (gi < CAP) g_perm[gi] = -1;
    int i = gi;
    const float* in; __half* out;
    if (i >= n4) { i -= n4; in = in2; out = out2; } else { in = in1; out = out1; }
    if (i >= n4) return;
    float4 v = ((const float4*)in)[i];
    ((half2*)out)[i*2]   = __floats2half2_rn(v.x, v.y);
    ((half2*)out)[i*2+1] = __floats2half2_rn(v.z, v.w);
}
__global__ void convT_h(const float* __restrict__ in, __half* __restrict__ out,
                        int R, int C) {
    __shared__ float t[32][65];
    int e = blockIdx.z;
    in  += (size_t)e*R*C;
    out += (size_t)e*R*C;
    int r0 = blockIdx.x*64, c0 = blockIdx.y*32;
    int tx = threadIdx.x, ty = threadIdx.y;
#pragma unroll
    for (int k = 0; k < 64; k += 8)
        t[tx][ty+k] = in[(size_t)(r0+ty+k)*C + c0+tx];
    __syncthreads();
#pragma unroll
    for (int k = 0; k < 32; k += 8) {
        int row = ty + k;
        half2 hv = __floats2half2_rn(t[row][2*tx], t[row][2*tx+1]);
        *(half2*)(out + (size_t)(c0+row)*R + r0 + 2*tx) = hv;
    }
}

// ---------------- layernorm ----------------
template<bool OUTF, bool OUTH>
__global__ void ln_kernel(const float* __restrict__ x, const float* __restrict__ w,
                          float* __restrict__ outf, __half* __restrict__ outh) {
    int row = blockIdx.x, tid = threadIdx.x;
    float4 v = ((const float4*)(x + (size_t)row*DM))[tid];
    float s = v.x+v.y+v.z+v.w;
    float q = v.x*v.x+v.y*v.y+v.z*v.z+v.w*v.w;
#pragma unroll
    for (int o = 16; o; o >>= 1) {
        s += __shfl_xor_sync(0xffffffffu, s, o);
        q += __shfl_xor_sync(0xffffffffu, q, o);
    }
    __shared__ float ssm[8], qsm[8];
    if ((tid & 31) == 0) { ssm[tid>>5] = s; qsm[tid>>5] = q; }
    __syncthreads();
    float ts = 0.f, tq = 0.f;
#pragma unroll
    for (int i = 0; i < 8; i++) { ts += ssm[i]; tq += qsm[i]; }
    float mu  = ts * (1.f/DM);
    float var = tq * (1.f/DM) - mu*mu;
    float rs  = rsqrtf(var + 1e-5f);
    float4 wv = ((const float4*)w)[tid];
    float4 r;
    r.x = (v.x-mu)*rs*wv.x; r.y = (v.y-mu)*rs*wv.y;
    r.z = (v.z-mu)*rs*wv.z; r.w = (v.w-mu)*rs*wv.w;
    if (OUTF) ((float4*)(outf + (size_t)row*DM))[tid] = r;
    if (OUTH) {
        ((half2*)(outh + (size_t)row*DM))[tid*2]   = __floats2half2_rn(r.x, r.y);
        ((half2*)(outh + (size_t)row*DM))[tid*2+1] = __floats2half2_rn(r.z, r.w);
    }
}

// ---------------- mma / cp.async / ldmatrix helpers ----------------
__device__ __forceinline__ void mma_f16(float* c,
        unsigned a0, unsigned a1, unsigned a2, unsigned a3,
        unsigned b0, unsigned b1) {
    asm volatile("mma.sync.aligned.m16n8k16.row.col.f32.f16.f16.f32 "
        "{%0,%1,%2,%3}, {%4,%5,%6,%7}, {%8,%9}, {%0,%1,%2,%3};"
        : "+f"(c[0]), "+f"(c[1]), "+f"(c[2]), "+f"(c[3])
        : "r"(a0), "r"(a1), "r"(a2), "r"(a3), "r"(b0), "r"(b1));
}
__device__ __forceinline__ void cp16(void* smem_dst, const void* gsrc, int src_bytes) {
    unsigned sa = (unsigned)__cvta_generic_to_shared(smem_dst);
    asm volatile("cp.async.cg.shared.global [%0], [%1], 16, %2;\n"
                 :: "r"(sa), "l"(gsrc), "r"(src_bytes));
}
__device__ __forceinline__ void ldsm4(unsigned& r0, unsigned& r1,
                                      unsigned& r2, unsigned& r3, unsigned addr) {
    asm volatile("ldmatrix.sync.aligned.m8n8.x4.shared.b16 {%0,%1,%2,%3}, [%4];"
        : "=r"(r0), "=r"(r1), "=r"(r2), "=r"(r3) : "r"(addr));
}
#define CP_COMMIT() asm volatile("cp.async.commit_group;\n")
#define CP_WAITG2() asm volatile("cp.async.wait_group 2;\n")
#define CP_WAITG1() asm volatile("cp.async.wait_group 1;\n")

// ---------------- fp16 GEMM: 128x128 tile, K=32 halfs/slab, ldmatrix frags -------
// EPI: 0 none(f32), 2 +resid(f32), 4 clip(fp16 out), 5 fp16 out
#define HSTRW 20
#define HSLABW (128*HSTRW)
#define HNSTG 4
#define HGEMM_SMEM (HNSTG*2*HSLABW*4)   // 81920 B
template<int EPI, bool GATHER, bool EXPERT>
__global__ void __launch_bounds__(256, 2)
hgemm(const __half* __restrict__ A, const __half* __restrict__ Bm,
      void* __restrict__ Cv, const float* __restrict__ resid,
      int N, int K, long ldbE) {
    int mbase = blockIdx.y * 128;
    if (EXPERT) {
        if (mbase >= g_total) return;
        int e = 0;
#pragma unroll
        for (int i = 0; i < NE; i++) if (g_segoff[i+1] <= mbase) e = i + 1;
        Bm += (size_t)e * ldbE;
    }
    int nbase = blockIdx.x * 128;
    extern __shared__ unsigned smw[];
    unsigned smbase = (unsigned)__cvta_generic_to_shared(smw);
    int tid  = threadIdx.x;
    int lane = tid & 31, warp = tid >> 5;
    int wM = (warp & 1) * 64;
    int wN = (warp >> 1) * 32;
    int g  = lane >> 2, tg = lane & 3;

    int ar = tid >> 1, ac = (tid & 1) * 16;
    const __half* arow;
    int asz = 16;
    if (GATHER) {
        int tok = g_perm[mbase + ar];
        asz  = (tok >= 0) ? 16 : 0;
        arow = A + (size_t)(tok >= 0 ? tok : 0) * K;
    } else {
        arow = A + (size_t)(mbase + ar) * K;
    }
    const __half* brow = Bm + (size_t)(nbase + ar) * K;

    // ldmatrix per-lane address components (bytes)
    int rowA = (lane & 7) + ((lane >> 3) & 1) * 8;
    unsigned aoff = ((wM + rowA) * HSTRW + (lane >> 4) * 4) * 4;
    unsigned boff = ((wN + (lane >> 4) * 8 + (lane & 7)) * HSTRW + ((lane >> 3) & 1) * 4) * 4;

    float acc[4][4][4];
#pragma unroll
    for (int mi = 0; mi < 4; mi++)
#pragma unroll
        for (int nj = 0; nj < 4; nj++)
#pragma unroll
            for (int r = 0; r < 4; r++) acc[mi][nj][r] = 0.f;

    auto load_slab = [&](int s, int kb) {
        unsigned* As = smw + s*(2*HSLABW);
        unsigned* Bs = As + HSLABW;
        cp16(&As[ar*HSTRW + ac/2],     arow + kb + ac,     asz);
        cp16(&As[ar*HSTRW + ac/2 + 4], arow + kb + ac + 8, asz);
        cp16(&Bs[ar*HSTRW + ac/2],     brow + kb + ac,     16);
        cp16(&Bs[ar*HSTRW + ac/2 + 4], brow + kb + ac + 8, 16);
    };

    int ns = K >> 5;
#pragma unroll
    for (int j = 0; j < 3; j++) { load_slab(j, j*32); CP_COMMIT(); }

    for (int i = 0; i < ns; i++) {
        int s = i & (HNSTG-1);
        CP_WAITG2();
        __syncthreads();
        int j = i + 3;
        if (j < ns) load_slab(j & (HNSTG-1), j*32);
        CP_COMMIT();
        unsigned abase = smbase + s*(2*HSLABW)*4 + aoff;
        unsigned bbase = smbase + s*(2*HSLABW)*4 + HSLABW*4 + boff;
#pragma unroll
        for (int ks = 0; ks < 2; ks++) {
            unsigned k0b = ks * 32;       // 8 words = 32 bytes per k-step
            unsigned bf[4][2];
            ldsm4(bf[0][0], bf[0][1], bf[1][0], bf[1][1], bbase + k0b);
            ldsm4(bf[2][0], bf[2][1], bf[3][0], bf[3][1], bbase + 16*HSTRW*4 + k0b);
#pragma unroll
            for (int mi = 0; mi < 4; mi++) {
                unsigned a0, a1, a2, a3;
                ldsm4(a0, a1, a2, a3, abase + mi*16*HSTRW*4 + k0b);
#pragma unroll
                for (int nj = 0; nj < 4; nj++)
                    mma_f16(acc[mi][nj], a0, a1, a2, a3, bf[nj][0], bf[nj][1]);
            }
        }
    }
    float* C = (float*)Cv;
    __half* Ch = (__half*)Cv;
#pragma unroll
    for (int mi = 0; mi < 4; mi++) {
#pragma unroll
        for (int nj = 0; nj < 4; nj++) {
            int r0 = mbase + wM + mi*16 + g;
            int r1 = r0 + 8;
            int c  = nbase + wN + nj*8 + tg*2;
            float v0 = acc[mi][nj][0], v1 = acc[mi][nj][1];
            float v2 = acc[mi][nj][2], v3 = acc[mi][nj][3];
            if (EPI == 4) {
                v0 = fminf(fmaxf(v0,-CLIPV),CLIPV); v1 = fminf(fmaxf(v1,-CLIPV),CLIPV);
                v2 = fminf(fmaxf(v2,-CLIPV),CLIPV); v3 = fminf(fmaxf(v3,-CLIPV),CLIPV);
            }
            if (EPI == 2) {
                float2 r0v = *(const float2*)(resid + (size_t)r0*N + c);
                float2 r1v = *(const float2*)(resid + (size_t)r1*N + c);
                v0 += r0v.x; v1 += r0v.y; v2 += r1v.x; v3 += r1v.y;
            }
            if (EPI == 4 || EPI == 5) {
                *(half2*)(Ch + (size_t)r0*N + c) = __floats2half2_rn(v0, v1);
                *(half2*)(Ch + (size_t)r1*N + c) = __floats2half2_rn(v2, v3);
            } else {
                *(float2*)(C + (size_t)r0*N + c) = make_float2(v0, v1);
                *(float2*)(C + (size_t)r1*N + c) = make_float2(v2, v3);
            }
        }
    }
}

// ---------------- fp16 dual-B up GEMM (ldmatrix frags) ----------------
#define UNSTG 4
#define UP_SMEM (UNSTG*3*HSLABW*4)     // 122880 B
__global__ void __launch_bounds__(256, 1)
up_hgemm(const __half* __restrict__ A, const __half* __restrict__ Bw,
         const __half* __restrict__ Bv, __half* __restrict__ C) {
    const int N = FF, K = DM;
    int mbase = blockIdx.y * 128;
    if (mbase >= g_total) return;
    int e = 0;
#pragma unroll
    for (int i = 0; i < NE; i++) if (g_segoff[i+1] <= mbase) e = i + 1;
    Bw += (size_t)e * FF * DM;
    Bv += (size_t)e * FF * DM;
    int nbase = blockIdx.x * 128;
    extern __shared__ unsigned smw[];
    unsigned smbase = (unsigned)__cvta_generic_to_shared(smw);
    int tid  = threadIdx.x;
    int lane = tid & 31, warp = tid >> 5;
    int wM = (warp & 1) * 64;
    int wN = (warp >> 1) * 32;
    int g  = lane >> 2, tg = lane & 3;

    int ar = tid >> 1, ac = (tid & 1) * 16;
    int tok = g_perm[mbase + ar];
    int asz  = (tok >= 0) ? 16 : 0;
    const __half* arow = A + (size_t)(tok >= 0 ? tok : 0) * K;
    const __half* wrow = Bw + (size_t)(nbase + ar) * K;
    const __half* vrow = Bv + (size_t)(nbase + ar) * K;

    int rowA = (lane & 7) + ((lane >> 3) & 1) * 8;
    unsigned aoff = ((wM + rowA) * HSTRW + (lane >> 4) * 4) * 4;
    unsigned boff = ((wN + (lane >> 4) * 8 + (lane & 7)) * HSTRW + ((lane >> 3) & 1) * 4) * 4;

    float accw[4][4][4], accv[4][4][4];
#pragma unroll
    for (int mi = 0; mi < 4; mi++)
#pragma unroll
        for (int nj = 0; nj < 4; nj++)
#pragma unroll
            for (int r = 0; r < 4; r++) { accw[mi][nj][r] = 0.f; accv[mi][nj][r] = 0.f; }

    auto load_slab = [&](int s, int kb) {
        unsigned* As = smw + s*(3*HSLABW);
        unsigned* Ws = As + HSLABW;
        unsigned* Vs = Ws + HSLABW;
        cp16(&As[ar*HSTRW + ac/2],     arow + kb + ac,     asz);
        cp16(&As[ar*HSTRW + ac/2 + 4], arow + kb + ac + 8, asz);
        cp16(&Ws[ar*HSTRW + ac/2],     wrow + kb + ac,     16);
        cp16(&Ws[ar*HSTRW + ac/2 + 4], wrow + kb + ac + 8, 16);
        cp16(&Vs[ar*HSTRW + ac/2],     vrow + kb + ac,     16);
        cp16(&Vs[ar*HSTRW + ac/2 + 4], vrow + kb + ac + 8, 16);
    };

    const int ns = K >> 5;
#pragma unroll
    for (int j = 0; j < 3; j++) { load_slab(j, j*32); CP_COMMIT(); }

    for (int i = 0; i < ns; i++) {
        int s = i & (UNSTG-1);
        CP_WAITG2();
        __syncthreads();
        int j = i + 3;
        if (j < ns) load_slab(j & (UNSTG-1), j*32);
        CP_COMMIT();
        unsigned abase = smbase + s*(3*HSLABW)*4 + aoff;
        unsigned wbase = smbase + s*(3*HSLABW)*4 + HSLABW*4 + boff;
        unsigned vbase = wbase + HSLABW*4;
#pragma unroll
        for (int ks = 0; ks < 2; ks++) {
            unsigned k0b = ks * 32;
            unsigned bw[4][2], bv[4][2];
            ldsm4(bw[0][0], bw[0][1], bw[1][0], bw[1][1], wbase + k0b);
            ldsm4(bw[2][0], bw[2][1], bw[3][0], bw[3][1], wbase + 16*HSTRW*4 + k0b);
            ldsm4(bv[0][0], bv[0][1], bv[1][0], bv[1][1], vbase + k0b);
            ldsm4(bv[2][0], bv[2][1], bv[3][0], bv[3][1], vbase + 16*HSTRW*4 + k0b);
#pragma unroll
            for (int mi = 0; mi < 4; mi++) {
                unsigned a0, a1, a2, a3;
                ldsm4(a0, a1, a2, a3, abase + mi*16*HSTRW*4 + k0b);
#pragma unroll
                for (int nj = 0; nj < 4; nj++) {
                    mma_f16(accw[mi][nj], a0, a1, a2, a3, bw[nj][0], bw[nj][1]);
                    mma_f16(accv[mi][nj], a0, a1, a2, a3, bv[nj][0], bv[nj][1]);
                }
            }
        }
    }
#pragma unroll
    for (int mi = 0; mi < 4; mi++) {
#pragma unroll
        for (int nj = 0; nj < 4; nj++) {
            int r0 = mbase + wM + mi*16 + g;
            int r1 = r0 + 8;
            int c  = nbase + wN + nj*8 + tg*2;
            float w0 = accw[mi][nj][0], w1 = accw[mi][nj][1];
            float w2 = accw[mi][nj][2], w3 = accw[mi][nj][3];
            float v0 = accv[mi][nj][0] * (w0 / (1.f + __expf(-w0)));
            float v1 = accv[mi][nj][1] * (w1 / (1.f + __expf(-w1)));
            float v2 = accv[mi][nj][2] * (w2 / (1.f + __expf(-w2)));
            float v3 = accv[mi][nj][3] * (w3 / (1.f + __expf(-w3)));
            *(half2*)(C + (size_t)r0*N + c) = __floats2half2_rn(v0, v1);
            *(half2*)(C + (size_t)r1*N + c) = __floats2half2_rn(v2, v3);
        }
    }
}

// ---------------- RoPE (fp16 in-place) + V transpose, one launch ----------------
#define NRBLK ((NT*20*32)/256)      // 10240 rope blocks
#define NVBLK (32*2*BB*NKV)         // 512 vt blocks
__global__ void ropevt_kernel() {
    int bid = blockIdx.x;
    int tid = threadIdx.x;
    if (bid < NRBLK) {
        int idx = bid*256 + tid;
        int i    = idx & 31;
        int head = (idx >> 5) % 20;
        int n    = idx / (32*20);
        int s    = n & (SS - 1);
        float ang = (float)s * g_invfreq[i];
        float sn, cs;
        sincosf(ang, &sn, &cs);
        __half* base = g_qkvh + (size_t)n*QKVN + (head < NH ? head*HDIM : DM + (head-NH)*HDIM);
        float x1 = __half2float(base[i]), x2 = __half2float(base[i+32]);
        float y1 = x1*cs - x2*sn;
        float y2 = x1*sn + x2*cs;
        if (head < NH) { y1 *= SCALEQ; y2 *= SCALEQ; }
        base[i]    = __float2half_rn(y1);
        base[i+32] = __float2half_rn(y2);
    } else {
        __shared__ float t[32][65];
        int vb = bid - NRBLK;
        int s0 = (vb & 31) * 64;
        int d0 = ((vb >> 5) & 1) * 32;
        int bk = vb >> 6;
        int tx = tid & 31, ty = tid >> 5;
        const __half* src = g_qkvh + (size_t)((bk>>2)*SS)*QKVN + DM + NKV*HDIM + (bk&3)*HDIM;
#pragma unroll
        for (int k = 0; k < 64; k += 8)
            t[tx][ty+k] = __half2float(src[(size_t)(s0+ty+k)*QKVN + d0+tx]);
        __syncthreads();
        __half* dst = g_vth + ((size_t)bk*HDIM)*SS;
#pragma unroll
        for (int k = 0; k < 32; k += 8) {
            int row = ty + k;
            half2 hv = __floats2half2_rn(t[row][2*tx], t[row][2*tx+1]);
            *(half2*)(dst + (size_t)(d0+row)*SS + s0 + 2*tx) = hv;
        }
    }
}

// ---------------- fp16 flash attention: QK | PV(prev) | softmax pipeline ----------------
#define FQ 128
#define FKT 64
#define FSTW 36
#define FLASH_SMEM ((FQ + 2*FKT + 3*FKT + FQ)*FSTW*4)   // 82944 B
__global__ void __launch_bounds__(256)
flash_h_kernel(const __half* __restrict__ qkvh, const __half* __restrict__ vth,
               __half* __restrict__ out) {
    extern __shared__ unsigned smw[];
    unsigned* Qs = smw;
    unsigned* Kst = Qs + FQ*FSTW;
    unsigned* Vst = Kst + 2*FKT*FSTW;
    unsigned* Ps = Vst + 3*FKT*FSTW;
    int qb = gridDim.x - 1 - blockIdx.x;
    int bh = blockIdx.y;
    int b = bh >> 4, h = bh & 15, kh = h >> 2;
    int tid = threadIdx.x, lane = tid & 31, warp = tid >> 5;
    int g = lane >> 2, tg = lane & 3;

    {
        const __half* qp = qkvh + (size_t)(b*SS + qb*FQ)*QKVN + h*HDIM;
        int r = tid >> 1;
        int c0 = (tid & 1) * 4;
#pragma unroll
        for (int q = 0; q < 4; q++)
            cp16(&Qs[r*FSTW + (c0+q)*4], qp + (size_t)r*QKVN + (c0+q)*8, 16);
    }
    int kvr = tid >> 2, kvc = (tid & 3) * 2;
    const __half* kbase = qkvh + (size_t)(b*SS)*QKVN + DM + kh*HDIM;
    const __half* vtb = vth + ((size_t)(b*NKV + kh)*HDIM)*SS;
    auto load_kv = [&](int kst, int vst, int kt) {
        const __half* kp = kbase + (size_t)(kt*FKT + kvr)*QKVN;
        const __half* vp = vtb + (size_t)kvr*SS + kt*FKT;
        unsigned* kd = Kst + kst*FKT*FSTW + kvr*FSTW;
        unsigned* vd = Vst + vst*FKT*FSTW + kvr*FSTW;
#pragma unroll
        for (int q = 0; q < 2; q++) {
            cp16(kd + (kvc+q)*4, kp + (kvc+q)*8, 16);
            cp16(vd + (kvc+q)*4, vp + (kvc+q)*8, 16);
        }
    };

    int wrow = warp*16;
    int grow = qb*FQ + wrow;

    float m0 = -1e30f, m1 = -1e30f, l0 = 0.f, l1 = 0.f;
    float o[8][4];
#pragma unroll
    for (int nj = 0; nj < 8; nj++)
#pragma unroll
        for (int r = 0; r < 4; r++) o[nj][r] = 0.f;

    int ktmax = 2*qb + 1;
    load_kv(0, 0, 0);
    CP_COMMIT();

    bool pend = false;
    int pkt = 0;

    for (int kt = 0; kt <= ktmax; kt++) {
        __syncthreads();
        if (kt < ktmax) load_kv((kt+1)&1, (kt+1)%3, kt+1);
        CP_COMMIT();
        CP_WAITG1();
        __syncthreads();

        bool act = (kt*FKT <= grow + 15);
        float s[8][4];
        if (act) {
            const unsigned* Ks = Kst + (kt&1)*FKT*FSTW;
#pragma unroll
            for (int nj = 0; nj < 8; nj++)
#pragma unroll
                for (int r = 0; r < 4; r++) s[nj][r] = 0.f;
#pragma unroll
            for (int k0w = 0; k0w < 32; k0w += 8) {
                unsigned a0 = Qs[(wrow+g  )*FSTW + k0w+tg];
                unsigned a1 = Qs[(wrow+g+8)*FSTW + k0w+tg];
                unsigned a2 = Qs[(wrow+g  )*FSTW + k0w+4+tg];
                unsigned a3 = Qs[(wrow+g+8)*FSTW + k0w+4+tg];
#pragma unroll
                for (int nj = 0; nj < 8; nj++) {
                    unsigned b0 = Ks[(nj*8+g)*FSTW + k0w+tg];
                    unsigned b1 = Ks[(nj*8+g)*FSTW + k0w+4+tg];
                    mma_f16(s[nj], a0, a1, a2, a3, b0, b1);
                }
            }
        }

        if (pend) {
            const unsigned* Vs = Vst + (pkt%3)*FKT*FSTW;
#pragma unroll
            for (int k0w = 0; k0w < 32; k0w += 8) {
                unsigned a0 = Ps[(wrow+g  )*FSTW + k0w+tg];
                unsigned a1 = Ps[(wrow+g+8)*FSTW + k0w+tg];
                unsigned a2 = Ps[(wrow+g  )*FSTW + k0w+4+tg];
                unsigned a3 = Ps[(wrow+g+8)*FSTW + k0w+4+tg];
#pragma unroll
                for (int nj = 0; nj < 8; nj++) {
                    unsigned b0 = Vs[(nj*8+g)*FSTW + k0w+tg];
                    unsigned b1 = Vs[(nj*8+g)*FSTW + k0w+4+tg];
                    mma_f16(o[nj], a0, a1, a2, a3, b0, b1);
                }
            }
            pend = false;
        }

        if (act) {
            if (kt >= 2*qb) {
                int r0 = grow + g, r1 = grow + g + 8;
#pragma unroll
                for (int nj = 0; nj < 8; nj++) {
                    int c = kt*FKT + nj*8 + 2*tg;
                    if (c     > r0) s[nj][0] = -1e30f;
                    if (c + 1 > r0) s[nj][1] = -1e30f;
                    if (c     > r1) s[nj][2] = -1e30f;
                    if (c + 1 > r1) s[nj][3] = -1e30f;
                }
            }
            float mt0 = -1e30f, mt1 = -1e30f;
#pragma unroll
            for (int nj = 0; nj < 8; nj++) {
                mt0 = fmaxf(mt0, fmaxf(s[nj][0], s[nj][1]));
                mt1 = fmaxf(mt1, fmaxf(s[nj][2], s[nj][3]));
            }
            mt0 = fmaxf(mt0, __shfl_xor_sync(0xffffffffu, mt0, 1));
            mt0 = fmaxf(mt0, __shfl_xor_sync(0xffffffffu, mt0, 2));
            mt1 = fmaxf(mt1, __shfl_xor_sync(0xffffffffu, mt1, 1));
            mt1 = fmaxf(mt1, __shfl_xor_sync(0xffffffffu, mt1, 2));
            float mn0 = fmaxf(m0, mt0), mn1 = fmaxf(m1, mt1);
            float c0 = __expf(m0 - mn0), c1 = __expf(m1 - mn1);
            l0 *= c0; l1 *= c1;
#pragma unroll
            for (int nj = 0; nj < 8; nj++) {
                o[nj][0] *= c0; o[nj][1] *= c0;
                o[nj][2] *= c1; o[nj][3] *= c1;
            }
            float rs0 = 0.f, rs1 = 0.f;
#pragma unroll
            for (int nj = 0; nj < 8; nj++) {
                float p0 = __expf(s[nj][0] - mn0);
                float p1 = __expf(s[nj][1] - mn0);
                float p2 = __expf(s[nj][2] - mn1);
                float p3 = __expf(s[nj][3] - mn1);
                rs0 += p0 + p1; rs1 += p2 + p3;
                int w = nj*4 + tg;
                ((half2*)Ps)[ ((wrow+g  )*FSTW + w) ] = __floats2half2_rn(p0, p1);
                ((half2*)Ps)[ ((wrow+g+8)*FSTW + w) ] = __floats2half2_rn(p2, p3);
            }
            rs0 += __shfl_xor_sync(0xffffffffu, rs0, 1);
            rs0 += __shfl_xor_sync(0xffffffffu, rs0, 2);
            rs1 += __shfl_xor_sync(0xffffffffu, rs1, 1);
            rs1 += __shfl_xor_sync(0xffffffffu, rs1, 2);
            l0 += rs0; l1 += rs1;
            m0 = mn0; m1 = mn1;
            __syncwarp();
            pend = true;
            pkt  = kt;
        }
    }

    if (pend) {
        const unsigned* Vs = Vst + (pkt%3)*FKT*FSTW;
#pragma unroll
        for (int k0w = 0; k0w < 32; k0w += 8) {
            unsigned a0 = Ps[(wrow+g  )*FSTW + k0w+tg];
            unsigned a1 = Ps[(wrow+g+8)*FSTW + k0w+tg];
            unsigned a2 = Ps[(wrow+g  )*FSTW + k0w+4+tg];
            unsigned a3 = Ps[(wrow+g+8)*FSTW + k0w+4+tg];
#pragma unroll
            for (int nj = 0; nj < 8; nj++) {
                unsigned b0 = Vs[(nj*8+g)*FSTW + k0w+tg];
                unsigned b1 = Vs[(nj*8+g)*FSTW + k0w+4+tg];
                mma_f16(o[nj], a0, a1, a2, a3, b0, b1);
            }
        }
    }

    float il0 = 1.f/l0, il1 = 1.f/l1;
    size_t tok0 = (size_t)(b*SS + qb*FQ + wrow + g);
    size_t tok1 = tok0 + 8;
#pragma unroll
    for (int nj = 0; nj < 8; nj++) {
        int col = h*HDIM + nj*8 + 2*tg;
        *(half2*)(out + tok0*DM + col) = __floats2half2_rn(o[nj][0]*il0, o[nj][1]*il0);
        *(half2*)(out + tok1*DM + col) = __floats2half2_rn(o[nj][2]*il1, o[nj][3]*il1);
    }
}

// ---------------- router ----------------
__global__ void router_kernel(const float* __restrict__ x2, const float* __restrict__ rw) {
    int t = (blockIdx.x*blockDim.x + threadIdx.x) >> 5;
    int lane = threadIdx.x & 31;
    if (t >= NT) return;
    const float* xr = x2 + (size_t)t*DM;
    float acc[NE];
#pragma unroll
    for (int e = 0; e < NE; e++) acc[e] = 0.f;
    for (int d = lane; d < DM; d += 32) {
        float xv = xr[d];
        float4 r0 = ((const float4*)rw)[d*2];
        float4 r1 = ((const float4*)rw)[d*2+1];
        acc[0]+=xv*r0.x; acc[1]+=xv*r0.y; acc[2]+=xv*r0.z; acc[3]+=xv*r0.w;
        acc[4]+=xv*r1.x; acc[5]+=xv*r1.y; acc[6]+=xv*r1.z; acc[7]+=xv*r1.w;
    }
#pragma unroll
    for (int o = 16; o; o >>= 1)
#pragma unroll
        for (int e = 0; e < NE; e++)
            acc[e] += __shfl_xor_sync(0xffffffffu, acc[e], o);
    if (lane == 0) {
        int e0 = 0; float m0 = acc[0];
#pragma unroll
        for (int e = 1; e < NE; e++) if (acc[e] > m0) { m0 = acc[e]; e0 = e; }
        int e1 = -1; float m1 = -3.4e38f;
#pragma unroll
        for (int e = 0; e < NE; e++) if (e != e0 && acc[e] > m1) { m1 = acc[e]; e1 = e; }
        float p1 = expf(m1 - m0);
        float w0 = 1.f / (1.f + p1);
        float w1 = p1 / (1.f + p1);
        g_top_e[2*t] = e0; g_top_e[2*t+1] = e1;
        g_top_w[2*t] = w0; g_top_w[2*t+1] = w1;
        atomicAdd(&g_cnt[e0], 1);
        atomicAdd(&g_cnt[e1], 1);
    }
}

// fill + local segoff
__global__ void fill_kernel() {
    int i = blockIdx.x*blockDim.x + threadIdx.x;
    if (i >= NT*2) return;
    int seg[NE+1];
    int off = 0;
#pragma unroll
    for (int e = 0; e < NE; e++) {
        seg[e] = off;
        off += ((g_cnt[e] + 127) >> 7) << 7;
    }
    seg[NE] = off;
    if (i == 0) {
#pragma unroll
        for (int e = 0; e <= NE; e++) g_segoff[e] = seg[e];
        g_total = off;
    }
    int e = g_top_e[i];
    int pos = seg[e] + atomicAdd(&g_fill[e], 1);
    g_perm[pos] = i >> 1;
    g_tok_slot[i] = pos;
}

__global__ void combine_kernel(float* __restrict__ out) {
    int i = blockIdx.x*blockDim.x + threadIdx.x;
    int n = i >> 8, d4 = i & 255;
    int s0 = g_tok_slot[2*n], s1 = g_tok_slot[2*n+1];
    float w0 = g_top_w[2*n], w1 = g_top_w[2*n+1];
    float4 hv = *(float4*)&g_hidden[(size_t)n*DM + d4*4];
    const half2* y0p = (const half2*)&g_yh[(size_t)s0*DM + d4*4];
    const half2* y1p = (const half2*)&g_yh[(size_t)s1*DM + d4*4];
    float2 ya0 = __half22float2(y0p[0]), yb0 = __half22float2(y0p[1]);
    float2 ya1 = __half22float2(y1p[0]), yb1 = __half22float2(y1p[1]);
    float4 r;
    r.x = hv.x + w0*ya0.x + w1*ya1.x;
    r.y = hv.y + w0*ya0.y + w1*ya1.y;
    r.z = hv.z + w0*yb0.x + w1*yb1.x;
    r.w = hv.w + w0*yb0.y + w1*yb1.y;
    *(float4*)&out[(size_t)n*DM + d4*4] = r;
}

// ---------------- launch (single stream) ----------------
extern "C" void kernel_launch(void* const* d_in, const int* in_sizes, int n_in,
                              void* d_out, int out_size) {
    const float* hs   = (const float*)d_in[0];
    const float* ln1w = (const float*)d_in[1];
    const float* ln2w = (const float*)d_in[2];
    const float* wqkv = (const float*)d_in[3];
    const float* outw = (const float*)d_in[4];
    const float* rw   = (const float*)d_in[5];
    const float* w1   = (const float*)d_in[6];
    const float* v1   = (const float*)d_in[7];
    const float* w2   = (const float*)d_in[8];
    float* out = (float*)d_out;

    float *phid, *px2;
    __half *px1h, *px2h, *pattnh, *ph1h, *pyh, *pqkvh, *pvth;
    __half *pwqkvh, *poutwh, *pw1h, *pv1h, *pw2h;
    cudaGetSymbolAddress((void**)&phid,  g_hidden);
    cudaGetSymbolAddress((void**)&px2,   g_x2);
    cudaGetSymbolAddress((void**)&px1h,  g_x1h);
    cudaGetSymbolAddress((void**)&px2h,  g_x2h);
    cudaGetSymbolAddress((void**)&pattnh,g_attnh);
    cudaGetSymbolAddress((void**)&ph1h,  g_h1h);
    cudaGetSymbolAddress((void**)&pyh,   g_yh);
    cudaGetSymbolAddress((void**)&pqkvh, g_qkvh);
    cudaGetSymbolAddress((void**)&pvth,  g_vth);
    cudaGetSymbolAddress((void**)&pwqkvh,g_wqkvh);
    cudaGetSymbolAddress((void**)&poutwh,g_outwh);
    cudaGetSymbolAddress((void**)&pw1h,  g_w1h);
    cudaGetSymbolAddress((void**)&pv1h,  g_v1h);
    cudaGetSymbolAddress((void**)&pw2h,  g_w2h);

    cudaFuncSetAttribute(flash_h_kernel,
                         cudaFuncAttributeMaxDynamicSharedMemorySize, FLASH_SMEM);
    cudaFuncSetAttribute(hgemm<4,false,false>,
                         cudaFuncAttributeMaxDynamicSharedMemorySize, HGEMM_SMEM);
    cudaFuncSetAttribute(hgemm<2,false,false>,
                         cudaFuncAttributeMaxDynamicSharedMemorySize, HGEMM_SMEM);
    cudaFuncSetAttribute(hgemm<5,false,true>,
                         cudaFuncAttributeMaxDynamicSharedMemorySize, HGEMM_SMEM);
    cudaFuncSetAttribute(up_hgemm,
                         cudaFuncAttributeMaxDynamicSharedMemorySize, UP_SMEM);

    // ---- weight conversions + one-time init ----
    conv2_h<<<(2*NE*FF*DM/4 + 255)/256, 256>>>(w1, pw1h, v1, pv1h, NE*FF*DM/4);
    convT_h<<<dim3(DM/64, QKVN/32, 1), dim3(32,8)>>>(wqkv, pwqkvh, DM, QKVN);
    convT_h<<<dim3(DM/64, DM/32, 1), dim3(32,8)>>>(outw, poutwh, DM, DM);
    convT_h<<<dim3(FF/64, DM/32, NE), dim3(32,8)>>>(w2, pw2h, FF, DM);

    // LN1 -> QKV(clip, fp16) -> RoPE+V^T -> attention -> out-proj(+resid)
    ln_kernel<false,true><<<NT, 256>>>(hs, ln1w, nullptr, px1h);
    hgemm<4,false,false><<<dim3(QKVN/128, NT/128), 256, HGEMM_SMEM>>>(
        px1h, pwqkvh, pqkvh, nullptr, QKVN, DM, 0);
    ropevt_kernel<<<NRBLK + NVBLK, 256>>>();
    flash_h_kernel<<<dim3(SS/FQ, BB*NH), 256, FLASH_SMEM>>>(pqkvh, pvth, pattnh);
    hgemm<2,false,false><<<dim3(DM/128, NT/128), 256, HGEMM_SMEM>>>(
        pattnh, poutwh, phid, hs, DM, DM, 0);

    // LN2 -> router -> fill(+segoff)
    ln_kernel<true,true><<<NT, 256>>>(phid, ln2w, px2, px2h);
    router_kernel<<<NT/8, 256>>>(px2, rw);
    fill_kernel<<<(NT*2 + 255)/256, 256>>>();

    // MoE: fused dual-B up (silu epilogue, fp16 out), then down (fp16 y)
    up_hgemm<<<dim3(FF/128, CAP/128), 256, UP_SMEM>>>(px2h, pw1h, pv1h, ph1h);
    hgemm<5,false,true><<<dim3(DM/128, CAP/128), 256, HGEMM_SMEM>>>(
        ph1h, pw2h, pyh, nullptr, DM, FF, (long)DM*FF);

    // resid2 + gated expert outputs
    combine_kernel<<<NT, 256>>>(out);
}

// round 17
// speedup vs baseline: 1.7033x; 1.0221x over previous
#include <cuda_runtime.h>
#include <cuda_fp16.h>
#include <math.h>

// ---------------- problem constants ----------------
#define BB 2
#define SS 2048
#define DM 1024
#define NH 16
#define NKV 4
#define HDIM 64
#define NE 8
#define FF 2048
#define NT (BB*SS)                    // 4096 tokens
#define QKVN (DM + 2*NKV*HDIM)        // 1536
#define CAP (2*NT + NE*128)           // 9216 padded MoE slots
#define SCALEQ 0.125f
#define CLIPV 8.0f

// ---------------- device scratch ----------------
__device__ float g_hidden[NT*DM];
__device__ float g_x2[NT*DM];
__device__ int   g_top_e[NT*2];
__device__ float g_top_w[NT*2];
__device__ int   g_cnt[NE];
__device__ int   g_fill[NE];
__device__ int   g_segoff[NE+1];
__device__ int   g_total;
__device__ int   g_perm[CAP];
__device__ int   g_tok_slot[NT*2];
__device__ float g_invfreq[32];
// fp16 buffers
__device__ __half g_x1h[NT*DM];
__device__ __half g_x2h[NT*DM];
__device__ __half g_attnh[NT*DM];
__device__ __half g_h1h[CAP*FF];
__device__ __half g_yh[CAP*DM];
__device__ __half g_qkvh[NT*QKVN];
__device__ __half g_vth[BB*NKV*HDIM*SS];
__device__ __half g_wqkvh[QKVN*DM];
__device__ __half g_outwh[DM*DM];
__device__ __half g_w1h[NE*FF*DM];
__device__ __half g_v1h[NE*FF*DM];
__device__ __half g_w2h[NE*DM*FF];

// ---------------- weight conversion + one-time init ----------------
__global__ void conv2_h(const float* __restrict__ in1, __half* __restrict__ out1,
                        const float* __restrict__ in2, __half* __restrict__ out2,
                        int n4) {
    int gi = blockIdx.x*blockDim.x + threadIdx.x;
    if (gi < 32) g_invfreq[gi] = (float)pow(10000.0, -(double)gi / 32.0);
    if (gi < NE) { g_cnt[gi] = 0; g_fill[gi] = 0; }
    if (gi < CAP) g_perm[gi] = -1;
    int i = gi;
    const float* in; __half* out;
    if (i >= n4) { i -= n4; in = in2; out = out2; } else { in = in1; out = out1; }
    if (i >= n4) return;
    float4 v = ((const float4*)in)[i];
    ((half2*)out)[i*2]   = __floats2half2_rn(v.x, v.y);
    ((half2*)out)[i*2+1] = __floats2half2_rn(v.z, v.w);
}
__global__ void convT_h(const float* __restrict__ in, __half* __restrict__ out,
                        int R, int C) {
    __shared__ float t[32][65];
    int e = blockIdx.z;
    in  += (size_t)e*R*C;
    out += (size_t)e*R*C;
    int r0 = blockIdx.x*64, c0 = blockIdx.y*32;
    int tx = threadIdx.x, ty = threadIdx.y;
#pragma unroll
    for (int k = 0; k < 64; k += 8)
        t[tx][ty+k] = in[(size_t)(r0+ty+k)*C + c0+tx];
    __syncthreads();
#pragma unroll
    for (int k = 0; k < 32; k += 8) {
        int row = ty + k;
        half2 hv = __floats2half2_rn(t[row][2*tx], t[row][2*tx+1]);
        *(half2*)(out + (size_t)(c0+row)*R + r0 + 2*tx) = hv;
    }
}

// ---------------- layernorm ----------------
template<bool OUTF, bool OUTH>
__global__ void ln_kernel(const float* __restrict__ x, const float* __restrict__ w,
                          float* __restrict__ outf, __half* __restrict__ outh) {
    int row = blockIdx.x, tid = threadIdx.x;
    float4 v = ((const float4*)(x + (size_t)row*DM))[tid];
    float s = v.x+v.y+v.z+v.w;
    float q = v.x*v.x+v.y*v.y+v.z*v.z+v.w*v.w;
#pragma unroll
    for (int o = 16; o; o >>= 1) {
        s += __shfl_xor_sync(0xffffffffu, s, o);
        q += __shfl_xor_sync(0xffffffffu, q, o);
    }
    __shared__ float ssm[8], qsm[8];
    if ((tid & 31) == 0) { ssm[tid>>5] = s; qsm[tid>>5] = q; }
    __syncthreads();
    float ts = 0.f, tq = 0.f;
#pragma unroll
    for (int i = 0; i < 8; i++) { ts += ssm[i]; tq += qsm[i]; }
    float mu  = ts * (1.f/DM);
    float var = tq * (1.f/DM) - mu*mu;
    float rs  = rsqrtf(var + 1e-5f);
    float4 wv = ((const float4*)w)[tid];
    float4 r;
    r.x = (v.x-mu)*rs*wv.x; r.y = (v.y-mu)*rs*wv.y;
    r.z = (v.z-mu)*rs*wv.z; r.w = (v.w-mu)*rs*wv.w;
    if (OUTF) ((float4*)(outf + (size_t)row*DM))[tid] = r;
    if (OUTH) {
        ((half2*)(outh + (size_t)row*DM))[tid*2]   = __floats2half2_rn(r.x, r.y);
        ((half2*)(outh + (size_t)row*DM))[tid*2+1] = __floats2half2_rn(r.z, r.w);
    }
}

// ---------------- mma / cp.async / ldmatrix helpers ----------------
__device__ __forceinline__ void mma_f16(float* c,
        unsigned a0, unsigned a1, unsigned a2, unsigned a3,
        unsigned b0, unsigned b1) {
    asm volatile("mma.sync.aligned.m16n8k16.row.col.f32.f16.f16.f32 "
        "{%0,%1,%2,%3}, {%4,%5,%6,%7}, {%8,%9}, {%0,%1,%2,%3};"
        : "+f"(c[0]), "+f"(c[1]), "+f"(c[2]), "+f"(c[3])
        : "r"(a0), "r"(a1), "r"(a2), "r"(a3), "r"(b0), "r"(b1));
}
__device__ __forceinline__ void cp16(void* smem_dst, const void* gsrc, int src_bytes) {
    unsigned sa = (unsigned)__cvta_generic_to_shared(smem_dst);
    asm volatile("cp.async.cg.shared.global [%0], [%1], 16, %2;\n"
                 :: "r"(sa), "l"(gsrc), "r"(src_bytes));
}
__device__ __forceinline__ void ldsm4(unsigned& r0, unsigned& r1,
                                      unsigned& r2, unsigned& r3, unsigned addr) {
    asm volatile("ldmatrix.sync.aligned.m8n8.x4.shared.b16 {%0,%1,%2,%3}, [%4];"
        : "=r"(r0), "=r"(r1), "=r"(r2), "=r"(r3) : "r"(addr));
}
#define CP_COMMIT() asm volatile("cp.async.commit_group;\n")
#define CP_WAITG2() asm volatile("cp.async.wait_group 2;\n")
#define CP_WAITG1() asm volatile("cp.async.wait_group 1;\n")

// ---------------- fp16 GEMM: 128x128 tile, K=32 halfs/slab, ldmatrix frags -------
// EPI: 0 none(f32), 2 +resid(f32), 4 clip(fp16 out), 5 fp16 out
#define HSTRW 20
#define HSLABW (128*HSTRW)
#define HNSTG 4
#define HGEMM_SMEM (HNSTG*2*HSLABW*4)   // 81920 B
template<int EPI, bool GATHER, bool EXPERT>
__global__ void __launch_bounds__(256, 2)
hgemm(const __half* __restrict__ A, const __half* __restrict__ Bm,
      void* __restrict__ Cv, const float* __restrict__ resid,
      int N, int K, long ldbE) {
    int mbase = blockIdx.y * 128;
    if (EXPERT) {
        if (mbase >= g_total) return;
        int e = 0;
#pragma unroll
        for (int i = 0; i < NE; i++) if (g_segoff[i+1] <= mbase) e = i + 1;
        Bm += (size_t)e * ldbE;
    }
    int nbase = blockIdx.x * 128;
    extern __shared__ unsigned smw[];
    unsigned smbase = (unsigned)__cvta_generic_to_shared(smw);
    int tid  = threadIdx.x;
    int lane = tid & 31, warp = tid >> 5;
    int wM = (warp & 1) * 64;
    int wN = (warp >> 1) * 32;
    int g  = lane >> 2, tg = lane & 3;

    int ar = tid >> 1, ac = (tid & 1) * 16;
    const __half* arow;
    int asz = 16;
    if (GATHER) {
        int tok = g_perm[mbase + ar];
        asz  = (tok >= 0) ? 16 : 0;
        arow = A + (size_t)(tok >= 0 ? tok : 0) * K;
    } else {
        arow = A + (size_t)(mbase + ar) * K;
    }
    const __half* brow = Bm + (size_t)(nbase + ar) * K;

    int rowA = (lane & 7) + ((lane >> 3) & 1) * 8;
    unsigned aoff = ((wM + rowA) * HSTRW + (lane >> 4) * 4) * 4;
    unsigned boff = ((wN + (lane >> 4) * 8 + (lane & 7)) * HSTRW + ((lane >> 3) & 1) * 4) * 4;

    float acc[4][4][4];
#pragma unroll
    for (int mi = 0; mi < 4; mi++)
#pragma unroll
        for (int nj = 0; nj < 4; nj++)
#pragma unroll
            for (int r = 0; r < 4; r++) acc[mi][nj][r] = 0.f;

    auto load_slab = [&](int s, int kb) {
        unsigned* As = smw + s*(2*HSLABW);
        unsigned* Bs = As + HSLABW;
        cp16(&As[ar*HSTRW + ac/2],     arow + kb + ac,     asz);
        cp16(&As[ar*HSTRW + ac/2 + 4], arow + kb + ac + 8, asz);
        cp16(&Bs[ar*HSTRW + ac/2],     brow + kb + ac,     16);
        cp16(&Bs[ar*HSTRW + ac/2 + 4], brow + kb + ac + 8, 16);
    };

    int ns = K >> 5;
#pragma unroll
    for (int j = 0; j < 3; j++) { load_slab(j, j*32); CP_COMMIT(); }

    for (int i = 0; i < ns; i++) {
        int s = i & (HNSTG-1);
        CP_WAITG2();
        __syncthreads();
        int j = i + 3;
        if (j < ns) load_slab(j & (HNSTG-1), j*32);
        CP_COMMIT();
        unsigned abase = smbase + s*(2*HSLABW)*4 + aoff;
        unsigned bbase = smbase + s*(2*HSLABW)*4 + HSLABW*4 + boff;
#pragma unroll
        for (int ks = 0; ks < 2; ks++) {
            unsigned k0b = ks * 32;
            unsigned bf[4][2];
            ldsm4(bf[0][0], bf[0][1], bf[1][0], bf[1][1], bbase + k0b);
            ldsm4(bf[2][0], bf[2][1], bf[3][0], bf[3][1], bbase + 16*HSTRW*4 + k0b);
#pragma unroll
            for (int mi = 0; mi < 4; mi++) {
                unsigned a0, a1, a2, a3;
                ldsm4(a0, a1, a2, a3, abase + mi*16*HSTRW*4 + k0b);
#pragma unroll
                for (int nj = 0; nj < 4; nj++)
                    mma_f16(acc[mi][nj], a0, a1, a2, a3, bf[nj][0], bf[nj][1]);
            }
        }
    }
    float* C = (float*)Cv;
    __half* Ch = (__half*)Cv;
#pragma unroll
    for (int mi = 0; mi < 4; mi++) {
#pragma unroll
        for (int nj = 0; nj < 4; nj++) {
            int r0 = mbase + wM + mi*16 + g;
            int r1 = r0 + 8;
            int c  = nbase + wN + nj*8 + tg*2;
            float v0 = acc[mi][nj][0], v1 = acc[mi][nj][1];
            float v2 = acc[mi][nj][2], v3 = acc[mi][nj][3];
            if (EPI == 4) {
                v0 = fminf(fmaxf(v0,-CLIPV),CLIPV); v1 = fminf(fmaxf(v1,-CLIPV),CLIPV);
                v2 = fminf(fmaxf(v2,-CLIPV),CLIPV); v3 = fminf(fmaxf(v3,-CLIPV),CLIPV);
            }
            if (EPI == 2) {
                float2 r0v = *(const float2*)(resid + (size_t)r0*N + c);
                float2 r1v = *(const float2*)(resid + (size_t)r1*N + c);
                v0 += r0v.x; v1 += r0v.y; v2 += r1v.x; v3 += r1v.y;
            }
            if (EPI == 4 || EPI == 5) {
                *(half2*)(Ch + (size_t)r0*N + c) = __floats2half2_rn(v0, v1);
                *(half2*)(Ch + (size_t)r1*N + c) = __floats2half2_rn(v2, v3);
            } else {
                *(float2*)(C + (size_t)r0*N + c) = make_float2(v0, v1);
                *(float2*)(C + (size_t)r1*N + c) = make_float2(v2, v3);
            }
        }
    }
}

// ---------------- fp16 dual-B up GEMM (ldmatrix frags) ----------------
#define UNSTG 4
#define UP_SMEM (UNSTG*3*HSLABW*4)     // 122880 B
__global__ void __launch_bounds__(256, 1)
up_hgemm(const __half* __restrict__ A, const __half* __restrict__ Bw,
         const __half* __restrict__ Bv, __half* __restrict__ C) {
    const int N = FF, K = DM;
    int mbase = blockIdx.y * 128;
    if (mbase >= g_total) return;
    int e = 0;
#pragma unroll
    for (int i = 0; i < NE; i++) if (g_segoff[i+1] <= mbase) e = i + 1;
    Bw += (size_t)e * FF * DM;
    Bv += (size_t)e * FF * DM;
    int nbase = blockIdx.x * 128;
    extern __shared__ unsigned smw[];
    unsigned smbase = (unsigned)__cvta_generic_to_shared(smw);
    int tid  = threadIdx.x;
    int lane = tid & 31, warp = tid >> 5;
    int wM = (warp & 1) * 64;
    int wN = (warp >> 1) * 32;
    int g  = lane >> 2, tg = lane & 3;

    int ar = tid >> 1, ac = (tid & 1) * 16;
    int tok = g_perm[mbase + ar];
    int asz  = (tok >= 0) ? 16 : 0;
    const __half* arow = A + (size_t)(tok >= 0 ? tok : 0) * K;
    const __half* wrow = Bw + (size_t)(nbase + ar) * K;
    const __half* vrow = Bv + (size_t)(nbase + ar) * K;

    int rowA = (lane & 7) + ((lane >> 3) & 1) * 8;
    unsigned aoff = ((wM + rowA) * HSTRW + (lane >> 4) * 4) * 4;
    unsigned boff = ((wN + (lane >> 4) * 8 + (lane & 7)) * HSTRW + ((lane >> 3) & 1) * 4) * 4;

    float accw[4][4][4], accv[4][4][4];
#pragma unroll
    for (int mi = 0; mi < 4; mi++)
#pragma unroll
        for (int nj = 0; nj < 4; nj++)
#pragma unroll
            for (int r = 0; r < 4; r++) { accw[mi][nj][r] = 0.f; accv[mi][nj][r] = 0.f; }

    auto load_slab = [&](int s, int kb) {
        unsigned* As = smw + s*(3*HSLABW);
        unsigned* Ws = As + HSLABW;
        unsigned* Vs = Ws + HSLABW;
        cp16(&As[ar*HSTRW + ac/2],     arow + kb + ac,     asz);
        cp16(&As[ar*HSTRW + ac/2 + 4], arow + kb + ac + 8, asz);
        cp16(&Ws[ar*HSTRW + ac/2],     wrow + kb + ac,     16);
        cp16(&Ws[ar*HSTRW + ac/2 + 4], wrow + kb + ac + 8, 16);
        cp16(&Vs[ar*HSTRW + ac/2],     vrow + kb + ac,     16);
        cp16(&Vs[ar*HSTRW + ac/2 + 4], vrow + kb + ac + 8, 16);
    };

    const int ns = K >> 5;
#pragma unroll
    for (int j = 0; j < 3; j++) { load_slab(j, j*32); CP_COMMIT(); }

    for (int i = 0; i < ns; i++) {
        int s = i & (UNSTG-1);
        CP_WAITG2();
        __syncthreads();
        int j = i + 3;
        if (j < ns) load_slab(j & (UNSTG-1), j*32);
        CP_COMMIT();
        unsigned abase = smbase + s*(3*HSLABW)*4 + aoff;
        unsigned wbase = smbase + s*(3*HSLABW)*4 + HSLABW*4 + boff;
        unsigned vbase = wbase + HSLABW*4;
#pragma unroll
        for (int ks = 0; ks < 2; ks++) {
            unsigned k0b = ks * 32;
            unsigned bw[4][2], bv[4][2];
            ldsm4(bw[0][0], bw[0][1], bw[1][0], bw[1][1], wbase + k0b);
            ldsm4(bw[2][0], bw[2][1], bw[3][0], bw[3][1], wbase + 16*HSTRW*4 + k0b);
            ldsm4(bv[0][0], bv[0][1], bv[1][0], bv[1][1], vbase + k0b);
            ldsm4(bv[2][0], bv[2][1], bv[3][0], bv[3][1], vbase + 16*HSTRW*4 + k0b);
#pragma unroll
            for (int mi = 0; mi < 4; mi++) {
                unsigned a0, a1, a2, a3;
                ldsm4(a0, a1, a2, a3, abase + mi*16*HSTRW*4 + k0b);
#pragma unroll
                for (int nj = 0; nj < 4; nj++) {
                    mma_f16(accw[mi][nj], a0, a1, a2, a3, bw[nj][0], bw[nj][1]);
                    mma_f16(accv[mi][nj], a0, a1, a2, a3, bv[nj][0], bv[nj][1]);
                }
            }
        }
    }
#pragma unroll
    for (int mi = 0; mi < 4; mi++) {
#pragma unroll
        for (int nj = 0; nj < 4; nj++) {
            int r0 = mbase + wM + mi*16 + g;
            int r1 = r0 + 8;
            int c  = nbase + wN + nj*8 + tg*2;
            float w0 = accw[mi][nj][0], w1 = accw[mi][nj][1];
            float w2 = accw[mi][nj][2], w3 = accw[mi][nj][3];
            float v0 = accv[mi][nj][0] * (w0 / (1.f + __expf(-w0)));
            float v1 = accv[mi][nj][1] * (w1 / (1.f + __expf(-w1)));
            float v2 = accv[mi][nj][2] * (w2 / (1.f + __expf(-w2)));
            float v3 = accv[mi][nj][3] * (w3 / (1.f + __expf(-w3)));
            *(half2*)(C + (size_t)r0*N + c) = __floats2half2_rn(v0, v1);
            *(half2*)(C + (size_t)r1*N + c) = __floats2half2_rn(v2, v3);
        }
    }
}

// ---------------- RoPE (fp16 in-place) + V transpose, one launch ----------------
#define NRBLK ((NT*20*32)/256)
#define NVBLK (32*2*BB*NKV)
__global__ void ropevt_kernel() {
    int bid = blockIdx.x;
    int tid = threadIdx.x;
    if (bid < NRBLK) {
        int idx = bid*256 + tid;
        int i    = idx & 31;
        int head = (idx >> 5) % 20;
        int n    = idx / (32*20);
        int s    = n & (SS - 1);
        float ang = (float)s * g_invfreq[i];
        float sn, cs;
        sincosf(ang, &sn, &cs);
        __half* base = g_qkvh + (size_t)n*QKVN + (head < NH ? head*HDIM : DM + (head-NH)*HDIM);
        float x1 = __half2float(base[i]), x2 = __half2float(base[i+32]);
        float y1 = x1*cs - x2*sn;
        float y2 = x1*sn + x2*cs;
        if (head < NH) { y1 *= SCALEQ; y2 *= SCALEQ; }
        base[i]    = __float2half_rn(y1);
        base[i+32] = __float2half_rn(y2);
    } else {
        __shared__ float t[32][65];
        int vb = bid - NRBLK;
        int s0 = (vb & 31) * 64;
        int d0 = ((vb >> 5) & 1) * 32;
        int bk = vb >> 6;
        int tx = tid & 31, ty = tid >> 5;
        const __half* src = g_qkvh + (size_t)((bk>>2)*SS)*QKVN + DM + NKV*HDIM + (bk&3)*HDIM;
#pragma unroll
        for (int k = 0; k < 64; k += 8)
            t[tx][ty+k] = __half2float(src[(size_t)(s0+ty+k)*QKVN + d0+tx]);
        __syncthreads();
        __half* dst = g_vth + ((size_t)bk*HDIM)*SS;
#pragma unroll
        for (int k = 0; k < 32; k += 8) {
            int row = ty + k;
            half2 hv = __floats2half2_rn(t[row][2*tx], t[row][2*tx+1]);
            *(half2*)(dst + (size_t)(d0+row)*SS + s0 + 2*tx) = hv;
        }
    }
}

// ---------------- fp16 flash attention: ldmatrix frags, QK | PV(prev) | softmax ----
#define FQ 128
#define FKT 64
#define FSTW 36
#define FLASH_SMEM ((FQ + 2*FKT + 3*FKT + FQ)*FSTW*4)   // 82944 B
__global__ void __launch_bounds__(256)
flash_h_kernel(const __half* __restrict__ qkvh, const __half* __restrict__ vth,
               __half* __restrict__ out) {
    extern __shared__ unsigned smw[];
    unsigned* Qs = smw;
    unsigned* Kst = Qs + FQ*FSTW;
    unsigned* Vst = Kst + 2*FKT*FSTW;
    unsigned* Ps = Vst + 3*FKT*FSTW;
    unsigned smbF = (unsigned)__cvta_generic_to_shared(smw);
    int qb = gridDim.x - 1 - blockIdx.x;
    int bh = blockIdx.y;
    int b = bh >> 4, h = bh & 15, kh = h >> 2;
    int tid = threadIdx.x, lane = tid & 31, warp = tid >> 5;
    int g = lane >> 2, tg = lane & 3;

    {
        const __half* qp = qkvh + (size_t)(b*SS + qb*FQ)*QKVN + h*HDIM;
        int r = tid >> 1;
        int c0 = (tid & 1) * 4;
#pragma unroll
        for (int q = 0; q < 4; q++)
            cp16(&Qs[r*FSTW + (c0+q)*4], qp + (size_t)r*QKVN + (c0+q)*8, 16);
    }
    int kvr = tid >> 2, kvc = (tid & 3) * 2;
    const __half* kbase = qkvh + (size_t)(b*SS)*QKVN + DM + kh*HDIM;
    const __half* vtb = vth + ((size_t)(b*NKV + kh)*HDIM)*SS;
    auto load_kv = [&](int kst, int vst, int kt) {
        const __half* kp = kbase + (size_t)(kt*FKT + kvr)*QKVN;
        const __half* vp = vtb + (size_t)kvr*SS + kt*FKT;
        unsigned* kd = Kst + kst*FKT*FSTW + kvr*FSTW;
        unsigned* vd = Vst + vst*FKT*FSTW + kvr*FSTW;
#pragma unroll
        for (int q = 0; q < 2; q++) {
            cp16(kd + (kvc+q)*4, kp + (kvc+q)*8, 16);
            cp16(vd + (kvc+q)*4, vp + (kvc+q)*8, 16);
        }
    };

    int wrow = warp*16;
    int grow = qb*FQ + wrow;

    // ldmatrix per-lane offsets
    int rowA = (lane & 7) + ((lane >> 3) & 1) * 8;
    unsigned afr = ((wrow + rowA) * FSTW + (lane >> 4) * 4) * 4;
    unsigned bfr = (((lane >> 4) * 8 + (lane & 7)) * FSTW + ((lane >> 3) & 1) * 4) * 4;
    unsigned qb_a = smbF + afr;
    unsigned pb_a = smbF + (unsigned)((FQ + 5*FKT)*FSTW)*4 + afr;

    float m0 = -1e30f, m1 = -1e30f, l0 = 0.f, l1 = 0.f;
    float o[8][4];
#pragma unroll
    for (int nj = 0; nj < 8; nj++)
#pragma unroll
        for (int r = 0; r < 4; r++) o[nj][r] = 0.f;

    int ktmax = 2*qb + 1;
    load_kv(0, 0, 0);
    CP_COMMIT();

    bool pend = false;
    int pkt = 0;

    for (int kt = 0; kt <= ktmax; kt++) {
        __syncthreads();
        if (kt < ktmax) load_kv((kt+1)&1, (kt+1)%3, kt+1);
        CP_COMMIT();
        CP_WAITG1();
        __syncthreads();

        bool act = (kt*FKT <= grow + 15);
        float s[8][4];
        if (act) {
            unsigned kb_b = smbF + (unsigned)((FQ + (kt&1)*FKT)*FSTW)*4 + bfr;
#pragma unroll
            for (int nj = 0; nj < 8; nj++)
#pragma unroll
                for (int r = 0; r < 4; r++) s[nj][r] = 0.f;
#pragma unroll
            for (int ks = 0; ks < 4; ks++) {
                unsigned k0b = ks * 32;
                unsigned a0, a1, a2, a3;
                ldsm4(a0, a1, a2, a3, qb_a + k0b);
                unsigned bf[8][2];
#pragma unroll
                for (int n2 = 0; n2 < 4; n2++)
                    ldsm4(bf[2*n2][0], bf[2*n2][1], bf[2*n2+1][0], bf[2*n2+1][1],
                          kb_b + n2*16*FSTW*4 + k0b);
#pragma unroll
                for (int nj = 0; nj < 8; nj++)
                    mma_f16(s[nj], a0, a1, a2, a3, bf[nj][0], bf[nj][1]);
            }
        }

        if (pend) {
            unsigned vb_b = smbF + (unsigned)((FQ + 2*FKT + (pkt%3)*FKT)*FSTW)*4 + bfr;
#pragma unroll
            for (int ks = 0; ks < 4; ks++) {
                unsigned k0b = ks * 32;
                unsigned a0, a1, a2, a3;
                ldsm4(a0, a1, a2, a3, pb_a + k0b);
                unsigned bf[8][2];
#pragma unroll
                for (int n2 = 0; n2 < 4; n2++)
                    ldsm4(bf[2*n2][0], bf[2*n2][1], bf[2*n2+1][0], bf[2*n2+1][1],
                          vb_b + n2*16*FSTW*4 + k0b);
#pragma unroll
                for (int nj = 0; nj < 8; nj++)
                    mma_f16(o[nj], a0, a1, a2, a3, bf[nj][0], bf[nj][1]);
            }
            pend = false;
        }

        if (act) {
            if (kt >= 2*qb) {
                int r0 = grow + g, r1 = grow + g + 8;
#pragma unroll
                for (int nj = 0; nj < 8; nj++) {
                    int c = kt*FKT + nj*8 + 2*tg;
                    if (c     > r0) s[nj][0] = -1e30f;
                    if (c + 1 > r0) s[nj][1] = -1e30f;
                    if (c     > r1) s[nj][2] = -1e30f;
                    if (c + 1 > r1) s[nj][3] = -1e30f;
                }
            }
            float mt0 = -1e30f, mt1 = -1e30f;
#pragma unroll
            for (int nj = 0; nj < 8; nj++) {
                mt0 = fmaxf(mt0, fmaxf(s[nj][0], s[nj][1]));
                mt1 = fmaxf(mt1, fmaxf(s[nj][2], s[nj][3]));
            }
            mt0 = fmaxf(mt0, __shfl_xor_sync(0xffffffffu, mt0, 1));
            mt0 = fmaxf(mt0, __shfl_xor_sync(0xffffffffu, mt0, 2));
            mt1 = fmaxf(mt1, __shfl_xor_sync(0xffffffffu, mt1, 1));
            mt1 = fmaxf(mt1, __shfl_xor_sync(0xffffffffu, mt1, 2));
            float mn0 = fmaxf(m0, mt0), mn1 = fmaxf(m1, mt1);
            float c0 = __expf(m0 - mn0), c1 = __expf(m1 - mn1);
            l0 *= c0; l1 *= c1;
#pragma unroll
            for (int nj = 0; nj < 8; nj++) {
                o[nj][0] *= c0; o[nj][1] *= c0;
                o[nj][2] *= c1; o[nj][3] *= c1;
            }
            float rs0 = 0.f, rs1 = 0.f;
#pragma unroll
            for (int nj = 0; nj < 8; nj++) {
                float p0 = __expf(s[nj][0] - mn0);
                float p1 = __expf(s[nj][1] - mn0);
                float p2 = __expf(s[nj][2] - mn1);
                float p3 = __expf(s[nj][3] - mn1);
                rs0 += p0 + p1; rs1 += p2 + p3;
                int w = nj*4 + tg;
                ((half2*)Ps)[ ((wrow+g  )*FSTW + w) ] = __floats2half2_rn(p0, p1);
                ((half2*)Ps)[ ((wrow+g+8)*FSTW + w) ] = __floats2half2_rn(p2, p3);
            }
            rs0 += __shfl_xor_sync(0xffffffffu, rs0, 1);
            rs0 += __shfl_xor_sync(0xffffffffu, rs0, 2);
            rs1 += __shfl_xor_sync(0xffffffffu, rs1, 1);
            rs1 += __shfl_xor_sync(0xffffffffu, rs1, 2);
            l0 += rs0; l1 += rs1;
            m0 = mn0; m1 = mn1;
            __syncwarp();
            pend = true;
            pkt  = kt;
        }
    }

    if (pend) {
        unsigned vb_b = smbF + (unsigned)((FQ + 2*FKT + (pkt%3)*FKT)*FSTW)*4 + bfr;
#pragma unroll
        for (int ks = 0; ks < 4; ks++) {
            unsigned k0b = ks * 32;
            unsigned a0, a1, a2, a3;
            ldsm4(a0, a1, a2, a3, pb_a + k0b);
            unsigned bf[8][2];
#pragma unroll
            for (int n2 = 0; n2 < 4; n2++)
                ldsm4(bf[2*n2][0], bf[2*n2][1], bf[2*n2+1][0], bf[2*n2+1][1],
                      vb_b + n2*16*FSTW*4 + k0b);
#pragma unroll
            for (int nj = 0; nj < 8; nj++)
                mma_f16(o[nj], a0, a1, a2, a3, bf[nj][0], bf[nj][1]);
        }
    }

    float il0 = 1.f/l0, il1 = 1.f/l1;
    size_t tok0 = (size_t)(b*SS + qb*FQ + wrow + g);
    size_t tok1 = tok0 + 8;
#pragma unroll
    for (int nj = 0; nj < 8; nj++) {
        int col = h*HDIM + nj*8 + 2*tg;
        *(half2*)(out + tok0*DM + col) = __floats2half2_rn(o[nj][0]*il0, o[nj][1]*il0);
        *(half2*)(out + tok1*DM + col) = __floats2half2_rn(o[nj][2]*il1, o[nj][3]*il1);
    }
}

// ---------------- router ----------------
__global__ void router_kernel(const float* __restrict__ x2, const float* __restrict__ rw) {
    int t = (blockIdx.x*blockDim.x + threadIdx.x) >> 5;
    int lane = threadIdx.x & 31;
    if (t >= NT) return;
    const float* xr = x2 + (size_t)t*DM;
    float acc[NE];
#pragma unroll
    for (int e = 0; e < NE; e++) acc[e] = 0.f;
    for (int d = lane; d < DM; d += 32) {
        float xv = xr[d];
        float4 r0 = ((const float4*)rw)[d*2];
        float4 r1 = ((const float4*)rw)[d*2+1];
        acc[0]+=xv*r0.x; acc[1]+=xv*r0.y; acc[2]+=xv*r0.z; acc[3]+=xv*r0.w;
        acc[4]+=xv*r1.x; acc[5]+=xv*r1.y; acc[6]+=xv*r1.z; acc[7]+=xv*r1.w;
    }
#pragma unroll
    for (int o = 16; o; o >>= 1)
#pragma unroll
        for (int e = 0; e < NE; e++)
            acc[e] += __shfl_xor_sync(0xffffffffu, acc[e], o);
    if (lane == 0) {
        int e0 = 0; float m0 = acc[0];
#pragma unroll
        for (int e = 1; e < NE; e++) if (acc[e] > m0) { m0 = acc[e]; e0 = e; }
        int e1 = -1; float m1 = -3.4e38f;
#pragma unroll
        for (int e = 0; e < NE; e++) if (e != e0 && acc[e] > m1) { m1 = acc[e]; e1 = e; }
        float p1 = expf(m1 - m0);
        float w0 = 1.f / (1.f + p1);
        float w1 = p1 / (1.f + p1);
        g_top_e[2*t] = e0; g_top_e[2*t+1] = e1;
        g_top_w[2*t] = w0; g_top_w[2*t+1] = w1;
        atomicAdd(&g_cnt[e0], 1);
        atomicAdd(&g_cnt[e1], 1);
    }
}

// fill + local segoff
__global__ void fill_kernel() {
    int i = blockIdx.x*blockDim.x + threadIdx.x;
    if (i >= NT*2) return;
    int seg[NE+1];
    int off = 0;
#pragma unroll
    for (int e = 0; e < NE; e++) {
        seg[e] = off;
        off += ((g_cnt[e] + 127) >> 7) << 7;
    }
    seg[NE] = off;
    if (i == 0) {
#pragma unroll
        for (int e = 0; e <= NE; e++) g_segoff[e] = seg[e];
        g_total = off;
    }
    int e = g_top_e[i];
    int pos = seg[e] + atomicAdd(&g_fill[e], 1);
    g_perm[pos] = i >> 1;
    g_tok_slot[i] = pos;
}

__global__ void combine_kernel(float* __restrict__ out) {
    int i = blockIdx.x*blockDim.x + threadIdx.x;
    int n = i >> 8, d4 = i & 255;
    int s0 = g_tok_slot[2*n], s1 = g_tok_slot[2*n+1];
    float w0 = g_top_w[2*n], w1 = g_top_w[2*n+1];
    float4 hv = *(float4*)&g_hidden[(size_t)n*DM + d4*4];
    const half2* y0p = (const half2*)&g_yh[(size_t)s0*DM + d4*4];
    const half2* y1p = (const half2*)&g_yh[(size_t)s1*DM + d4*4];
    float2 ya0 = __half22float2(y0p[0]), yb0 = __half22float2(y0p[1]);
    float2 ya1 = __half22float2(y1p[0]), yb1 = __half22float2(y1p[1]);
    float4 r;
    r.x = hv.x + w0*ya0.x + w1*ya1.x;
    r.y = hv.y + w0*ya0.y + w1*ya1.y;
    r.z = hv.z + w0*yb0.x + w1*yb1.x;
    r.w = hv.w + w0*yb0.y + w1*yb1.y;
    *(float4*)&out[(size_t)n*DM + d4*4] = r;
}

// ---------------- launch (single stream) ----------------
extern "C" void kernel_launch(void* const* d_in, const int* in_sizes, int n_in,
                              void* d_out, int out_size) {
    const float* hs   = (const float*)d_in[0];
    const float* ln1w = (const float*)d_in[1];
    const float* ln2w = (const float*)d_in[2];
    const float* wqkv = (const float*)d_in[3];
    const float* outw = (const float*)d_in[4];
    const float* rw   = (const float*)d_in[5];
    const float* w1   = (const float*)d_in[6];
    const float* v1   = (const float*)d_in[7];
    const float* w2   = (const float*)d_in[8];
    float* out = (float*)d_out;

    float *phid, *px2;
    __half *px1h, *px2h, *pattnh, *ph1h, *pyh, *pqkvh, *pvth;
    __half *pwqkvh, *poutwh, *pw1h, *pv1h, *pw2h;
    cudaGetSymbolAddress((void**)&phid,  g_hidden);
    cudaGetSymbolAddress((void**)&px2,   g_x2);
    cudaGetSymbolAddress((void**)&px1h,  g_x1h);
    cudaGetSymbolAddress((void**)&px2h,  g_x2h);
    cudaGetSymbolAddress((void**)&pattnh,g_attnh);
    cudaGetSymbolAddress((void**)&ph1h,  g_h1h);
    cudaGetSymbolAddress((void**)&pyh,   g_yh);
    cudaGetSymbolAddress((void**)&pqkvh, g_qkvh);
    cudaGetSymbolAddress((void**)&pvth,  g_vth);
    cudaGetSymbolAddress((void**)&pwqkvh,g_wqkvh);
    cudaGetSymbolAddress((void**)&poutwh,g_outwh);
    cudaGetSymbolAddress((void**)&pw1h,  g_w1h);
    cudaGetSymbolAddress((void**)&pv1h,  g_v1h);
    cudaGetSymbolAddress((void**)&pw2h,  g_w2h);

    cudaFuncSetAttribute(flash_h_kernel,
                         cudaFuncAttributeMaxDynamicSharedMemorySize, FLASH_SMEM);
    cudaFuncSetAttribute(hgemm<4,false,false>,
                         cudaFuncAttributeMaxDynamicSharedMemorySize, HGEMM_SMEM);
    cudaFuncSetAttribute(hgemm<2,false,false>,
                         cudaFuncAttributeMaxDynamicSharedMemorySize, HGEMM_SMEM);
    cudaFuncSetAttribute(hgemm<5,false,true>,
                         cudaFuncAttributeMaxDynamicSharedMemorySize, HGEMM_SMEM);
    cudaFuncSetAttribute(up_hgemm,
                         cudaFuncAttributeMaxDynamicSharedMemorySize, UP_SMEM);

    // ---- weight conversions + one-time init ----
    conv2_h<<<(2*NE*FF*DM/4 + 255)/256, 256>>>(w1, pw1h, v1, pv1h, NE*FF*DM/4);
    convT_h<<<dim3(DM/64, QKVN/32, 1), dim3(32,8)>>>(wqkv, pwqkvh, DM, QKVN);
    convT_h<<<dim3(DM/64, DM/32, 1), dim3(32,8)>>>(outw, poutwh, DM, DM);
    convT_h<<<dim3(FF/64, DM/32, NE), dim3(32,8)>>>(w2, pw2h, FF, DM);

    // LN1 -> QKV(clip, fp16) -> RoPE+V^T -> attention -> out-proj(+resid)
    ln_kernel<false,true><<<NT, 256>>>(hs, ln1w, nullptr, px1h);
    hgemm<4,false,false><<<dim3(QKVN/128, NT/128), 256, HGEMM_SMEM>>>(
        px1h, pwqkvh, pqkvh, nullptr, QKVN, DM, 0);
    ropevt_kernel<<<NRBLK + NVBLK, 256>>>();
    flash_h_kernel<<<dim3(SS/FQ, BB*NH), 256, FLASH_SMEM>>>(pqkvh, pvth, pattnh);
    hgemm<2,false,false><<<dim3(DM/128, NT/128), 256, HGEMM_SMEM>>>(
        pattnh, poutwh, phid, hs, DM, DM, 0);

    // LN2 -> router -> fill(+segoff)
    ln_kernel<true,true><<<NT, 256>>>(phid, ln2w, px2, px2h);
    router_kernel<<<NT/8, 256>>>(px2, rw);
    fill_kernel<<<(NT*2 + 255)/256, 256>>>();

    // MoE: fused dual-B up (silu epilogue, fp16 out), then down (fp16 y)
    up_hgemm<<<dim3(FF/128, CAP/128), 256, UP_SMEM>>>(px2h, pw1h, pv1h, ph1h);
    hgemm<5,false,true><<<dim3(DM/128, CAP/128), 256, HGEMM_SMEM>>>(
        ph1h, pw2h, pyh, nullptr, DM, FF, (long)DM*FF);

    // resid2 + gated expert outputs
    combine_kernel<<<NT, 256>>>(out);
}